// round 7
// baseline (speedup 1.0000x reference)
#include <cuda_runtime.h>
#include <math.h>

#define NN 64
#define MATSZ 4096
#define NB 4096

enum { F_NONE = -1, F_SQRT = 0, F_INVSQRT = 1, F_LOG = 2, F_EXP = 3 };

// device-global scratch (no runtime allocation allowed)
__device__ float  g_bufA[(size_t)NB * MATSZ];
__device__ float  g_bufB[(size_t)NB * MATSZ];
__device__ float  g_bufC[(size_t)NB * MATSZ];
__device__ float  g_bufD[(size_t)NB * MATSZ];
__device__ float  g_small[20 * MATSZ];
__device__ double g_part[256];
__device__ float  g_scal[4];

__device__ __forceinline__ float apply_fn(int f, float w) {
    switch (f) {
        case F_SQRT:    return sqrtf(fmaxf(w, 0.0f));
        case F_INVSQRT: return rsqrtf(fmaxf(w, 1e-30f));
        case F_LOG:     return logf(fmaxf(w, 1e-30f));
        case F_EXP:     return expf(w);
    }
    return w;
}

// ---------------------------------------------------------------------------
// In-shared 64x64 GEMM helper: C = alpha*(A@B) + beta*D + diag*I.
// 256 threads, 4x4 tiles. C must differ from A and B. D==C or D==A allowed.
// ---------------------------------------------------------------------------
__device__ __forceinline__ void mm64(const float* __restrict__ A,
                                     const float* __restrict__ B,
                                     float alpha, float beta,
                                     const float* __restrict__ D,
                                     float diag, float* __restrict__ C, int tid)
{
    const int ti = (tid >> 4) << 2, tj = (tid & 15) << 2;
    float acc[4][4] = {};
    #pragma unroll 4
    for (int k = 0; k < 64; ++k) {
        float a0 = A[(ti + 0) * 64 + k], a1 = A[(ti + 1) * 64 + k];
        float a2 = A[(ti + 2) * 64 + k], a3 = A[(ti + 3) * 64 + k];
        float4 b = *reinterpret_cast<const float4*>(B + k * 64 + tj);
        acc[0][0] += a0 * b.x; acc[0][1] += a0 * b.y; acc[0][2] += a0 * b.z; acc[0][3] += a0 * b.w;
        acc[1][0] += a1 * b.x; acc[1][1] += a1 * b.y; acc[1][2] += a1 * b.z; acc[1][3] += a1 * b.w;
        acc[2][0] += a2 * b.x; acc[2][1] += a2 * b.y; acc[2][2] += a2 * b.z; acc[2][3] += a2 * b.w;
        acc[3][0] += a3 * b.x; acc[3][1] += a3 * b.y; acc[3][2] += a3 * b.z; acc[3][3] += a3 * b.w;
    }
    __syncthreads();
    #pragma unroll
    for (int r = 0; r < 4; ++r) {
        float4 v;
        v.x = alpha * acc[r][0]; v.y = alpha * acc[r][1];
        v.z = alpha * acc[r][2]; v.w = alpha * acc[r][3];
        if (beta != 0.0f) {
            float4 d = *reinterpret_cast<const float4*>(D + (ti + r) * 64 + tj);
            v.x += beta * d.x; v.y += beta * d.y; v.z += beta * d.z; v.w += beta * d.w;
        }
        if (diag != 0.0f) {
            int row = ti + r;
            if (row >= tj && row < tj + 4) (&v.x)[row - tj] += diag;
        }
        *reinterpret_cast<float4*>(C + (ti + r) * 64 + tj) = v;
    }
    __syncthreads();
}

// ---------------------------------------------------------------------------
// Batched matrix sqrt via coupled Newton-Schulz (Higham). One CTA/matrix.
// ---------------------------------------------------------------------------
__global__ __launch_bounds__(256) void nssqrt_kernel(
    const float* __restrict__ in, float* __restrict__ out)
{
    extern __shared__ float sh[];          // 4 * 4096 floats
    float *Y = sh, *Z = sh + 4096, *W = sh + 8192, *T = sh + 12288;
    __shared__ float red[256];
    __shared__ float s_s;

    const int tid = threadIdx.x;
    const size_t boff = (size_t)blockIdx.x * MATSZ;

    float fa = 0.0f;
    for (int idx = tid; idx < MATSZ; idx += 256) {
        float v = in[boff + idx];
        Y[idx] = v;
        fa += v * v;
        Z[idx] = ((idx >> 6) == (idx & 63)) ? 1.0f : 0.0f;
    }
    red[tid] = fa;
    __syncthreads();
    #pragma unroll
    for (int s = 128; s > 0; s >>= 1) {
        if (tid < s) red[tid] += red[tid + s];
        __syncthreads();
    }
    if (tid == 0) s_s = fmaxf(sqrtf(red[0]) / 1.8f, 1e-20f);
    __syncthreads();
    float inv_s = 1.0f / s_s;
    for (int idx = tid; idx < MATSZ; idx += 256) Y[idx] *= inv_s;
    __syncthreads();

    for (int it = 0; it < 10; ++it) {
        mm64(Z, Y, 1.0f, 0.0f, nullptr, 0.0f, W, tid);      // W = Z@Y
        mm64(Y, W, -0.5f, 1.5f, Y, 0.0f, T, tid);           // T = 1.5Y - 0.5 Y@W
        if (it < 9) {
            mm64(W, Z, -0.5f, 1.5f, Z, 0.0f, Y, tid);       // Znew -> old Y buffer
            float* nY = T; float* nZ = Y; float* nT = Z;
            Y = nY; Z = nZ; T = nT;
        } else {
            Y = T;
        }
    }
    float rs = sqrtf(s_s);
    for (int idx = tid; idx < MATSZ; idx += 256)
        out[boff + idx] = Y[idx] * rs;
}

// ---------------------------------------------------------------------------
// Batched matrix exp via scaling-and-squaring + degree-7 Taylor (Horner).
// ---------------------------------------------------------------------------
__global__ __launch_bounds__(256) void expm_kernel(
    const float* __restrict__ in, float* __restrict__ out)
{
    extern __shared__ float sh[];          // 3 * 4096 floats
    float *B = sh, *P = sh + 4096, *Q = sh + 8192;
    __shared__ float red[256];
    __shared__ float sc_s;
    __shared__ int   j_s;

    const int tid = threadIdx.x;
    const size_t boff = (size_t)blockIdx.x * MATSZ;

    float fa = 0.0f;
    for (int idx = tid; idx < MATSZ; idx += 256) {
        float v = in[boff + idx];
        B[idx] = v;
        fa += v * v;
    }
    red[tid] = fa;
    __syncthreads();
    #pragma unroll
    for (int s = 128; s > 0; s >>= 1) {
        if (tid < s) red[tid] += red[tid + s];
        __syncthreads();
    }
    if (tid == 0) {
        float F = sqrtf(red[0]);
        int j = 0;
        while (F > 0.25f && j < 40) { F *= 0.5f; ++j; }
        j_s = j;
        sc_s = exp2f((float)(-j));
    }
    __syncthreads();
    const int j = j_s;
    float sc = sc_s;
    for (int idx = tid; idx < MATSZ; idx += 256) B[idx] *= sc;
    __syncthreads();

    const float c7 = 1.0f / 5040.0f, c6 = 1.0f / 720.0f;
    for (int idx = tid; idx < MATSZ; idx += 256) {
        float v = c7 * B[idx];
        if ((idx >> 6) == (idx & 63)) v += c6;
        P[idx] = v;
    }
    __syncthreads();
    const float cs[6] = { 1.0f / 120.0f, 1.0f / 24.0f, 1.0f / 6.0f, 0.5f, 1.0f, 1.0f };
    float *cur = P, *oth = Q;
    #pragma unroll
    for (int k = 0; k < 6; ++k) {
        mm64(cur, B, 1.0f, 0.0f, nullptr, cs[k], oth, tid);
        float* t = cur; cur = oth; oth = t;
    }
    for (int t = 0; t < j; ++t) {
        mm64(cur, cur, 1.0f, 0.0f, nullptr, 0.0f, oth, tid);
        float* tt = cur; cur = oth; oth = tt;
    }
    for (int idx = tid; idx < MATSZ; idx += 256)
        out[boff + idx] = cur[idx];
}

// ---------------------------------------------------------------------------
// One-sided (Hestenes) Jacobi eigensolver, symmetric 64x64.
// PPW = 32/NW independent pairs interleaved per warp: their shuffle-reduction
// chains overlap (ILP), smaller barriers, more CTAs/SM at TPB=256.
// ---------------------------------------------------------------------------
template <int TPB>
__global__ __launch_bounds__(TPB) void jac1s(
    const float* __restrict__ in, float* __restrict__ out1,
    float* __restrict__ out2, int f1, int f2, int useShift, int nsweeps)
{
    constexpr int NW  = TPB / 32;
    constexpr int PPW = 32 / NW;
    __shared__ float2 As2[NN * 33];
    __shared__ float norms[NN];
    __shared__ float gv[NN], gv2[NN];
    __shared__ float red[TPB];
    __shared__ float shift_s;
    float* Asf = reinterpret_cast<float*>(As2);

    const int tid  = threadIdx.x;
    const int lane = tid & 31;
    const int wid  = tid >> 5;
    const size_t boff = (size_t)blockIdx.x * MATSZ;

    float fa = 0.0f;
    for (int idx = tid; idx < MATSZ; idx += TPB) {
        int c = idx >> 6, r = idx & 63;
        float v = in[boff + idx];
        Asf[c * 66 + r] = v;
        fa += v * v;
    }
    red[tid] = fa;
    __syncthreads();
    if (useShift) {
        #pragma unroll
        for (int s = TPB / 2; s > 0; s >>= 1) {
            if (tid < s) red[tid] += red[tid + s];
            __syncthreads();
        }
        if (tid == 0) shift_s = sqrtf(red[0]) * 1.000001f + 1e-20f;
        __syncthreads();
        if (tid < 64) Asf[tid * 66 + tid] += shift_s;
    } else {
        if (tid == 0) shift_s = 0.0f;
    }
    __syncthreads();

    for (int j = wid; j < 64; j += NW) {
        float2 a = As2[j * 33 + lane];
        float s = a.x * a.x + a.y * a.y;
        #pragma unroll
        for (int o = 16; o; o >>= 1) s += __shfl_xor_sync(0xFFFFFFFFu, s, o);
        if (lane == 0) norms[j] = s;
    }
    __syncthreads();

    for (int sw = 0; sw < nsweeps; ++sw) {
        for (int r = 0; r < 63; ++r) {
            int    p[PPW], q[PPW];
            float2 ap[PPW], aq[PPW];
            float  g[PPW];
            #pragma unroll
            for (int u = 0; u < PPW; ++u) {
                int k = wid + u * NW;
                if (k == 0) { p[u] = 63; q[u] = r; }
                else {
                    int a1 = r + k;      p[u] = (a1 < 63) ? a1 : a1 - 63;
                    int a2 = r + 63 - k; q[u] = (a2 < 63) ? a2 : a2 - 63;
                }
                ap[u] = As2[p[u] * 33 + lane];
                aq[u] = As2[q[u] * 33 + lane];
                g[u] = ap[u].x * aq[u].x + ap[u].y * aq[u].y;
            }
            #pragma unroll
            for (int o = 16; o; o >>= 1) {
                #pragma unroll
                for (int u = 0; u < PPW; ++u)
                    g[u] += __shfl_xor_sync(0xFFFFFFFFu, g[u], o);
            }
            #pragma unroll
            for (int u = 0; u < PPW; ++u) {
                if (g[u] != 0.0f) {
                    float al = norms[p[u]], be = norms[q[u]];
                    float tau = (be - al) / (2.0f * g[u]);
                    float t = 1.0f / (fabsf(tau) + sqrtf(1.0f + tau * tau));
                    if (tau < 0.0f) t = -t;
                    float c = rsqrtf(1.0f + t * t);
                    float s = t * c;
                    float2 np, nq;
                    np.x = c * ap[u].x - s * aq[u].x;
                    np.y = c * ap[u].y - s * aq[u].y;
                    nq.x = s * ap[u].x + c * aq[u].x;
                    nq.y = s * ap[u].y + c * aq[u].y;
                    As2[p[u] * 33 + lane] = np;
                    As2[q[u] * 33 + lane] = nq;
                    if (lane == 0) {
                        float cc = c * c, ss = s * s, cs2 = 2.0f * c * s;
                        norms[p[u]] = cc * al - cs2 * g[u] + ss * be;
                        norms[q[u]] = ss * al + cs2 * g[u] + cc * be;
                    }
                }
            }
            __syncthreads();
        }
    }

    for (int j = wid; j < 64; j += NW) {
        float2 a = As2[j * 33 + lane];
        float s = a.x * a.x + a.y * a.y;
        #pragma unroll
        for (int o = 16; o; o >>= 1) s += __shfl_xor_sync(0xFFFFFFFFu, s, o);
        if (lane == 0) {
            s = fmaxf(s, 1e-30f);
            float lam = sqrtf(s) - shift_s;
            gv[j] = apply_fn(f1, lam) / s;
            if (f2 != F_NONE) gv2[j] = apply_fn(f2, lam) / s;
        }
    }
    __syncthreads();

    constexpr int TRI = MATSZ / TPB / 4;   // 256 -> 4, 1024 -> 1
    const int ti = (tid >> 4) * TRI;
    const int tj = (tid & 15) << 2;
    {
        float acc[TRI][4] = {};
        #pragma unroll 4
        for (int k = 0; k < 64; ++k) {
            const float* ck = Asf + k * 66;
            float gk = gv[k];
            float a[TRI], b[4];
            #pragma unroll
            for (int r = 0; r < TRI; ++r) a[r] = gk * ck[ti + r];
            #pragma unroll
            for (int c = 0; c < 4; ++c) b[c] = ck[tj + c];
            #pragma unroll
            for (int r = 0; r < TRI; ++r)
                #pragma unroll
                for (int c = 0; c < 4; ++c) acc[r][c] += a[r] * b[c];
        }
        #pragma unroll
        for (int r = 0; r < TRI; ++r) {
            float4 v = make_float4(acc[r][0], acc[r][1], acc[r][2], acc[r][3]);
            *reinterpret_cast<float4*>(out1 + boff + (size_t)(ti + r) * 64 + tj) = v;
        }
    }
    if (f2 != F_NONE) {
        float acc[TRI][4] = {};
        #pragma unroll 4
        for (int k = 0; k < 64; ++k) {
            const float* ck = Asf + k * 66;
            float gk = gv2[k];
            float a[TRI], b[4];
            #pragma unroll
            for (int r = 0; r < TRI; ++r) a[r] = gk * ck[ti + r];
            #pragma unroll
            for (int c = 0; c < 4; ++c) b[c] = ck[tj + c];
            #pragma unroll
            for (int r = 0; r < TRI; ++r)
                #pragma unroll
                for (int c = 0; c < 4; ++c) acc[r][c] += a[r] * b[c];
        }
        #pragma unroll
        for (int r = 0; r < TRI; ++r) {
            float4 v = make_float4(acc[r][0], acc[r][1], acc[r][2], acc[r][3]);
            *reinterpret_cast<float4*>(out2 + boff + (size_t)(ti + r) * 64 + tj) = v;
        }
    }
}

// 4x4 register tile inner product: C[ti..][tj..] += op(A) op(B)
template <int TA, int TB>
__device__ __forceinline__ void tile_mm(const float* __restrict__ A,
                                        const float* __restrict__ B,
                                        float acc[4][4], int ti, int tj)
{
    #pragma unroll 4
    for (int k = 0; k < 64; ++k) {
        float a[4], b[4];
        #pragma unroll
        for (int r = 0; r < 4; ++r) a[r] = TA ? A[k * 64 + ti + r] : A[(ti + r) * 64 + k];
        #pragma unroll
        for (int c = 0; c < 4; ++c) b[c] = TB ? B[(tj + c) * 64 + k] : B[k * 64 + tj + c];
        #pragma unroll
        for (int r = 0; r < 4; ++r)
            #pragma unroll
            for (int c = 0; c < 4; ++c) acc[r][c] += a[r] * b[c];
    }
}

// out_b = scale * L @ X_b @ op(R)  (L, R broadcast)
__global__ __launch_bounds__(256) void cong_kernel(
    const float* __restrict__ Lm, const float* __restrict__ Xb,
    const float* __restrict__ Rm, float* __restrict__ out,
    int useScale, int transR)
{
    __shared__ float Ls[MATSZ], Rs[MATSZ], Xs[MATSZ];
    const int tid = threadIdx.x;
    const size_t boff = (size_t)blockIdx.x * MATSZ;
    for (int i = tid; i < MATSZ; i += 256) {
        Ls[i] = Lm[i]; Rs[i] = Rm[i]; Xs[i] = Xb[boff + i];
    }
    __syncthreads();

    const int ti = (tid >> 4) << 2, tj = (tid & 15) << 2;
    float acc[4][4] = {};
    tile_mm<0, 0>(Ls, Xs, acc, ti, tj);
    __syncthreads();
    #pragma unroll
    for (int r = 0; r < 4; ++r)
        #pragma unroll
        for (int c = 0; c < 4; ++c) Xs[(ti + r) * 64 + tj + c] = acc[r][c];
    __syncthreads();

    float sc = useScale ? g_scal[0] : 1.0f;
    float acc2[4][4] = {};
    if (transR) tile_mm<0, 1>(Xs, Rs, acc2, ti, tj);
    else        tile_mm<0, 0>(Xs, Rs, acc2, ti, tj);
    #pragma unroll
    for (int r = 0; r < 4; ++r) {
        float4 v = make_float4(acc2[r][0] * sc, acc2[r][1] * sc,
                               acc2[r][2] * sc, acc2[r][3] * sc);
        *reinterpret_cast<float4*>(out + boff + (size_t)(ti + r) * 64 + tj) = v;
    }
}

// out_b = A_b @ B_(b*strideB)   (strideB = 0 broadcasts B)
__global__ __launch_bounds__(256) void gemmB_kernel(
    const float* __restrict__ A, const float* __restrict__ Bm, int strideB,
    float* __restrict__ out)
{
    __shared__ float As_[MATSZ], Bs_[MATSZ];
    const int tid = threadIdx.x;
    const size_t boff = (size_t)blockIdx.x * MATSZ;
    const float* Bb = Bm + (size_t)blockIdx.x * strideB;
    for (int i = tid; i < MATSZ; i += 256) { As_[i] = A[boff + i]; Bs_[i] = Bb[i]; }
    __syncthreads();
    const int ti = (tid >> 4) << 2, tj = (tid & 15) << 2;
    float acc[4][4] = {};
    tile_mm<0, 0>(As_, Bs_, acc, ti, tj);
    #pragma unroll
    for (int r = 0; r < 4; ++r) {
        float4 v = make_float4(acc[r][0], acc[r][1], acc[r][2], acc[r][3]);
        *reinterpret_cast<float4*>(out + boff + (size_t)(ti + r) * 64 + tj) = v;
    }
}

// single 64x64 gemm: C = op(A) @ B
__global__ __launch_bounds__(256) void gemm1_kernel(
    const float* __restrict__ A, const float* __restrict__ B,
    float* __restrict__ C, int transA)
{
    __shared__ float As_[MATSZ], Bs_[MATSZ];
    const int tid = threadIdx.x;
    for (int i = tid; i < MATSZ; i += 256) { As_[i] = A[i]; Bs_[i] = B[i]; }
    __syncthreads();
    const int ti = (tid >> 4) << 2, tj = (tid & 15) << 2;
    float acc[4][4] = {};
    if (transA) tile_mm<1, 0>(As_, Bs_, acc, ti, tj);
    else        tile_mm<0, 0>(As_, Bs_, acc, ti, tj);
    #pragma unroll
    for (int r = 0; r < 4; ++r) {
        float4 v = make_float4(acc[r][0], acc[r][1], acc[r][2], acc[r][3]);
        *reinterpret_cast<float4*>(C + (size_t)(ti + r) * 64 + tj) = v;
    }
}

// out[e] = mean_b in[b*4096 + e]
__global__ void mean_kernel(const float* __restrict__ in, float* __restrict__ out)
{
    int e = blockIdx.x * blockDim.x + threadIdx.x;
    double a0 = 0, a1 = 0, a2 = 0, a3 = 0;
    for (int b = 0; b < NB; b += 4) {
        a0 += (double)in[(size_t)(b + 0) * MATSZ + e];
        a1 += (double)in[(size_t)(b + 1) * MATSZ + e];
        a2 += (double)in[(size_t)(b + 2) * MATSZ + e];
        a3 += (double)in[(size_t)(b + 3) * MATSZ + e];
    }
    out[e] = (float)((a0 + a1 + a2 + a3) * (1.0 / (double)NB));
}

// deterministic two-pass sum of squares
__global__ __launch_bounds__(256) void sumsq_kernel(const float* __restrict__ in)
{
    __shared__ double sh[256];
    const int tid = threadIdx.x;
    const size_t base = (size_t)blockIdx.x * 65536;
    double a = 0;
    for (int i = tid; i < 65536; i += 256) {
        float v = in[base + i];
        a += (double)v * (double)v;
    }
    sh[tid] = a;
    __syncthreads();
    for (int s = 128; s > 0; s >>= 1) {
        if (tid < s) sh[tid] += sh[tid + s];
        __syncthreads();
    }
    if (tid == 0) g_part[blockIdx.x] = sh[0];
}

__global__ void finalize_kernel(const float* __restrict__ shift)
{
    __shared__ double sh[256];
    const int tid = threadIdx.x;
    sh[tid] = g_part[tid];
    __syncthreads();
    for (int s = 128; s > 0; s >>= 1) {
        if (tid < s) sh[tid] += sh[tid + s];
        __syncthreads();
    }
    if (tid == 0) {
        double var = sh[0] / (double)NB;
        g_scal[0] = shift[0] / (float)sqrt(var + 1e-5);
    }
}

extern "C" void kernel_launch(void* const* d_in, const int* in_sizes, int n_in,
                              void* d_out, int out_size)
{
    const float* X     = (const float*)d_in[0];
    const float* W     = (const float*)d_in[1];
    const float* M     = (const float*)d_in[2];
    const float* shift = (const float*)d_in[3];
    float* out = (float*)d_out;

    float *bufA, *bufB, *bufC, *bufD, *sm;
    cudaGetSymbolAddress((void**)&bufA, g_bufA);
    cudaGetSymbolAddress((void**)&bufB, g_bufB);
    cudaGetSymbolAddress((void**)&bufC, g_bufC);
    cudaGetSymbolAddress((void**)&bufD, g_bufD);
    cudaGetSymbolAddress((void**)&sm,   g_small);

    cudaFuncSetAttribute(nssqrt_kernel, cudaFuncAttributeMaxDynamicSharedMemorySize, 65536);
    cudaFuncSetAttribute(expm_kernel,   cudaFuncAttributeMaxDynamicSharedMemorySize, 49152);

    #define SLOT(i) (sm + (i) * MATSZ)
    // slots: 0 Mh, 1 Mnh, 2 Wh, 3 tmp, 4 Wc, 5 Wch, 6 Wcnh, 7 P, 8 Q, 9 R,
    //        10 G0, 11 G0h, 12 G0nh, 13 Tm, 14 expTm, 15 G, 16 mnh

    // parameter prep (tiny single-matrix ops; 8 sweeps, negligible cost)
    jac1s<1024><<<1, 1024>>>(M, SLOT(0), SLOT(1), F_SQRT, F_INVSQRT, 0, 8);   // Mh, Mnh
    jac1s<1024><<<1, 1024>>>(W, SLOT(2), SLOT(2), F_SQRT, F_NONE, 0, 8);      // Wh
    gemm1_kernel<<<1, 256>>>(SLOT(1), SLOT(2), SLOT(3), 0);                   // Mnh Wh
    gemm1_kernel<<<1, 256>>>(SLOT(3), SLOT(1), SLOT(4), 0);                   // Wc
    jac1s<1024><<<1, 1024>>>(SLOT(4), SLOT(5), SLOT(6), F_SQRT, F_INVSQRT, 0, 8); // Wch, Wcnh
    gemm1_kernel<<<1, 256>>>(SLOT(6), SLOT(2), SLOT(7), 0);                   // P = Wcnh Wh
    gemm1_kernel<<<1, 256>>>(SLOT(0), SLOT(5), SLOT(8), 0);                   // Q = Mh Wch
    gemm1_kernel<<<1, 256>>>(SLOT(8), SLOT(8), SLOT(9), 1);                   // R = Q^T Q

    // Xp = X^{1/2} (Newton-Schulz); Xc = Mnh Xp Mnh
    nssqrt_kernel<<<NB, 256, 65536>>>(X, bufA);
    cong_kernel<<<NB, 256>>>(SLOT(1), bufA, SLOT(1), bufB, 0, 0);             // Xc

    // bary_geom: 1 Karcher step from arithmetic mean
    mean_kernel<<<16, 256>>>(bufB, SLOT(10));                                 // G0
    jac1s<1024><<<1, 1024>>>(SLOT(10), SLOT(11), SLOT(12), F_SQRT, F_INVSQRT, 0, 8);
    cong_kernel<<<NB, 256>>>(SLOT(12), bufB, SLOT(12), bufC, 0, 0);
    jac1s<256><<<NB, 256>>>(bufC, bufA, bufA, F_LOG, F_NONE, 0, 7);
    mean_kernel<<<16, 256>>>(bufA, SLOT(13));                                 // Tm
    jac1s<1024><<<1, 1024>>>(SLOT(13), SLOT(14), SLOT(14), F_EXP, F_NONE, 1, 8); // exp (shift)
    gemm1_kernel<<<1, 256>>>(SLOT(11), SLOT(14), SLOT(3), 0);
    gemm1_kernel<<<1, 256>>>(SLOT(3), SLOT(11), SLOT(15), 0);                 // G
    jac1s<1024><<<1, 1024>>>(SLOT(15), SLOT(16), SLOT(16), F_INVSQRT, F_NONE, 0, 8); // mnh

    // tangent at I, variance, scale
    cong_kernel<<<NB, 256>>>(SLOT(16), bufB, SLOT(16), bufC, 0, 0);
    jac1s<256><<<NB, 256>>>(bufC, bufD, bufD, F_LOG, F_NONE, 0, 7);           // T0
    sumsq_kernel<<<256, 256>>>(bufD);
    finalize_kernel<<<1, 256>>>(shift);

    // arg = factor * P T0 P^T ; E = exp(arg) (scaling & squaring)
    cong_kernel<<<NB, 256>>>(SLOT(7), bufD, SLOT(7), bufC, 1, 1);
    expm_kernel<<<NB, 256, 49152>>>(bufC, bufA);                              // E

    // out = Q (E R E) Q^T
    gemmB_kernel<<<NB, 256>>>(bufA, SLOT(9), 0, bufC);                        // E R
    gemmB_kernel<<<NB, 256>>>(bufC, bufA, MATSZ, bufD);                       // (E R) E
    cong_kernel<<<NB, 256>>>(SLOT(8), bufD, SLOT(8), out, 0, 1);
    #undef SLOT
}

// round 8
// speedup vs baseline: 1.1086x; 1.1086x over previous
#include <cuda_runtime.h>
#include <math.h>

#define NN 64
#define MATSZ 4096
#define NB 4096

enum { F_NONE = -1, F_SQRT = 0, F_INVSQRT = 1, F_LOG = 2, F_EXP = 3 };

// device-global scratch (no runtime allocation allowed)
__device__ float  g_bufA[(size_t)NB * MATSZ];
__device__ float  g_bufB[(size_t)NB * MATSZ];
__device__ float  g_bufC[(size_t)NB * MATSZ];
__device__ float  g_bufD[(size_t)NB * MATSZ];
__device__ float  g_small[20 * MATSZ];
__device__ double g_part[256];
__device__ float  g_scal[4];

__device__ __forceinline__ float apply_fn(int f, float w) {
    switch (f) {
        case F_SQRT:    return sqrtf(fmaxf(w, 0.0f));
        case F_INVSQRT: return rsqrtf(fmaxf(w, 1e-30f));
        case F_LOG:     return logf(fmaxf(w, 1e-30f));
        case F_EXP:     return expf(w);
    }
    return w;
}

// ---------------------------------------------------------------------------
// In-shared 64x64 GEMM helper: C = alpha*(A@B) + beta*D + diag*I.
// 256 threads, 4x4 tiles. C must differ from A and B. D==C or D==A allowed.
// ---------------------------------------------------------------------------
__device__ __forceinline__ void mm64(const float* __restrict__ A,
                                     const float* __restrict__ B,
                                     float alpha, float beta,
                                     const float* __restrict__ D,
                                     float diag, float* __restrict__ C, int tid)
{
    const int ti = (tid >> 4) << 2, tj = (tid & 15) << 2;
    float acc[4][4] = {};
    #pragma unroll 4
    for (int k = 0; k < 64; ++k) {
        float a0 = A[(ti + 0) * 64 + k], a1 = A[(ti + 1) * 64 + k];
        float a2 = A[(ti + 2) * 64 + k], a3 = A[(ti + 3) * 64 + k];
        float4 b = *reinterpret_cast<const float4*>(B + k * 64 + tj);
        acc[0][0] += a0 * b.x; acc[0][1] += a0 * b.y; acc[0][2] += a0 * b.z; acc[0][3] += a0 * b.w;
        acc[1][0] += a1 * b.x; acc[1][1] += a1 * b.y; acc[1][2] += a1 * b.z; acc[1][3] += a1 * b.w;
        acc[2][0] += a2 * b.x; acc[2][1] += a2 * b.y; acc[2][2] += a2 * b.z; acc[2][3] += a2 * b.w;
        acc[3][0] += a3 * b.x; acc[3][1] += a3 * b.y; acc[3][2] += a3 * b.z; acc[3][3] += a3 * b.w;
    }
    __syncthreads();
    #pragma unroll
    for (int r = 0; r < 4; ++r) {
        float4 v;
        v.x = alpha * acc[r][0]; v.y = alpha * acc[r][1];
        v.z = alpha * acc[r][2]; v.w = alpha * acc[r][3];
        if (beta != 0.0f) {
            float4 d = *reinterpret_cast<const float4*>(D + (ti + r) * 64 + tj);
            v.x += beta * d.x; v.y += beta * d.y; v.z += beta * d.z; v.w += beta * d.w;
        }
        if (diag != 0.0f) {
            int row = ti + r;
            if (row >= tj && row < tj + 4) (&v.x)[row - tj] += diag;
        }
        *reinterpret_cast<float4*>(C + (ti + r) * 64 + tj) = v;
    }
    __syncthreads();
}

// ---------------------------------------------------------------------------
// Batched matrix sqrt via coupled Newton-Schulz (Higham). One CTA/matrix.
// ---------------------------------------------------------------------------
__global__ __launch_bounds__(256) void nssqrt_kernel(
    const float* __restrict__ in, float* __restrict__ out)
{
    extern __shared__ float sh[];          // 4 * 4096 floats
    float *Y = sh, *Z = sh + 4096, *W = sh + 8192, *T = sh + 12288;
    __shared__ float red[256];
    __shared__ float s_s;

    const int tid = threadIdx.x;
    const size_t boff = (size_t)blockIdx.x * MATSZ;

    float fa = 0.0f;
    for (int idx = tid; idx < MATSZ; idx += 256) {
        float v = in[boff + idx];
        Y[idx] = v;
        fa += v * v;
        Z[idx] = ((idx >> 6) == (idx & 63)) ? 1.0f : 0.0f;
    }
    red[tid] = fa;
    __syncthreads();
    #pragma unroll
    for (int s = 128; s > 0; s >>= 1) {
        if (tid < s) red[tid] += red[tid + s];
        __syncthreads();
    }
    if (tid == 0) s_s = fmaxf(sqrtf(red[0]) / 1.8f, 1e-20f);
    __syncthreads();
    float inv_s = 1.0f / s_s;
    for (int idx = tid; idx < MATSZ; idx += 256) Y[idx] *= inv_s;
    __syncthreads();

    for (int it = 0; it < 10; ++it) {
        mm64(Z, Y, 1.0f, 0.0f, nullptr, 0.0f, W, tid);      // W = Z@Y
        mm64(Y, W, -0.5f, 1.5f, Y, 0.0f, T, tid);           // T = 1.5Y - 0.5 Y@W
        if (it < 9) {
            mm64(W, Z, -0.5f, 1.5f, Z, 0.0f, Y, tid);       // Znew -> old Y buffer
            float* nY = T; float* nZ = Y; float* nT = Z;
            Y = nY; Z = nZ; T = nT;
        } else {
            Y = T;
        }
    }
    float rs = sqrtf(s_s);
    for (int idx = tid; idx < MATSZ; idx += 256)
        out[boff + idx] = Y[idx] * rs;
}

// ---------------------------------------------------------------------------
// Batched matrix exp via scaling-and-squaring + degree-7 Taylor (Horner).
// ---------------------------------------------------------------------------
__global__ __launch_bounds__(256) void expm_kernel(
    const float* __restrict__ in, float* __restrict__ out)
{
    extern __shared__ float sh[];          // 3 * 4096 floats
    float *B = sh, *P = sh + 4096, *Q = sh + 8192;
    __shared__ float red[256];
    __shared__ float sc_s;
    __shared__ int   j_s;

    const int tid = threadIdx.x;
    const size_t boff = (size_t)blockIdx.x * MATSZ;

    float fa = 0.0f;
    for (int idx = tid; idx < MATSZ; idx += 256) {
        float v = in[boff + idx];
        B[idx] = v;
        fa += v * v;
    }
    red[tid] = fa;
    __syncthreads();
    #pragma unroll
    for (int s = 128; s > 0; s >>= 1) {
        if (tid < s) red[tid] += red[tid + s];
        __syncthreads();
    }
    if (tid == 0) {
        float F = sqrtf(red[0]);
        int j = 0;
        while (F > 0.25f && j < 40) { F *= 0.5f; ++j; }
        j_s = j;
        sc_s = exp2f((float)(-j));
    }
    __syncthreads();
    const int j = j_s;
    float sc = sc_s;
    for (int idx = tid; idx < MATSZ; idx += 256) B[idx] *= sc;
    __syncthreads();

    const float c7 = 1.0f / 5040.0f, c6 = 1.0f / 720.0f;
    for (int idx = tid; idx < MATSZ; idx += 256) {
        float v = c7 * B[idx];
        if ((idx >> 6) == (idx & 63)) v += c6;
        P[idx] = v;
    }
    __syncthreads();
    const float cs[6] = { 1.0f / 120.0f, 1.0f / 24.0f, 1.0f / 6.0f, 0.5f, 1.0f, 1.0f };
    float *cur = P, *oth = Q;
    #pragma unroll
    for (int k = 0; k < 6; ++k) {
        mm64(cur, B, 1.0f, 0.0f, nullptr, cs[k], oth, tid);
        float* t = cur; cur = oth; oth = t;
    }
    for (int t = 0; t < j; ++t) {
        mm64(cur, cur, 1.0f, 0.0f, nullptr, 0.0f, oth, tid);
        float* tt = cur; cur = oth; oth = tt;
    }
    for (int idx = tid; idx < MATSZ; idx += 256)
        out[boff + idx] = cur[idx];
}

// ---------------------------------------------------------------------------
// One-sided (Hestenes) Jacobi eigensolver, symmetric 64x64.
// ---------------------------------------------------------------------------
template <int TPB>
__global__ __launch_bounds__(TPB) void jac1s(
    const float* __restrict__ in, float* __restrict__ out1,
    float* __restrict__ out2, int f1, int f2, int useShift, int nsweeps)
{
    constexpr int NW  = TPB / 32;
    constexpr int PPW = 32 / NW;
    __shared__ float2 As2[NN * 33];
    __shared__ float norms[NN];
    __shared__ float gv[NN], gv2[NN];
    __shared__ float red[TPB];
    __shared__ float shift_s;
    float* Asf = reinterpret_cast<float*>(As2);

    const int tid  = threadIdx.x;
    const int lane = tid & 31;
    const int wid  = tid >> 5;
    const size_t boff = (size_t)blockIdx.x * MATSZ;

    float fa = 0.0f;
    for (int idx = tid; idx < MATSZ; idx += TPB) {
        int c = idx >> 6, r = idx & 63;
        float v = in[boff + idx];
        Asf[c * 66 + r] = v;
        fa += v * v;
    }
    red[tid] = fa;
    __syncthreads();
    if (useShift) {
        #pragma unroll
        for (int s = TPB / 2; s > 0; s >>= 1) {
            if (tid < s) red[tid] += red[tid + s];
            __syncthreads();
        }
        if (tid == 0) shift_s = sqrtf(red[0]) * 1.000001f + 1e-20f;
        __syncthreads();
        if (tid < 64) Asf[tid * 66 + tid] += shift_s;
    } else {
        if (tid == 0) shift_s = 0.0f;
    }
    __syncthreads();

    for (int j = wid; j < 64; j += NW) {
        float2 a = As2[j * 33 + lane];
        float s = a.x * a.x + a.y * a.y;
        #pragma unroll
        for (int o = 16; o; o >>= 1) s += __shfl_xor_sync(0xFFFFFFFFu, s, o);
        if (lane == 0) norms[j] = s;
    }
    __syncthreads();

    for (int sw = 0; sw < nsweeps; ++sw) {
        for (int r = 0; r < 63; ++r) {
            int    p[PPW], q[PPW];
            float2 ap[PPW], aq[PPW];
            float  g[PPW];
            #pragma unroll
            for (int u = 0; u < PPW; ++u) {
                int k = wid + u * NW;
                if (k == 0) { p[u] = 63; q[u] = r; }
                else {
                    int a1 = r + k;      p[u] = (a1 < 63) ? a1 : a1 - 63;
                    int a2 = r + 63 - k; q[u] = (a2 < 63) ? a2 : a2 - 63;
                }
                ap[u] = As2[p[u] * 33 + lane];
                aq[u] = As2[q[u] * 33 + lane];
                g[u] = ap[u].x * aq[u].x + ap[u].y * aq[u].y;
            }
            #pragma unroll
            for (int o = 16; o; o >>= 1) {
                #pragma unroll
                for (int u = 0; u < PPW; ++u)
                    g[u] += __shfl_xor_sync(0xFFFFFFFFu, g[u], o);
            }
            #pragma unroll
            for (int u = 0; u < PPW; ++u) {
                if (g[u] != 0.0f) {
                    float al = norms[p[u]], be = norms[q[u]];
                    float tau = (be - al) / (2.0f * g[u]);
                    float t = 1.0f / (fabsf(tau) + sqrtf(1.0f + tau * tau));
                    if (tau < 0.0f) t = -t;
                    float c = rsqrtf(1.0f + t * t);
                    float s = t * c;
                    float2 np, nq;
                    np.x = c * ap[u].x - s * aq[u].x;
                    np.y = c * ap[u].y - s * aq[u].y;
                    nq.x = s * ap[u].x + c * aq[u].x;
                    nq.y = s * ap[u].y + c * aq[u].y;
                    As2[p[u] * 33 + lane] = np;
                    As2[q[u] * 33 + lane] = nq;
                    if (lane == 0) {
                        float cc = c * c, ss = s * s, cs2 = 2.0f * c * s;
                        norms[p[u]] = cc * al - cs2 * g[u] + ss * be;
                        norms[q[u]] = ss * al + cs2 * g[u] + cc * be;
                    }
                }
            }
            __syncthreads();
        }
    }

    for (int j = wid; j < 64; j += NW) {
        float2 a = As2[j * 33 + lane];
        float s = a.x * a.x + a.y * a.y;
        #pragma unroll
        for (int o = 16; o; o >>= 1) s += __shfl_xor_sync(0xFFFFFFFFu, s, o);
        if (lane == 0) {
            s = fmaxf(s, 1e-30f);
            float lam = sqrtf(s) - shift_s;
            gv[j] = apply_fn(f1, lam) / s;
            if (f2 != F_NONE) gv2[j] = apply_fn(f2, lam) / s;
        }
    }
    __syncthreads();

    constexpr int TRI = MATSZ / TPB / 4;   // 512 -> 2, 1024 -> 1
    const int ti = (tid >> 4) * TRI;
    const int tj = (tid & 15) << 2;
    {
        float acc[TRI][4] = {};
        #pragma unroll 4
        for (int k = 0; k < 64; ++k) {
            const float* ck = Asf + k * 66;
            float gk = gv[k];
            float a[TRI], b[4];
            #pragma unroll
            for (int r = 0; r < TRI; ++r) a[r] = gk * ck[ti + r];
            #pragma unroll
            for (int c = 0; c < 4; ++c) b[c] = ck[tj + c];
            #pragma unroll
            for (int r = 0; r < TRI; ++r)
                #pragma unroll
                for (int c = 0; c < 4; ++c) acc[r][c] += a[r] * b[c];
        }
        #pragma unroll
        for (int r = 0; r < TRI; ++r) {
            float4 v = make_float4(acc[r][0], acc[r][1], acc[r][2], acc[r][3]);
            *reinterpret_cast<float4*>(out1 + boff + (size_t)(ti + r) * 64 + tj) = v;
        }
    }
    if (f2 != F_NONE) {
        float acc[TRI][4] = {};
        #pragma unroll 4
        for (int k = 0; k < 64; ++k) {
            const float* ck = Asf + k * 66;
            float gk = gv2[k];
            float a[TRI], b[4];
            #pragma unroll
            for (int r = 0; r < TRI; ++r) a[r] = gk * ck[ti + r];
            #pragma unroll
            for (int c = 0; c < 4; ++c) b[c] = ck[tj + c];
            #pragma unroll
            for (int r = 0; r < TRI; ++r)
                #pragma unroll
                for (int c = 0; c < 4; ++c) acc[r][c] += a[r] * b[c];
        }
        #pragma unroll
        for (int r = 0; r < TRI; ++r) {
            float4 v = make_float4(acc[r][0], acc[r][1], acc[r][2], acc[r][3]);
            *reinterpret_cast<float4*>(out2 + boff + (size_t)(ti + r) * 64 + tj) = v;
        }
    }
}

// 4x4 register tile inner product: C[ti..][tj..] += op(A) op(B)
template <int TA, int TB>
__device__ __forceinline__ void tile_mm(const float* __restrict__ A,
                                        const float* __restrict__ B,
                                        float acc[4][4], int ti, int tj)
{
    #pragma unroll 4
    for (int k = 0; k < 64; ++k) {
        float a[4], b[4];
        #pragma unroll
        for (int r = 0; r < 4; ++r) a[r] = TA ? A[k * 64 + ti + r] : A[(ti + r) * 64 + k];
        #pragma unroll
        for (int c = 0; c < 4; ++c) b[c] = TB ? B[(tj + c) * 64 + k] : B[k * 64 + tj + c];
        #pragma unroll
        for (int r = 0; r < 4; ++r)
            #pragma unroll
            for (int c = 0; c < 4; ++c) acc[r][c] += a[r] * b[c];
    }
}

// out_b = scale * L @ X_b @ op(R)  (L, R broadcast)
__global__ __launch_bounds__(256) void cong_kernel(
    const float* __restrict__ Lm, const float* __restrict__ Xb,
    const float* __restrict__ Rm, float* __restrict__ out,
    int useScale, int transR)
{
    __shared__ float Ls[MATSZ], Rs[MATSZ], Xs[MATSZ];
    const int tid = threadIdx.x;
    const size_t boff = (size_t)blockIdx.x * MATSZ;
    for (int i = tid; i < MATSZ; i += 256) {
        Ls[i] = Lm[i]; Rs[i] = Rm[i]; Xs[i] = Xb[boff + i];
    }
    __syncthreads();

    const int ti = (tid >> 4) << 2, tj = (tid & 15) << 2;
    float acc[4][4] = {};
    tile_mm<0, 0>(Ls, Xs, acc, ti, tj);
    __syncthreads();
    #pragma unroll
    for (int r = 0; r < 4; ++r)
        #pragma unroll
        for (int c = 0; c < 4; ++c) Xs[(ti + r) * 64 + tj + c] = acc[r][c];
    __syncthreads();

    float sc = useScale ? g_scal[0] : 1.0f;
    float acc2[4][4] = {};
    if (transR) tile_mm<0, 1>(Xs, Rs, acc2, ti, tj);
    else        tile_mm<0, 0>(Xs, Rs, acc2, ti, tj);
    #pragma unroll
    for (int r = 0; r < 4; ++r) {
        float4 v = make_float4(acc2[r][0] * sc, acc2[r][1] * sc,
                               acc2[r][2] * sc, acc2[r][3] * sc);
        *reinterpret_cast<float4*>(out + boff + (size_t)(ti + r) * 64 + tj) = v;
    }
}

// out_b = A_b @ B_(b*strideB)   (strideB = 0 broadcasts B)
__global__ __launch_bounds__(256) void gemmB_kernel(
    const float* __restrict__ A, const float* __restrict__ Bm, int strideB,
    float* __restrict__ out)
{
    __shared__ float As_[MATSZ], Bs_[MATSZ];
    const int tid = threadIdx.x;
    const size_t boff = (size_t)blockIdx.x * MATSZ;
    const float* Bb = Bm + (size_t)blockIdx.x * strideB;
    for (int i = tid; i < MATSZ; i += 256) { As_[i] = A[boff + i]; Bs_[i] = Bb[i]; }
    __syncthreads();
    const int ti = (tid >> 4) << 2, tj = (tid & 15) << 2;
    float acc[4][4] = {};
    tile_mm<0, 0>(As_, Bs_, acc, ti, tj);
    #pragma unroll
    for (int r = 0; r < 4; ++r) {
        float4 v = make_float4(acc[r][0], acc[r][1], acc[r][2], acc[r][3]);
        *reinterpret_cast<float4*>(out + boff + (size_t)(ti + r) * 64 + tj) = v;
    }
}

// single 64x64 gemm: C = op(A) @ B
__global__ __launch_bounds__(256) void gemm1_kernel(
    const float* __restrict__ A, const float* __restrict__ B,
    float* __restrict__ C, int transA)
{
    __shared__ float As_[MATSZ], Bs_[MATSZ];
    const int tid = threadIdx.x;
    for (int i = tid; i < MATSZ; i += 256) { As_[i] = A[i]; Bs_[i] = B[i]; }
    __syncthreads();
    const int ti = (tid >> 4) << 2, tj = (tid & 15) << 2;
    float acc[4][4] = {};
    if (transA) tile_mm<1, 0>(As_, Bs_, acc, ti, tj);
    else        tile_mm<0, 0>(As_, Bs_, acc, ti, tj);
    #pragma unroll
    for (int r = 0; r < 4; ++r) {
        float4 v = make_float4(acc[r][0], acc[r][1], acc[r][2], acc[r][3]);
        *reinterpret_cast<float4*>(C + (size_t)(ti + r) * 64 + tj) = v;
    }
}

// out[e] = mean_b in[b*4096 + e]
__global__ void mean_kernel(const float* __restrict__ in, float* __restrict__ out)
{
    int e = blockIdx.x * blockDim.x + threadIdx.x;
    double a0 = 0, a1 = 0, a2 = 0, a3 = 0;
    for (int b = 0; b < NB; b += 4) {
        a0 += (double)in[(size_t)(b + 0) * MATSZ + e];
        a1 += (double)in[(size_t)(b + 1) * MATSZ + e];
        a2 += (double)in[(size_t)(b + 2) * MATSZ + e];
        a3 += (double)in[(size_t)(b + 3) * MATSZ + e];
    }
    out[e] = (float)((a0 + a1 + a2 + a3) * (1.0 / (double)NB));
}

// deterministic two-pass sum of squares
__global__ __launch_bounds__(256) void sumsq_kernel(const float* __restrict__ in)
{
    __shared__ double sh[256];
    const int tid = threadIdx.x;
    const size_t base = (size_t)blockIdx.x * 65536;
    double a = 0;
    for (int i = tid; i < 65536; i += 256) {
        float v = in[base + i];
        a += (double)v * (double)v;
    }
    sh[tid] = a;
    __syncthreads();
    for (int s = 128; s > 0; s >>= 1) {
        if (tid < s) sh[tid] += sh[tid + s];
        __syncthreads();
    }
    if (tid == 0) g_part[blockIdx.x] = sh[0];
}

__global__ void finalize_kernel(const float* __restrict__ shift)
{
    __shared__ double sh[256];
    const int tid = threadIdx.x;
    sh[tid] = g_part[tid];
    __syncthreads();
    for (int s = 128; s > 0; s >>= 1) {
        if (tid < s) sh[tid] += sh[tid + s];
        __syncthreads();
    }
    if (tid == 0) {
        double var = sh[0] / (double)NB;
        g_scal[0] = shift[0] / (float)sqrt(var + 1e-5);
    }
}

extern "C" void kernel_launch(void* const* d_in, const int* in_sizes, int n_in,
                              void* d_out, int out_size)
{
    const float* X     = (const float*)d_in[0];
    const float* W     = (const float*)d_in[1];
    const float* M     = (const float*)d_in[2];
    const float* shift = (const float*)d_in[3];
    float* out = (float*)d_out;

    float *bufA, *bufB, *bufC, *bufD, *sm;
    cudaGetSymbolAddress((void**)&bufA, g_bufA);
    cudaGetSymbolAddress((void**)&bufB, g_bufB);
    cudaGetSymbolAddress((void**)&bufC, g_bufC);
    cudaGetSymbolAddress((void**)&bufD, g_bufD);
    cudaGetSymbolAddress((void**)&sm,   g_small);

    cudaFuncSetAttribute(nssqrt_kernel, cudaFuncAttributeMaxDynamicSharedMemorySize, 65536);
    cudaFuncSetAttribute(expm_kernel,   cudaFuncAttributeMaxDynamicSharedMemorySize, 49152);

    #define SLOT(i) (sm + (i) * MATSZ)
    // slots: 0 Mh, 1 Mnh, 2 Wh, 3 tmp, 4 Wc, 5 Wch, 6 Wcnh, 7 P, 8 Q, 9 R,
    //        10 G0, 11 G0h, 12 G0nh, 13 Tm, 14 expTm, 15 G, 16 mnh

    // parameter prep (tiny single-matrix ops; 8 sweeps, negligible cost)
    jac1s<1024><<<1, 1024>>>(M, SLOT(0), SLOT(1), F_SQRT, F_INVSQRT, 0, 8);   // Mh, Mnh
    jac1s<1024><<<1, 1024>>>(W, SLOT(2), SLOT(2), F_SQRT, F_NONE, 0, 8);      // Wh
    gemm1_kernel<<<1, 256>>>(SLOT(1), SLOT(2), SLOT(3), 0);                   // Mnh Wh
    gemm1_kernel<<<1, 256>>>(SLOT(3), SLOT(1), SLOT(4), 0);                   // Wc
    jac1s<1024><<<1, 1024>>>(SLOT(4), SLOT(5), SLOT(6), F_SQRT, F_INVSQRT, 0, 8); // Wch, Wcnh
    gemm1_kernel<<<1, 256>>>(SLOT(6), SLOT(2), SLOT(7), 0);                   // P = Wcnh Wh
    gemm1_kernel<<<1, 256>>>(SLOT(0), SLOT(5), SLOT(8), 0);                   // Q = Mh Wch
    gemm1_kernel<<<1, 256>>>(SLOT(8), SLOT(8), SLOT(9), 1);                   // R = Q^T Q

    // Xp = X^{1/2} (Newton-Schulz); Xc = Mnh Xp Mnh
    nssqrt_kernel<<<NB, 256, 65536>>>(X, bufA);
    cong_kernel<<<NB, 256>>>(SLOT(1), bufA, SLOT(1), bufB, 0, 0);             // Xc

    // bary_geom: 1 Karcher step from arithmetic mean
    mean_kernel<<<16, 256>>>(bufB, SLOT(10));                                 // G0
    jac1s<1024><<<1, 1024>>>(SLOT(10), SLOT(11), SLOT(12), F_SQRT, F_INVSQRT, 0, 8);
    cong_kernel<<<NB, 256>>>(SLOT(12), bufB, SLOT(12), bufC, 0, 0);
    jac1s<512><<<NB, 512>>>(bufC, bufA, bufA, F_LOG, F_NONE, 0, 6);
    mean_kernel<<<16, 256>>>(bufA, SLOT(13));                                 // Tm
    jac1s<1024><<<1, 1024>>>(SLOT(13), SLOT(14), SLOT(14), F_EXP, F_NONE, 1, 8); // exp (shift)
    gemm1_kernel<<<1, 256>>>(SLOT(11), SLOT(14), SLOT(3), 0);
    gemm1_kernel<<<1, 256>>>(SLOT(3), SLOT(11), SLOT(15), 0);                 // G
    jac1s<1024><<<1, 1024>>>(SLOT(15), SLOT(16), SLOT(16), F_INVSQRT, F_NONE, 0, 8); // mnh

    // tangent at I, variance, scale
    cong_kernel<<<NB, 256>>>(SLOT(16), bufB, SLOT(16), bufC, 0, 0);
    jac1s<512><<<NB, 512>>>(bufC, bufD, bufD, F_LOG, F_NONE, 0, 6);           // T0
    sumsq_kernel<<<256, 256>>>(bufD);
    finalize_kernel<<<1, 256>>>(shift);

    // arg = factor * P T0 P^T ; E = exp(arg) (scaling & squaring)
    cong_kernel<<<NB, 256>>>(SLOT(7), bufD, SLOT(7), bufC, 1, 1);
    expm_kernel<<<NB, 256, 49152>>>(bufC, bufA);                              // E

    // out = Q (E R E) Q^T
    gemmB_kernel<<<NB, 256>>>(bufA, SLOT(9), 0, bufC);                        // E R
    gemmB_kernel<<<NB, 256>>>(bufC, bufA, MATSZ, bufD);                       // (E R) E
    cong_kernel<<<NB, 256>>>(SLOT(8), bufD, SLOT(8), out, 0, 1);
    #undef SLOT
}

// round 9
// speedup vs baseline: 1.5681x; 1.4145x over previous
#include <cuda_runtime.h>
#include <math.h>

#define NN 64
#define MATSZ 4096
#define NB 4096

enum { F_NONE = -1, F_SQRT = 0, F_INVSQRT = 1, F_LOG = 2, F_EXP = 3 };

// device-global scratch (no runtime allocation allowed)
__device__ float  g_bufA[(size_t)NB * MATSZ];
__device__ float  g_bufB[(size_t)NB * MATSZ];
__device__ float  g_bufC[(size_t)NB * MATSZ];
__device__ float  g_bufD[(size_t)NB * MATSZ];
__device__ float  g_small[20 * MATSZ];
__device__ double g_part[256];
__device__ float  g_scal[4];

__device__ __forceinline__ float apply_fn(int f, float w) {
    switch (f) {
        case F_SQRT:    return sqrtf(fmaxf(w, 0.0f));
        case F_INVSQRT: return rsqrtf(fmaxf(w, 1e-30f));
        case F_LOG:     return logf(fmaxf(w, 1e-30f));
        case F_EXP:     return expf(w);
    }
    return w;
}

// ---------------------------------------------------------------------------
// In-shared 64x64 GEMM helper: C = alpha*(A@B) + beta*D + diag*I.
// 256 threads, 4x4 tiles. C must differ from A and B.
// ---------------------------------------------------------------------------
__device__ __forceinline__ void mm64(const float* __restrict__ A,
                                     const float* __restrict__ B,
                                     float alpha, float beta,
                                     const float* __restrict__ D,
                                     float diag, float* __restrict__ C, int tid)
{
    const int ti = (tid >> 4) << 2, tj = (tid & 15) << 2;
    float acc[4][4] = {};
    #pragma unroll 4
    for (int k = 0; k < 64; ++k) {
        float a0 = A[(ti + 0) * 64 + k], a1 = A[(ti + 1) * 64 + k];
        float a2 = A[(ti + 2) * 64 + k], a3 = A[(ti + 3) * 64 + k];
        float4 b = *reinterpret_cast<const float4*>(B + k * 64 + tj);
        acc[0][0] += a0 * b.x; acc[0][1] += a0 * b.y; acc[0][2] += a0 * b.z; acc[0][3] += a0 * b.w;
        acc[1][0] += a1 * b.x; acc[1][1] += a1 * b.y; acc[1][2] += a1 * b.z; acc[1][3] += a1 * b.w;
        acc[2][0] += a2 * b.x; acc[2][1] += a2 * b.y; acc[2][2] += a2 * b.z; acc[2][3] += a2 * b.w;
        acc[3][0] += a3 * b.x; acc[3][1] += a3 * b.y; acc[3][2] += a3 * b.z; acc[3][3] += a3 * b.w;
    }
    __syncthreads();
    #pragma unroll
    for (int r = 0; r < 4; ++r) {
        float4 v;
        v.x = alpha * acc[r][0]; v.y = alpha * acc[r][1];
        v.z = alpha * acc[r][2]; v.w = alpha * acc[r][3];
        if (beta != 0.0f) {
            float4 d = *reinterpret_cast<const float4*>(D + (ti + r) * 64 + tj);
            v.x += beta * d.x; v.y += beta * d.y; v.z += beta * d.z; v.w += beta * d.w;
        }
        if (diag != 0.0f) {
            int row = ti + r;
            if (row >= tj && row < tj + 4) (&v.x)[row - tj] += diag;
        }
        *reinterpret_cast<float4*>(C + (ti + r) * 64 + tj) = v;
    }
    __syncthreads();
}

// ---------------------------------------------------------------------------
// Batched matrix sqrt via coupled Newton-Schulz (Higham). One CTA/matrix.
// ---------------------------------------------------------------------------
__global__ __launch_bounds__(256) void nssqrt_kernel(
    const float* __restrict__ in, float* __restrict__ out)
{
    extern __shared__ float sh[];          // 4 * 4096 floats
    float *Y = sh, *Z = sh + 4096, *W = sh + 8192, *T = sh + 12288;
    __shared__ float red[256];
    __shared__ float s_s;

    const int tid = threadIdx.x;
    const size_t boff = (size_t)blockIdx.x * MATSZ;

    float fa = 0.0f;
    for (int idx = tid; idx < MATSZ; idx += 256) {
        float v = in[boff + idx];
        Y[idx] = v;
        fa += v * v;
        Z[idx] = ((idx >> 6) == (idx & 63)) ? 1.0f : 0.0f;
    }
    red[tid] = fa;
    __syncthreads();
    #pragma unroll
    for (int s = 128; s > 0; s >>= 1) {
        if (tid < s) red[tid] += red[tid + s];
        __syncthreads();
    }
    if (tid == 0) s_s = fmaxf(sqrtf(red[0]) / 1.8f, 1e-20f);
    __syncthreads();
    float inv_s = 1.0f / s_s;
    for (int idx = tid; idx < MATSZ; idx += 256) Y[idx] *= inv_s;
    __syncthreads();

    for (int it = 0; it < 10; ++it) {
        mm64(Z, Y, 1.0f, 0.0f, nullptr, 0.0f, W, tid);      // W = Z@Y
        mm64(Y, W, -0.5f, 1.5f, Y, 0.0f, T, tid);           // T = 1.5Y - 0.5 Y@W
        if (it < 9) {
            mm64(W, Z, -0.5f, 1.5f, Z, 0.0f, Y, tid);       // Znew -> old Y buffer
            float* nY = T; float* nZ = Y; float* nT = Z;
            Y = nY; Z = nZ; T = nT;
        } else {
            Y = T;
        }
    }
    float rs = sqrtf(s_s);
    for (int idx = tid; idx < MATSZ; idx += 256)
        out[boff + idx] = Y[idx] * rs;
}

// ---------------------------------------------------------------------------
// Batched matrix exp via scaling-and-squaring + degree-7 Taylor (Horner).
// ---------------------------------------------------------------------------
__global__ __launch_bounds__(256) void expm_kernel(
    const float* __restrict__ in, float* __restrict__ out)
{
    extern __shared__ float sh[];          // 3 * 4096 floats
    float *B = sh, *P = sh + 4096, *Q = sh + 8192;
    __shared__ float red[256];
    __shared__ float sc_s;
    __shared__ int   j_s;

    const int tid = threadIdx.x;
    const size_t boff = (size_t)blockIdx.x * MATSZ;

    float fa = 0.0f;
    for (int idx = tid; idx < MATSZ; idx += 256) {
        float v = in[boff + idx];
        B[idx] = v;
        fa += v * v;
    }
    red[tid] = fa;
    __syncthreads();
    #pragma unroll
    for (int s = 128; s > 0; s >>= 1) {
        if (tid < s) red[tid] += red[tid + s];
        __syncthreads();
    }
    if (tid == 0) {
        float F = sqrtf(red[0]);
        int j = 0;
        while (F > 0.25f && j < 40) { F *= 0.5f; ++j; }
        j_s = j;
        sc_s = exp2f((float)(-j));
    }
    __syncthreads();
    const int j = j_s;
    float sc = sc_s;
    for (int idx = tid; idx < MATSZ; idx += 256) B[idx] *= sc;
    __syncthreads();

    const float c7 = 1.0f / 5040.0f, c6 = 1.0f / 720.0f;
    for (int idx = tid; idx < MATSZ; idx += 256) {
        float v = c7 * B[idx];
        if ((idx >> 6) == (idx & 63)) v += c6;
        P[idx] = v;
    }
    __syncthreads();
    const float cs[6] = { 1.0f / 120.0f, 1.0f / 24.0f, 1.0f / 6.0f, 0.5f, 1.0f, 1.0f };
    float *cur = P, *oth = Q;
    #pragma unroll
    for (int k = 0; k < 6; ++k) {
        mm64(cur, B, 1.0f, 0.0f, nullptr, cs[k], oth, tid);
        float* t = cur; cur = oth; oth = t;
    }
    for (int t = 0; t < j; ++t) {
        mm64(cur, cur, 1.0f, 0.0f, nullptr, 0.0f, oth, tid);
        float* tt = cur; cur = oth; oth = tt;
    }
    for (int idx = tid; idx < MATSZ; idx += 256)
        out[boff + idx] = cur[idx];
}

// ---------------------------------------------------------------------------
// One-sided (Hestenes) Jacobi, symmetric 64x64 — half-warp float4 version.
// 512 threads = 16 warps = 32 half-warps; each half-warp owns one pair per
// round (lane holds 4 elements as float4, columns at stride 68 floats =
// 272B, 16B-aligned). 16-lane butterfly = 4 SHFLs serving two pairs per
// warp in lockstep. Pair indices precomputed in a shared table.
// Column norms cached & updated analytically; recon from rotated columns:
//    V f(L) V^T = sum_j [f(lam_j)/||a'_j||^2] a'_j a'_j^T.
// Indefinite input (useShift): diagonalize A + c*I, apply f(lam - c).
// ---------------------------------------------------------------------------
__global__ __launch_bounds__(512) void jac1s512(
    const float* __restrict__ in, float* __restrict__ out1,
    float* __restrict__ out2, int f1, int f2, int useShift, int nsweeps)
{
    __shared__ float  As[64 * 68];         // column j at As + j*68
    __shared__ float  norms[64];
    __shared__ float  gv[64], gv2[64];
    __shared__ float  red[512];
    __shared__ float  shift_s;
    __shared__ uchar2 ptab[63 * 32];

    const int tid  = threadIdx.x;
    const int lane = tid & 31;
    const int wid  = tid >> 5;
    const int sl   = lane & 15;            // sublane within half-warp
    const int k    = (wid << 1) | (lane >> 4);  // pair slot 0..31
    const size_t boff = (size_t)blockIdx.x * MATSZ;

    // pair table: round r slot kk
    for (int i = tid; i < 63 * 32; i += 512) {
        int r = i >> 5, kk = i & 31;
        int p, q;
        if (kk == 0) { p = 63; q = r; }
        else {
            int a1 = r + kk;      p = (a1 < 63) ? a1 : a1 - 63;
            int a2 = r + 63 - kk; q = (a2 < 63) ? a2 : a2 - 63;
        }
        ptab[i] = make_uchar2((unsigned char)p, (unsigned char)q);
    }

    // load (symmetric: row c == column c); accumulate frob^2
    float fa = 0.0f;
    for (int idx = tid; idx < MATSZ; idx += 512) {
        int c = idx >> 6, r = idx & 63;
        float v = in[boff + idx];
        As[c * 68 + r] = v;
        fa += v * v;
    }
    red[tid] = fa;
    __syncthreads();
    if (useShift) {
        #pragma unroll
        for (int s = 256; s > 0; s >>= 1) {
            if (tid < s) red[tid] += red[tid + s];
            __syncthreads();
        }
        if (tid == 0) shift_s = sqrtf(red[0]) * 1.000001f + 1e-20f;
        __syncthreads();
        if (tid < 64) As[tid * 68 + tid] += shift_s;
    } else {
        if (tid == 0) shift_s = 0.0f;
    }
    __syncthreads();

    // initial column norms: 32 half-warps x 2 columns
    for (int j = k; j < 64; j += 32) {
        float4 a = *reinterpret_cast<const float4*>(As + j * 68 + sl * 4);
        float s = a.x * a.x + a.y * a.y + a.z * a.z + a.w * a.w;
        #pragma unroll
        for (int o = 8; o; o >>= 1) s += __shfl_xor_sync(0xFFFFFFFFu, s, o);
        if (sl == 0) norms[j] = s;
    }
    __syncthreads();

    // sweeps: 63 rounds x 32 disjoint pairs, one pair per half-warp
    for (int sw = 0; sw < nsweeps; ++sw) {
        for (int r = 0; r < 63; ++r) {
            uchar2 pq = ptab[(r << 5) | k];
            const int p = pq.x, q = pq.y;
            float4* cp = reinterpret_cast<float4*>(As + p * 68);
            float4* cq = reinterpret_cast<float4*>(As + q * 68);
            float4 ap = cp[sl];
            float4 aq = cq[sl];
            float g = ap.x * aq.x + ap.y * aq.y + ap.z * aq.z + ap.w * aq.w;
            #pragma unroll
            for (int o = 8; o; o >>= 1) g += __shfl_xor_sync(0xFFFFFFFFu, g, o);
            if (g != 0.0f) {
                float al = norms[p], be = norms[q];
                float tau = (be - al) / (2.0f * g);
                float t = 1.0f / (fabsf(tau) + sqrtf(1.0f + tau * tau));
                if (tau < 0.0f) t = -t;
                float c = rsqrtf(1.0f + t * t);
                float s = t * c;
                float4 np, nq;
                np.x = c * ap.x - s * aq.x;  nq.x = s * ap.x + c * aq.x;
                np.y = c * ap.y - s * aq.y;  nq.y = s * ap.y + c * aq.y;
                np.z = c * ap.z - s * aq.z;  nq.z = s * ap.z + c * aq.z;
                np.w = c * ap.w - s * aq.w;  nq.w = s * ap.w + c * aq.w;
                cp[sl] = np;
                cq[sl] = nq;
                if (sl == 0) {
                    float cc = c * c, ss = s * s, cs2 = 2.0f * c * s;
                    norms[p] = cc * al - cs2 * g + ss * be;
                    norms[q] = ss * al + cs2 * g + cc * be;
                }
            }
            __syncthreads();
        }
    }

    // exact final norms -> eigenvalues -> reconstruction coefficients
    for (int j = k; j < 64; j += 32) {
        float4 a = *reinterpret_cast<const float4*>(As + j * 68 + sl * 4);
        float s = a.x * a.x + a.y * a.y + a.z * a.z + a.w * a.w;
        #pragma unroll
        for (int o = 8; o; o >>= 1) s += __shfl_xor_sync(0xFFFFFFFFu, s, o);
        if (sl == 0) {
            s = fmaxf(s, 1e-30f);
            float lam = sqrtf(s) - shift_s;
            gv[j] = apply_fn(f1, lam) / s;
            if (f2 != F_NONE) gv2[j] = apply_fn(f2, lam) / s;
        }
    }
    __syncthreads();

    // out = sum_kk gv[kk] * col_kk col_kk^T   (2x4 register tiles)
    const int ti = (tid >> 4) * 2;
    const int tj = (tid & 15) << 2;
    {
        float acc[2][4] = {};
        #pragma unroll 4
        for (int kk = 0; kk < 64; ++kk) {
            const float* ck = As + kk * 68;
            float gk = gv[kk];
            float a0 = gk * ck[ti], a1 = gk * ck[ti + 1];
            float b0 = ck[tj], b1 = ck[tj + 1], b2 = ck[tj + 2], b3 = ck[tj + 3];
            acc[0][0] += a0 * b0; acc[0][1] += a0 * b1; acc[0][2] += a0 * b2; acc[0][3] += a0 * b3;
            acc[1][0] += a1 * b0; acc[1][1] += a1 * b1; acc[1][2] += a1 * b2; acc[1][3] += a1 * b3;
        }
        #pragma unroll
        for (int r = 0; r < 2; ++r) {
            float4 v = make_float4(acc[r][0], acc[r][1], acc[r][2], acc[r][3]);
            *reinterpret_cast<float4*>(out1 + boff + (size_t)(ti + r) * 64 + tj) = v;
        }
    }
    if (f2 != F_NONE) {
        float acc[2][4] = {};
        #pragma unroll 4
        for (int kk = 0; kk < 64; ++kk) {
            const float* ck = As + kk * 68;
            float gk = gv2[kk];
            float a0 = gk * ck[ti], a1 = gk * ck[ti + 1];
            float b0 = ck[tj], b1 = ck[tj + 1], b2 = ck[tj + 2], b3 = ck[tj + 3];
            acc[0][0] += a0 * b0; acc[0][1] += a0 * b1; acc[0][2] += a0 * b2; acc[0][3] += a0 * b3;
            acc[1][0] += a1 * b0; acc[1][1] += a1 * b1; acc[1][2] += a1 * b2; acc[1][3] += a1 * b3;
        }
        #pragma unroll
        for (int r = 0; r < 2; ++r) {
            float4 v = make_float4(acc[r][0], acc[r][1], acc[r][2], acc[r][3]);
            *reinterpret_cast<float4*>(out2 + boff + (size_t)(ti + r) * 64 + tj) = v;
        }
    }
}

// 4x4 register tile inner product: C[ti..][tj..] += op(A) op(B)
template <int TA, int TB>
__device__ __forceinline__ void tile_mm(const float* __restrict__ A,
                                        const float* __restrict__ B,
                                        float acc[4][4], int ti, int tj)
{
    #pragma unroll 4
    for (int k = 0; k < 64; ++k) {
        float a[4], b[4];
        #pragma unroll
        for (int r = 0; r < 4; ++r) a[r] = TA ? A[k * 64 + ti + r] : A[(ti + r) * 64 + k];
        #pragma unroll
        for (int c = 0; c < 4; ++c) b[c] = TB ? B[(tj + c) * 64 + k] : B[k * 64 + tj + c];
        #pragma unroll
        for (int r = 0; r < 4; ++r)
            #pragma unroll
            for (int c = 0; c < 4; ++c) acc[r][c] += a[r] * b[c];
    }
}

// out_b = scale * L @ X_b @ op(R)  (L, R broadcast)
__global__ __launch_bounds__(256) void cong_kernel(
    const float* __restrict__ Lm, const float* __restrict__ Xb,
    const float* __restrict__ Rm, float* __restrict__ out,
    int useScale, int transR)
{
    __shared__ float Ls[MATSZ], Rs[MATSZ], Xs[MATSZ];
    const int tid = threadIdx.x;
    const size_t boff = (size_t)blockIdx.x * MATSZ;
    for (int i = tid; i < MATSZ; i += 256) {
        Ls[i] = Lm[i]; Rs[i] = Rm[i]; Xs[i] = Xb[boff + i];
    }
    __syncthreads();

    const int ti = (tid >> 4) << 2, tj = (tid & 15) << 2;
    float acc[4][4] = {};
    tile_mm<0, 0>(Ls, Xs, acc, ti, tj);
    __syncthreads();
    #pragma unroll
    for (int r = 0; r < 4; ++r)
        #pragma unroll
        for (int c = 0; c < 4; ++c) Xs[(ti + r) * 64 + tj + c] = acc[r][c];
    __syncthreads();

    float sc = useScale ? g_scal[0] : 1.0f;
    float acc2[4][4] = {};
    if (transR) tile_mm<0, 1>(Xs, Rs, acc2, ti, tj);
    else        tile_mm<0, 0>(Xs, Rs, acc2, ti, tj);
    #pragma unroll
    for (int r = 0; r < 4; ++r) {
        float4 v = make_float4(acc2[r][0] * sc, acc2[r][1] * sc,
                               acc2[r][2] * sc, acc2[r][3] * sc);
        *reinterpret_cast<float4*>(out + boff + (size_t)(ti + r) * 64 + tj) = v;
    }
}

// out_b = A_b @ B_(b*strideB)   (strideB = 0 broadcasts B)
__global__ __launch_bounds__(256) void gemmB_kernel(
    const float* __restrict__ A, const float* __restrict__ Bm, int strideB,
    float* __restrict__ out)
{
    __shared__ float As_[MATSZ], Bs_[MATSZ];
    const int tid = threadIdx.x;
    const size_t boff = (size_t)blockIdx.x * MATSZ;
    const float* Bb = Bm + (size_t)blockIdx.x * strideB;
    for (int i = tid; i < MATSZ; i += 256) { As_[i] = A[boff + i]; Bs_[i] = Bb[i]; }
    __syncthreads();
    const int ti = (tid >> 4) << 2, tj = (tid & 15) << 2;
    float acc[4][4] = {};
    tile_mm<0, 0>(As_, Bs_, acc, ti, tj);
    #pragma unroll
    for (int r = 0; r < 4; ++r) {
        float4 v = make_float4(acc[r][0], acc[r][1], acc[r][2], acc[r][3]);
        *reinterpret_cast<float4*>(out + boff + (size_t)(ti + r) * 64 + tj) = v;
    }
}

// single 64x64 gemm: C = op(A) @ B
__global__ __launch_bounds__(256) void gemm1_kernel(
    const float* __restrict__ A, const float* __restrict__ B,
    float* __restrict__ C, int transA)
{
    __shared__ float As_[MATSZ], Bs_[MATSZ];
    const int tid = threadIdx.x;
    for (int i = tid; i < MATSZ; i += 256) { As_[i] = A[i]; Bs_[i] = B[i]; }
    __syncthreads();
    const int ti = (tid >> 4) << 2, tj = (tid & 15) << 2;
    float acc[4][4] = {};
    if (transA) tile_mm<1, 0>(As_, Bs_, acc, ti, tj);
    else        tile_mm<0, 0>(As_, Bs_, acc, ti, tj);
    #pragma unroll
    for (int r = 0; r < 4; ++r) {
        float4 v = make_float4(acc[r][0], acc[r][1], acc[r][2], acc[r][3]);
        *reinterpret_cast<float4*>(C + (size_t)(ti + r) * 64 + tj) = v;
    }
}

// out[e] = mean_b in[b*4096 + e]
__global__ void mean_kernel(const float* __restrict__ in, float* __restrict__ out)
{
    int e = blockIdx.x * blockDim.x + threadIdx.x;
    double a0 = 0, a1 = 0, a2 = 0, a3 = 0;
    for (int b = 0; b < NB; b += 4) {
        a0 += (double)in[(size_t)(b + 0) * MATSZ + e];
        a1 += (double)in[(size_t)(b + 1) * MATSZ + e];
        a2 += (double)in[(size_t)(b + 2) * MATSZ + e];
        a3 += (double)in[(size_t)(b + 3) * MATSZ + e];
    }
    out[e] = (float)((a0 + a1 + a2 + a3) * (1.0 / (double)NB));
}

// deterministic two-pass sum of squares
__global__ __launch_bounds__(256) void sumsq_kernel(const float* __restrict__ in)
{
    __shared__ double sh[256];
    const int tid = threadIdx.x;
    const size_t base = (size_t)blockIdx.x * 65536;
    double a = 0;
    for (int i = tid; i < 65536; i += 256) {
        float v = in[base + i];
        a += (double)v * (double)v;
    }
    sh[tid] = a;
    __syncthreads();
    for (int s = 128; s > 0; s >>= 1) {
        if (tid < s) sh[tid] += sh[tid + s];
        __syncthreads();
    }
    if (tid == 0) g_part[blockIdx.x] = sh[0];
}

__global__ void finalize_kernel(const float* __restrict__ shift)
{
    __shared__ double sh[256];
    const int tid = threadIdx.x;
    sh[tid] = g_part[tid];
    __syncthreads();
    for (int s = 128; s > 0; s >>= 1) {
        if (tid < s) sh[tid] += sh[tid + s];
        __syncthreads();
    }
    if (tid == 0) {
        double var = sh[0] / (double)NB;
        g_scal[0] = shift[0] / (float)sqrt(var + 1e-5);
    }
}

extern "C" void kernel_launch(void* const* d_in, const int* in_sizes, int n_in,
                              void* d_out, int out_size)
{
    const float* X     = (const float*)d_in[0];
    const float* W     = (const float*)d_in[1];
    const float* M     = (const float*)d_in[2];
    const float* shift = (const float*)d_in[3];
    float* out = (float*)d_out;

    float *bufA, *bufB, *bufC, *bufD, *sm;
    cudaGetSymbolAddress((void**)&bufA, g_bufA);
    cudaGetSymbolAddress((void**)&bufB, g_bufB);
    cudaGetSymbolAddress((void**)&bufC, g_bufC);
    cudaGetSymbolAddress((void**)&bufD, g_bufD);
    cudaGetSymbolAddress((void**)&sm,   g_small);

    cudaFuncSetAttribute(nssqrt_kernel, cudaFuncAttributeMaxDynamicSharedMemorySize, 65536);
    cudaFuncSetAttribute(expm_kernel,   cudaFuncAttributeMaxDynamicSharedMemorySize, 49152);

    #define SLOT(i) (sm + (i) * MATSZ)
    // slots: 0 Mh, 1 Mnh, 2 Wh, 3 tmp, 4 Wc, 5 Wch, 6 Wcnh, 7 P, 8 Q, 9 R,
    //        10 G0, 11 G0h, 12 G0nh, 13 Tm, 14 expTm, 15 G, 16 mnh

    // parameter prep (tiny single-matrix ops; 8 sweeps, negligible cost)
    jac1s512<<<1, 512>>>(M, SLOT(0), SLOT(1), F_SQRT, F_INVSQRT, 0, 8);       // Mh, Mnh
    jac1s512<<<1, 512>>>(W, SLOT(2), SLOT(2), F_SQRT, F_NONE, 0, 8);          // Wh
    gemm1_kernel<<<1, 256>>>(SLOT(1), SLOT(2), SLOT(3), 0);                   // Mnh Wh
    gemm1_kernel<<<1, 256>>>(SLOT(3), SLOT(1), SLOT(4), 0);                   // Wc
    jac1s512<<<1, 512>>>(SLOT(4), SLOT(5), SLOT(6), F_SQRT, F_INVSQRT, 0, 8); // Wch, Wcnh
    gemm1_kernel<<<1, 256>>>(SLOT(6), SLOT(2), SLOT(7), 0);                   // P = Wcnh Wh
    gemm1_kernel<<<1, 256>>>(SLOT(0), SLOT(5), SLOT(8), 0);                   // Q = Mh Wch
    gemm1_kernel<<<1, 256>>>(SLOT(8), SLOT(8), SLOT(9), 1);                   // R = Q^T Q

    // Xp = X^{1/2} (Newton-Schulz); Xc = Mnh Xp Mnh
    nssqrt_kernel<<<NB, 256, 65536>>>(X, bufA);
    cong_kernel<<<NB, 256>>>(SLOT(1), bufA, SLOT(1), bufB, 0, 0);             // Xc

    // bary_geom: 1 Karcher step from arithmetic mean
    mean_kernel<<<16, 256>>>(bufB, SLOT(10));                                 // G0
    jac1s512<<<1, 512>>>(SLOT(10), SLOT(11), SLOT(12), F_SQRT, F_INVSQRT, 0, 8);
    cong_kernel<<<NB, 256>>>(SLOT(12), bufB, SLOT(12), bufC, 0, 0);
    jac1s512<<<NB, 512>>>(bufC, bufA, bufA, F_LOG, F_NONE, 0, 6);
    mean_kernel<<<16, 256>>>(bufA, SLOT(13));                                 // Tm
    jac1s512<<<1, 512>>>(SLOT(13), SLOT(14), SLOT(14), F_EXP, F_NONE, 1, 8);  // exp (shift)
    gemm1_kernel<<<1, 256>>>(SLOT(11), SLOT(14), SLOT(3), 0);
    gemm1_kernel<<<1, 256>>>(SLOT(3), SLOT(11), SLOT(15), 0);                 // G
    jac1s512<<<1, 512>>>(SLOT(15), SLOT(16), SLOT(16), F_INVSQRT, F_NONE, 0, 8); // mnh

    // tangent at I, variance, scale
    cong_kernel<<<NB, 256>>>(SLOT(16), bufB, SLOT(16), bufC, 0, 0);
    jac1s512<<<NB, 512>>>(bufC, bufD, bufD, F_LOG, F_NONE, 0, 6);             // T0
    sumsq_kernel<<<256, 256>>>(bufD);
    finalize_kernel<<<1, 256>>>(shift);

    // arg = factor * P T0 P^T ; E = exp(arg) (scaling & squaring)
    cong_kernel<<<NB, 256>>>(SLOT(7), bufD, SLOT(7), bufC, 1, 1);
    expm_kernel<<<NB, 256, 49152>>>(bufC, bufA);                              // E

    // out = Q (E R E) Q^T
    gemmB_kernel<<<NB, 256>>>(bufA, SLOT(9), 0, bufC);                        // E R
    gemmB_kernel<<<NB, 256>>>(bufC, bufA, MATSZ, bufD);                       // (E R) E
    cong_kernel<<<NB, 256>>>(SLOT(8), bufD, SLOT(8), out, 0, 1);
    #undef SLOT
}

// round 10
// speedup vs baseline: 1.8195x; 1.1603x over previous
#include <cuda_runtime.h>
#include <math.h>

#define NN 64
#define MATSZ 4096
#define NB 4096

enum { F_NONE = -1, F_SQRT = 0, F_INVSQRT = 1, F_LOG = 2, F_EXP = 3 };

// device-global scratch (no runtime allocation allowed)
__device__ float  g_bufA[(size_t)NB * MATSZ];
__device__ float  g_bufB[(size_t)NB * MATSZ];
__device__ float  g_bufC[(size_t)NB * MATSZ];
__device__ float  g_bufD[(size_t)NB * MATSZ];
__device__ float  g_small[20 * MATSZ];
__device__ double g_part[256];
__device__ float  g_scal[4];

__device__ __forceinline__ float apply_fn(int f, float w) {
    switch (f) {
        case F_SQRT:    return sqrtf(fmaxf(w, 0.0f));
        case F_INVSQRT: return rsqrtf(fmaxf(w, 1e-30f));
        case F_LOG:     return logf(fmaxf(w, 1e-30f));
        case F_EXP:     return expf(w);
    }
    return w;
}

__device__ __forceinline__ float f4c(const float4& v, int k) {
    return k == 0 ? v.x : k == 1 ? v.y : k == 2 ? v.z : v.w;
}

// ---------------------------------------------------------------------------
// Vectorized 4x4-tile inner product, both matrices row-major stride 64,
// no transposes: acc += A[ti..ti+3][:] * B[:][tj..tj+3]. float4 loads on both
// operands (A over k, B over tj). Math order over k identical to scalar.
// ---------------------------------------------------------------------------
__device__ __forceinline__ void tile_mm_nn(const float* __restrict__ A,
                                           const float* __restrict__ B,
                                           float acc[4][4], int ti, int tj)
{
    #pragma unroll 4
    for (int k4 = 0; k4 < 64; k4 += 4) {
        float4 av[4];
        #pragma unroll
        for (int r = 0; r < 4; ++r)
            av[r] = *reinterpret_cast<const float4*>(A + (ti + r) * 64 + k4);
        #pragma unroll
        for (int kk = 0; kk < 4; ++kk) {
            float4 b = *reinterpret_cast<const float4*>(B + (k4 + kk) * 64 + tj);
            #pragma unroll
            for (int r = 0; r < 4; ++r) {
                float a = f4c(av[r], kk);
                acc[r][0] += a * b.x; acc[r][1] += a * b.y;
                acc[r][2] += a * b.z; acc[r][3] += a * b.w;
            }
        }
    }
}

// scalar transposed-A tile (tiny gemm1 only): acc += A^T[ti..][:]*B[:][tj..]
__device__ __forceinline__ void tile_mm_tn(const float* __restrict__ A,
                                           const float* __restrict__ B,
                                           float acc[4][4], int ti, int tj)
{
    #pragma unroll 4
    for (int k = 0; k < 64; ++k) {
        float a[4];
        #pragma unroll
        for (int r = 0; r < 4; ++r) a[r] = A[k * 64 + ti + r];
        float4 b = *reinterpret_cast<const float4*>(B + k * 64 + tj);
        #pragma unroll
        for (int r = 0; r < 4; ++r) {
            acc[r][0] += a[r] * b.x; acc[r][1] += a[r] * b.y;
            acc[r][2] += a[r] * b.z; acc[r][3] += a[r] * b.w;
        }
    }
}

// ---------------------------------------------------------------------------
// In-shared 64x64 GEMM helper: C = alpha*(A@B) + beta*D + diag*I.
// 256 threads, 4x4 tiles, vectorized loads. C must differ from A and B.
// ---------------------------------------------------------------------------
__device__ __forceinline__ void mm64(const float* __restrict__ A,
                                     const float* __restrict__ B,
                                     float alpha, float beta,
                                     const float* __restrict__ D,
                                     float diag, float* __restrict__ C, int tid)
{
    const int ti = (tid >> 4) << 2, tj = (tid & 15) << 2;
    float acc[4][4] = {};
    tile_mm_nn(A, B, acc, ti, tj);
    __syncthreads();   // all reads of A, B complete
    #pragma unroll
    for (int r = 0; r < 4; ++r) {
        float4 v;
        v.x = alpha * acc[r][0]; v.y = alpha * acc[r][1];
        v.z = alpha * acc[r][2]; v.w = alpha * acc[r][3];
        if (beta != 0.0f) {
            float4 d = *reinterpret_cast<const float4*>(D + (ti + r) * 64 + tj);
            v.x += beta * d.x; v.y += beta * d.y; v.z += beta * d.z; v.w += beta * d.w;
        }
        if (diag != 0.0f) {
            int row = ti + r;
            if (row >= tj && row < tj + 4) (&v.x)[row - tj] += diag;
        }
        *reinterpret_cast<float4*>(C + (ti + r) * 64 + tj) = v;
    }
    __syncthreads();
}

// ---------------------------------------------------------------------------
// Batched matrix sqrt via coupled Newton-Schulz (Higham). One CTA/matrix.
// ---------------------------------------------------------------------------
__global__ __launch_bounds__(256) void nssqrt_kernel(
    const float* __restrict__ in, float* __restrict__ out)
{
    extern __shared__ float sh[];          // 4 * 4096 floats
    float *Y = sh, *Z = sh + 4096, *W = sh + 8192, *T = sh + 12288;
    __shared__ float red[256];
    __shared__ float s_s;

    const int tid = threadIdx.x;
    const size_t boff = (size_t)blockIdx.x * MATSZ;

    float fa = 0.0f;
    for (int idx = tid; idx < MATSZ; idx += 256) {
        float v = in[boff + idx];
        Y[idx] = v;
        fa += v * v;
        Z[idx] = ((idx >> 6) == (idx & 63)) ? 1.0f : 0.0f;
    }
    red[tid] = fa;
    __syncthreads();
    #pragma unroll
    for (int s = 128; s > 0; s >>= 1) {
        if (tid < s) red[tid] += red[tid + s];
        __syncthreads();
    }
    if (tid == 0) s_s = fmaxf(sqrtf(red[0]) / 1.8f, 1e-20f);
    __syncthreads();
    float inv_s = 1.0f / s_s;
    for (int idx = tid; idx < MATSZ; idx += 256) Y[idx] *= inv_s;
    __syncthreads();

    for (int it = 0; it < 10; ++it) {
        mm64(Z, Y, 1.0f, 0.0f, nullptr, 0.0f, W, tid);      // W = Z@Y
        mm64(Y, W, -0.5f, 1.5f, Y, 0.0f, T, tid);           // T = 1.5Y - 0.5 Y@W
        if (it < 9) {
            mm64(W, Z, -0.5f, 1.5f, Z, 0.0f, Y, tid);       // Znew -> old Y buffer
            float* nY = T; float* nZ = Y; float* nT = Z;
            Y = nY; Z = nZ; T = nT;
        } else {
            Y = T;
        }
    }
    float rs = sqrtf(s_s);
    for (int idx = tid; idx < MATSZ; idx += 256)
        out[boff + idx] = Y[idx] * rs;
}

// ---------------------------------------------------------------------------
// Tiny (1-2 matrix) coupled Newton-Schulz giving BOTH A^{1/2} and A^{-1/2}.
// blockIdx 0 -> (inA, sqA, isqA); blockIdx 1 -> (inB, sqB, isqB).
// 12 iterations, Z updated every iteration. Null output pointers skipped.
// ---------------------------------------------------------------------------
__global__ __launch_bounds__(256) void nssmall_kernel(
    const float* __restrict__ inA, float* sqA, float* isqA,
    const float* __restrict__ inB, float* sqB, float* isqB)
{
    extern __shared__ float sh[];          // 4 * 4096 floats
    float *Y = sh, *Z = sh + 4096, *W = sh + 8192, *T = sh + 12288;
    __shared__ float red[256];
    __shared__ float s_s;

    const int tid = threadIdx.x;
    const float* in = blockIdx.x ? inB : inA;
    float* osq  = blockIdx.x ? sqB  : sqA;
    float* oisq = blockIdx.x ? isqB : isqA;

    float fa = 0.0f;
    for (int idx = tid; idx < MATSZ; idx += 256) {
        float v = in[idx];
        Y[idx] = v;
        fa += v * v;
        Z[idx] = ((idx >> 6) == (idx & 63)) ? 1.0f : 0.0f;
    }
    red[tid] = fa;
    __syncthreads();
    #pragma unroll
    for (int s = 128; s > 0; s >>= 1) {
        if (tid < s) red[tid] += red[tid + s];
        __syncthreads();
    }
    if (tid == 0) s_s = fmaxf(sqrtf(red[0]) / 1.8f, 1e-20f);
    __syncthreads();
    float inv_s = 1.0f / s_s;
    for (int idx = tid; idx < MATSZ; idx += 256) Y[idx] *= inv_s;
    __syncthreads();

    for (int it = 0; it < 12; ++it) {
        mm64(Z, Y, 1.0f, 0.0f, nullptr, 0.0f, W, tid);      // W = Z@Y
        mm64(Y, W, -0.5f, 1.5f, Y, 0.0f, T, tid);           // newY -> T
        mm64(W, Z, -0.5f, 1.5f, Z, 0.0f, Y, tid);           // newZ -> old Y
        float* oY = Y; float* oZ = Z;
        Y = T; Z = oY; T = oZ;
    }
    float rs  = sqrtf(s_s);
    float irs = rsqrtf(s_s);
    if (osq)
        for (int idx = tid; idx < MATSZ; idx += 256) osq[idx] = Y[idx] * rs;
    if (oisq)
        for (int idx = tid; idx < MATSZ; idx += 256) oisq[idx] = Z[idx] * irs;
}

// ---------------------------------------------------------------------------
// Matrix exp via scaling-and-squaring + degree-7 Taylor (Horner). 1 CTA/matrix.
// ---------------------------------------------------------------------------
__global__ __launch_bounds__(256) void expm_kernel(
    const float* __restrict__ in, float* __restrict__ out)
{
    extern __shared__ float sh[];          // 3 * 4096 floats
    float *B = sh, *P = sh + 4096, *Q = sh + 8192;
    __shared__ float red[256];
    __shared__ float sc_s;
    __shared__ int   j_s;

    const int tid = threadIdx.x;
    const size_t boff = (size_t)blockIdx.x * MATSZ;

    float fa = 0.0f;
    for (int idx = tid; idx < MATSZ; idx += 256) {
        float v = in[boff + idx];
        B[idx] = v;
        fa += v * v;
    }
    red[tid] = fa;
    __syncthreads();
    #pragma unroll
    for (int s = 128; s > 0; s >>= 1) {
        if (tid < s) red[tid] += red[tid + s];
        __syncthreads();
    }
    if (tid == 0) {
        float F = sqrtf(red[0]);
        int j = 0;
        while (F > 0.25f && j < 40) { F *= 0.5f; ++j; }
        j_s = j;
        sc_s = exp2f((float)(-j));
    }
    __syncthreads();
    const int j = j_s;
    float sc = sc_s;
    for (int idx = tid; idx < MATSZ; idx += 256) B[idx] *= sc;
    __syncthreads();

    const float c7 = 1.0f / 5040.0f, c6 = 1.0f / 720.0f;
    for (int idx = tid; idx < MATSZ; idx += 256) {
        float v = c7 * B[idx];
        if ((idx >> 6) == (idx & 63)) v += c6;
        P[idx] = v;
    }
    __syncthreads();
    const float cs[6] = { 1.0f / 120.0f, 1.0f / 24.0f, 1.0f / 6.0f, 0.5f, 1.0f, 1.0f };
    float *cur = P, *oth = Q;
    #pragma unroll
    for (int k = 0; k < 6; ++k) {
        mm64(cur, B, 1.0f, 0.0f, nullptr, cs[k], oth, tid);
        float* t = cur; cur = oth; oth = t;
    }
    for (int t = 0; t < j; ++t) {
        mm64(cur, cur, 1.0f, 0.0f, nullptr, 0.0f, oth, tid);
        float* tt = cur; cur = oth; oth = tt;
    }
    for (int idx = tid; idx < MATSZ; idx += 256)
        out[boff + idx] = cur[idx];
}

// ---------------------------------------------------------------------------
// One-sided (Hestenes) Jacobi, symmetric 64x64 — half-warp float4 version
// (round-9 winner, unchanged).
// ---------------------------------------------------------------------------
__global__ __launch_bounds__(512) void jac1s512(
    const float* __restrict__ in, float* __restrict__ out1,
    float* __restrict__ out2, int f1, int f2, int useShift, int nsweeps)
{
    __shared__ float  As[64 * 68];
    __shared__ float  norms[64];
    __shared__ float  gv[64], gv2[64];
    __shared__ float  red[512];
    __shared__ float  shift_s;
    __shared__ uchar2 ptab[63 * 32];

    const int tid  = threadIdx.x;
    const int lane = tid & 31;
    const int wid  = tid >> 5;
    const int sl   = lane & 15;
    const int k    = (wid << 1) | (lane >> 4);
    const size_t boff = (size_t)blockIdx.x * MATSZ;

    for (int i = tid; i < 63 * 32; i += 512) {
        int r = i >> 5, kk = i & 31;
        int p, q;
        if (kk == 0) { p = 63; q = r; }
        else {
            int a1 = r + kk;      p = (a1 < 63) ? a1 : a1 - 63;
            int a2 = r + 63 - kk; q = (a2 < 63) ? a2 : a2 - 63;
        }
        ptab[i] = make_uchar2((unsigned char)p, (unsigned char)q);
    }

    float fa = 0.0f;
    for (int idx = tid; idx < MATSZ; idx += 512) {
        int c = idx >> 6, r = idx & 63;
        float v = in[boff + idx];
        As[c * 68 + r] = v;
        fa += v * v;
    }
    red[tid] = fa;
    __syncthreads();
    if (useShift) {
        #pragma unroll
        for (int s = 256; s > 0; s >>= 1) {
            if (tid < s) red[tid] += red[tid + s];
            __syncthreads();
        }
        if (tid == 0) shift_s = sqrtf(red[0]) * 1.000001f + 1e-20f;
        __syncthreads();
        if (tid < 64) As[tid * 68 + tid] += shift_s;
    } else {
        if (tid == 0) shift_s = 0.0f;
    }
    __syncthreads();

    for (int j = k; j < 64; j += 32) {
        float4 a = *reinterpret_cast<const float4*>(As + j * 68 + sl * 4);
        float s = a.x * a.x + a.y * a.y + a.z * a.z + a.w * a.w;
        #pragma unroll
        for (int o = 8; o; o >>= 1) s += __shfl_xor_sync(0xFFFFFFFFu, s, o);
        if (sl == 0) norms[j] = s;
    }
    __syncthreads();

    for (int sw = 0; sw < nsweeps; ++sw) {
        for (int r = 0; r < 63; ++r) {
            uchar2 pq = ptab[(r << 5) | k];
            const int p = pq.x, q = pq.y;
            float4* cp = reinterpret_cast<float4*>(As + p * 68);
            float4* cq = reinterpret_cast<float4*>(As + q * 68);
            float4 ap = cp[sl];
            float4 aq = cq[sl];
            float g = ap.x * aq.x + ap.y * aq.y + ap.z * aq.z + ap.w * aq.w;
            #pragma unroll
            for (int o = 8; o; o >>= 1) g += __shfl_xor_sync(0xFFFFFFFFu, g, o);
            if (g != 0.0f) {
                float al = norms[p], be = norms[q];
                float tau = (be - al) / (2.0f * g);
                float t = 1.0f / (fabsf(tau) + sqrtf(1.0f + tau * tau));
                if (tau < 0.0f) t = -t;
                float c = rsqrtf(1.0f + t * t);
                float s = t * c;
                float4 np, nq;
                np.x = c * ap.x - s * aq.x;  nq.x = s * ap.x + c * aq.x;
                np.y = c * ap.y - s * aq.y;  nq.y = s * ap.y + c * aq.y;
                np.z = c * ap.z - s * aq.z;  nq.z = s * ap.z + c * aq.z;
                np.w = c * ap.w - s * aq.w;  nq.w = s * ap.w + c * aq.w;
                cp[sl] = np;
                cq[sl] = nq;
                if (sl == 0) {
                    float cc = c * c, ss = s * s, cs2 = 2.0f * c * s;
                    norms[p] = cc * al - cs2 * g + ss * be;
                    norms[q] = ss * al + cs2 * g + cc * be;
                }
            }
            __syncthreads();
        }
    }

    for (int j = k; j < 64; j += 32) {
        float4 a = *reinterpret_cast<const float4*>(As + j * 68 + sl * 4);
        float s = a.x * a.x + a.y * a.y + a.z * a.z + a.w * a.w;
        #pragma unroll
        for (int o = 8; o; o >>= 1) s += __shfl_xor_sync(0xFFFFFFFFu, s, o);
        if (sl == 0) {
            s = fmaxf(s, 1e-30f);
            float lam = sqrtf(s) - shift_s;
            gv[j] = apply_fn(f1, lam) / s;
            if (f2 != F_NONE) gv2[j] = apply_fn(f2, lam) / s;
        }
    }
    __syncthreads();

    const int ti = (tid >> 4) * 2;
    const int tj = (tid & 15) << 2;
    {
        float acc[2][4] = {};
        #pragma unroll 4
        for (int kk = 0; kk < 64; ++kk) {
            const float* ck = As + kk * 68;
            float gk = gv[kk];
            float a0 = gk * ck[ti], a1 = gk * ck[ti + 1];
            float b0 = ck[tj], b1 = ck[tj + 1], b2 = ck[tj + 2], b3 = ck[tj + 3];
            acc[0][0] += a0 * b0; acc[0][1] += a0 * b1; acc[0][2] += a0 * b2; acc[0][3] += a0 * b3;
            acc[1][0] += a1 * b0; acc[1][1] += a1 * b1; acc[1][2] += a1 * b2; acc[1][3] += a1 * b3;
        }
        #pragma unroll
        for (int r = 0; r < 2; ++r) {
            float4 v = make_float4(acc[r][0], acc[r][1], acc[r][2], acc[r][3]);
            *reinterpret_cast<float4*>(out1 + boff + (size_t)(ti + r) * 64 + tj) = v;
        }
    }
    if (f2 != F_NONE) {
        float acc[2][4] = {};
        #pragma unroll 4
        for (int kk = 0; kk < 64; ++kk) {
            const float* ck = As + kk * 68;
            float gk = gv2[kk];
            float a0 = gk * ck[ti], a1 = gk * ck[ti + 1];
            float b0 = ck[tj], b1 = ck[tj + 1], b2 = ck[tj + 2], b3 = ck[tj + 3];
            acc[0][0] += a0 * b0; acc[0][1] += a0 * b1; acc[0][2] += a0 * b2; acc[0][3] += a0 * b3;
            acc[1][0] += a1 * b0; acc[1][1] += a1 * b1; acc[1][2] += a1 * b2; acc[1][3] += a1 * b3;
        }
        #pragma unroll
        for (int r = 0; r < 2; ++r) {
            float4 v = make_float4(acc[r][0], acc[r][1], acc[r][2], acc[r][3]);
            *reinterpret_cast<float4*>(out2 + boff + (size_t)(ti + r) * 64 + tj) = v;
        }
    }
}

// out_b = scale * L @ X_b @ R  (L, R broadcast, both plain row-major)
__global__ __launch_bounds__(256) void cong_kernel(
    const float* __restrict__ Lm, const float* __restrict__ Xb,
    const float* __restrict__ Rm, float* __restrict__ out, int useScale)
{
    __shared__ float Ls[MATSZ], Rs[MATSZ], Xs[MATSZ];
    const int tid = threadIdx.x;
    const size_t boff = (size_t)blockIdx.x * MATSZ;
    for (int i = tid; i < MATSZ; i += 256) {
        Ls[i] = Lm[i]; Rs[i] = Rm[i]; Xs[i] = Xb[boff + i];
    }
    __syncthreads();

    const int ti = (tid >> 4) << 2, tj = (tid & 15) << 2;
    float acc[4][4] = {};
    tile_mm_nn(Ls, Xs, acc, ti, tj);          // T = L @ X
    __syncthreads();
    #pragma unroll
    for (int r = 0; r < 4; ++r)
        #pragma unroll
        for (int c = 0; c < 4; ++c) Xs[(ti + r) * 64 + tj + c] = acc[r][c];
    __syncthreads();

    float sc = useScale ? g_scal[0] : 1.0f;
    float acc2[4][4] = {};
    tile_mm_nn(Xs, Rs, acc2, ti, tj);         // out = T @ R
    #pragma unroll
    for (int r = 0; r < 4; ++r) {
        float4 v = make_float4(acc2[r][0] * sc, acc2[r][1] * sc,
                               acc2[r][2] * sc, acc2[r][3] * sc);
        *reinterpret_cast<float4*>(out + boff + (size_t)(ti + r) * 64 + tj) = v;
    }
}

// out_b = A_b @ B_(b*strideB)   (strideB = 0 broadcasts B)
__global__ __launch_bounds__(256) void gemmB_kernel(
    const float* __restrict__ A, const float* __restrict__ Bm, int strideB,
    float* __restrict__ out)
{
    __shared__ float As_[MATSZ], Bs_[MATSZ];
    const int tid = threadIdx.x;
    const size_t boff = (size_t)blockIdx.x * MATSZ;
    const float* Bb = Bm + (size_t)blockIdx.x * strideB;
    for (int i = tid; i < MATSZ; i += 256) { As_[i] = A[boff + i]; Bs_[i] = Bb[i]; }
    __syncthreads();
    const int ti = (tid >> 4) << 2, tj = (tid & 15) << 2;
    float acc[4][4] = {};
    tile_mm_nn(As_, Bs_, acc, ti, tj);
    #pragma unroll
    for (int r = 0; r < 4; ++r) {
        float4 v = make_float4(acc[r][0], acc[r][1], acc[r][2], acc[r][3]);
        *reinterpret_cast<float4*>(out + boff + (size_t)(ti + r) * 64 + tj) = v;
    }
}

// single 64x64 gemm: C = op(A) @ B
__global__ __launch_bounds__(256) void gemm1_kernel(
    const float* __restrict__ A, const float* __restrict__ B,
    float* __restrict__ C, int transA)
{
    __shared__ float As_[MATSZ], Bs_[MATSZ];
    const int tid = threadIdx.x;
    for (int i = tid; i < MATSZ; i += 256) { As_[i] = A[i]; Bs_[i] = B[i]; }
    __syncthreads();
    const int ti = (tid >> 4) << 2, tj = (tid & 15) << 2;
    float acc[4][4] = {};
    if (transA) tile_mm_tn(As_, Bs_, acc, ti, tj);
    else        tile_mm_nn(As_, Bs_, acc, ti, tj);
    #pragma unroll
    for (int r = 0; r < 4; ++r) {
        float4 v = make_float4(acc[r][0], acc[r][1], acc[r][2], acc[r][3]);
        *reinterpret_cast<float4*>(C + (size_t)(ti + r) * 64 + tj) = v;
    }
}

// out[e] = mean_b in[b*4096 + e]
__global__ void mean_kernel(const float* __restrict__ in, float* __restrict__ out)
{
    int e = blockIdx.x * blockDim.x + threadIdx.x;
    double a0 = 0, a1 = 0, a2 = 0, a3 = 0;
    for (int b = 0; b < NB; b += 4) {
        a0 += (double)in[(size_t)(b + 0) * MATSZ + e];
        a1 += (double)in[(size_t)(b + 1) * MATSZ + e];
        a2 += (double)in[(size_t)(b + 2) * MATSZ + e];
        a3 += (double)in[(size_t)(b + 3) * MATSZ + e];
    }
    out[e] = (float)((a0 + a1 + a2 + a3) * (1.0 / (double)NB));
}

// deterministic two-pass sum of squares
__global__ __launch_bounds__(256) void sumsq_kernel(const float* __restrict__ in)
{
    __shared__ double sh[256];
    const int tid = threadIdx.x;
    const size_t base = (size_t)blockIdx.x * 65536;
    double a = 0;
    for (int i = tid; i < 65536; i += 256) {
        float v = in[base + i];
        a += (double)v * (double)v;
    }
    sh[tid] = a;
    __syncthreads();
    for (int s = 128; s > 0; s >>= 1) {
        if (tid < s) sh[tid] += sh[tid + s];
        __syncthreads();
    }
    if (tid == 0) g_part[blockIdx.x] = sh[0];
}

__global__ void finalize_kernel(const float* __restrict__ shift)
{
    __shared__ double sh[256];
    const int tid = threadIdx.x;
    sh[tid] = g_part[tid];
    __syncthreads();
    for (int s = 128; s > 0; s >>= 1) {
        if (tid < s) sh[tid] += sh[tid + s];
        __syncthreads();
    }
    if (tid == 0) {
        double var = sh[0] / (double)NB;
        g_scal[0] = shift[0] / (float)sqrt(var + 1e-5);
    }
}

extern "C" void kernel_launch(void* const* d_in, const int* in_sizes, int n_in,
                              void* d_out, int out_size)
{
    const float* X     = (const float*)d_in[0];
    const float* W     = (const float*)d_in[1];
    const float* M     = (const float*)d_in[2];
    const float* shift = (const float*)d_in[3];
    float* out = (float*)d_out;

    float *bufA, *bufB, *bufC, *bufD, *sm;
    cudaGetSymbolAddress((void**)&bufA, g_bufA);
    cudaGetSymbolAddress((void**)&bufB, g_bufB);
    cudaGetSymbolAddress((void**)&bufC, g_bufC);
    cudaGetSymbolAddress((void**)&bufD, g_bufD);
    cudaGetSymbolAddress((void**)&sm,   g_small);

    cudaFuncSetAttribute(nssqrt_kernel,  cudaFuncAttributeMaxDynamicSharedMemorySize, 65536);
    cudaFuncSetAttribute(nssmall_kernel, cudaFuncAttributeMaxDynamicSharedMemorySize, 65536);
    cudaFuncSetAttribute(expm_kernel,    cudaFuncAttributeMaxDynamicSharedMemorySize, 49152);

    #define SLOT(i) (sm + (i) * MATSZ)
    // slots: 0 Mh, 1 Mnh, 2 Wh, 3 tmp, 4 Wc, 5 Wch, 6 Wcnh, 7 P, 8 Q, 9 R,
    //        10 G0, 11 G0h, 12 G0nh, 13 Tm, 14 expTm, 15 G, 16 mnh, 17 Pt, 18 Qt

    // parameter prep: tiny Newton-Schulz (sqrt + invsqrt) replaces tiny Jacobi
    nssmall_kernel<<<2, 256, 65536>>>(M, SLOT(0), SLOT(1),   // Mh, Mnh
                                      W, SLOT(2), nullptr);  // Wh
    gemm1_kernel<<<1, 256>>>(SLOT(1), SLOT(2), SLOT(3), 0);  // Mnh Wh
    gemm1_kernel<<<1, 256>>>(SLOT(3), SLOT(1), SLOT(4), 0);  // Wc
    nssmall_kernel<<<1, 256, 65536>>>(SLOT(4), SLOT(5), SLOT(6),  // Wch, Wcnh
                                      SLOT(4), nullptr, nullptr);
    gemm1_kernel<<<1, 256>>>(SLOT(6), SLOT(2), SLOT(7), 0);  // P  = Wcnh Wh
    gemm1_kernel<<<1, 256>>>(SLOT(2), SLOT(6), SLOT(17), 0); // Pt = Wh Wcnh = P^T
    gemm1_kernel<<<1, 256>>>(SLOT(0), SLOT(5), SLOT(8), 0);  // Q  = Mh Wch
    gemm1_kernel<<<1, 256>>>(SLOT(5), SLOT(0), SLOT(18), 0); // Qt = Wch Mh = Q^T
    gemm1_kernel<<<1, 256>>>(SLOT(8), SLOT(8), SLOT(9), 1);  // R = Q^T Q

    // Xp = X^{1/2} (Newton-Schulz); Xc = Mnh Xp Mnh
    nssqrt_kernel<<<NB, 256, 65536>>>(X, bufA);
    cong_kernel<<<NB, 256>>>(SLOT(1), bufA, SLOT(1), bufB, 0);     // Xc

    // bary_geom: 1 Karcher step from arithmetic mean
    mean_kernel<<<16, 256>>>(bufB, SLOT(10));                      // G0
    nssmall_kernel<<<1, 256, 65536>>>(SLOT(10), SLOT(11), SLOT(12),
                                      SLOT(10), nullptr, nullptr); // G0h, G0nh
    cong_kernel<<<NB, 256>>>(SLOT(12), bufB, SLOT(12), bufC, 0);
    jac1s512<<<NB, 512>>>(bufC, bufA, bufA, F_LOG, F_NONE, 0, 6);
    mean_kernel<<<16, 256>>>(bufA, SLOT(13));                      // Tm
    expm_kernel<<<1, 256, 49152>>>(SLOT(13), SLOT(14));            // expTm
    gemm1_kernel<<<1, 256>>>(SLOT(11), SLOT(14), SLOT(3), 0);
    gemm1_kernel<<<1, 256>>>(SLOT(3), SLOT(11), SLOT(15), 0);      // G
    nssmall_kernel<<<1, 256, 65536>>>(SLOT(15), nullptr, SLOT(16),
                                      SLOT(15), nullptr, nullptr); // mnh

    // tangent at I, variance, scale
    cong_kernel<<<NB, 256>>>(SLOT(16), bufB, SLOT(16), bufC, 0);
    jac1s512<<<NB, 512>>>(bufC, bufD, bufD, F_LOG, F_NONE, 0, 6);  // T0
    sumsq_kernel<<<256, 256>>>(bufD);
    finalize_kernel<<<1, 256>>>(shift);

    // arg = factor * P T0 P^T ; E = exp(arg)
    cong_kernel<<<NB, 256>>>(SLOT(7), bufD, SLOT(17), bufC, 1);    // P T0 Pt
    expm_kernel<<<NB, 256, 49152>>>(bufC, bufA);                   // E

    // out = Q (E R E) Q^T
    gemmB_kernel<<<NB, 256>>>(bufA, SLOT(9), 0, bufC);             // E R
    gemmB_kernel<<<NB, 256>>>(bufC, bufA, MATSZ, bufD);            // (E R) E
    cong_kernel<<<NB, 256>>>(SLOT(8), bufD, SLOT(18), out, 0);     // Q .. Qt
    #undef SLOT
}

// round 11
// speedup vs baseline: 1.8704x; 1.0280x over previous
#include <cuda_runtime.h>
#include <math.h>

#define NN 64
#define MATSZ 4096
#define NB 4096

enum { F_NONE = -1, F_SQRT = 0, F_INVSQRT = 1, F_LOG = 2, F_EXP = 3 };

// device-global scratch (no runtime allocation allowed)
__device__ float  g_bufA[(size_t)NB * MATSZ];
__device__ float  g_bufB[(size_t)NB * MATSZ];
__device__ float  g_bufC[(size_t)NB * MATSZ];
__device__ float  g_bufD[(size_t)NB * MATSZ];
__device__ float  g_small[20 * MATSZ];
__device__ double g_part[256];
__device__ float  g_scal[4];

// Blackwell packed fp32x2 (FFMA2) — PTX-only, ptxas never auto-fuses.
#define PACKF2(d, lo, hi) asm("mov.b64 %0, {%1, %2};" : "=l"(d) : "f"(lo), "f"(hi))
#define UNPACKF2(lo, hi, d) asm("mov.b64 {%0, %1}, %2;" : "=f"(lo), "=f"(hi) : "l"(d))
#define FMAF2(acc, a, b) asm("fma.rn.f32x2 %0, %1, %2, %0;" : "+l"(acc) : "l"(a), "l"(b))

__device__ __forceinline__ float apply_fn(int f, float w) {
    switch (f) {
        case F_SQRT:    return sqrtf(fmaxf(w, 0.0f));
        case F_INVSQRT: return rsqrtf(fmaxf(w, 1e-30f));
        case F_LOG:     return logf(fmaxf(w, 1e-30f));
        case F_EXP:     return expf(w);
    }
    return w;
}

__device__ __forceinline__ float f4c(const float4& v, int k) {
    return k == 0 ? v.x : k == 1 ? v.y : k == 2 ? v.z : v.w;
}

// ---------------------------------------------------------------------------
// Vectorized 4x4-tile inner product with packed f32x2 accumulation.
// Both matrices row-major stride 64, no transposes. Per-element fp32 math
// identical to the scalar version (FFMA2 = 2 independent IEEE FMAs).
// ---------------------------------------------------------------------------
__device__ __forceinline__ void tile_mm_nn(const float* __restrict__ A,
                                           const float* __restrict__ B,
                                           float acc[4][4], int ti, int tj)
{
    unsigned long long p01[4], p23[4];
    #pragma unroll
    for (int r = 0; r < 4; ++r) {
        PACKF2(p01[r], acc[r][0], acc[r][1]);
        PACKF2(p23[r], acc[r][2], acc[r][3]);
    }
    #pragma unroll 4
    for (int k4 = 0; k4 < 64; k4 += 4) {
        float4 av[4];
        #pragma unroll
        for (int r = 0; r < 4; ++r)
            av[r] = *reinterpret_cast<const float4*>(A + (ti + r) * 64 + k4);
        #pragma unroll
        for (int kk = 0; kk < 4; ++kk) {
            float4 b = *reinterpret_cast<const float4*>(B + (k4 + kk) * 64 + tj);
            unsigned long long b01, b23;
            PACKF2(b01, b.x, b.y);
            PACKF2(b23, b.z, b.w);
            #pragma unroll
            for (int r = 0; r < 4; ++r) {
                float a = f4c(av[r], kk);
                unsigned long long aa;
                PACKF2(aa, a, a);
                FMAF2(p01[r], aa, b01);
                FMAF2(p23[r], aa, b23);
            }
        }
    }
    #pragma unroll
    for (int r = 0; r < 4; ++r) {
        UNPACKF2(acc[r][0], acc[r][1], p01[r]);
        UNPACKF2(acc[r][2], acc[r][3], p23[r]);
    }
}

// scalar transposed-A tile (tiny gemm1 only): acc += A^T[ti..][:]*B[:][tj..]
__device__ __forceinline__ void tile_mm_tn(const float* __restrict__ A,
                                           const float* __restrict__ B,
                                           float acc[4][4], int ti, int tj)
{
    #pragma unroll 4
    for (int k = 0; k < 64; ++k) {
        float a[4];
        #pragma unroll
        for (int r = 0; r < 4; ++r) a[r] = A[k * 64 + ti + r];
        float4 b = *reinterpret_cast<const float4*>(B + k * 64 + tj);
        #pragma unroll
        for (int r = 0; r < 4; ++r) {
            acc[r][0] += a[r] * b.x; acc[r][1] += a[r] * b.y;
            acc[r][2] += a[r] * b.z; acc[r][3] += a[r] * b.w;
        }
    }
}

// ---------------------------------------------------------------------------
// In-shared 64x64 GEMM helper: C = alpha*(A@B) + beta*D + diag*I.
// 256 threads, 4x4 tiles, packed-FFMA2 inner product.
// ---------------------------------------------------------------------------
__device__ __forceinline__ void mm64(const float* __restrict__ A,
                                     const float* __restrict__ B,
                                     float alpha, float beta,
                                     const float* __restrict__ D,
                                     float diag, float* __restrict__ C, int tid)
{
    const int ti = (tid >> 4) << 2, tj = (tid & 15) << 2;
    float acc[4][4] = {};
    tile_mm_nn(A, B, acc, ti, tj);
    __syncthreads();   // all reads of A, B complete
    #pragma unroll
    for (int r = 0; r < 4; ++r) {
        float4 v;
        v.x = alpha * acc[r][0]; v.y = alpha * acc[r][1];
        v.z = alpha * acc[r][2]; v.w = alpha * acc[r][3];
        if (beta != 0.0f) {
            float4 d = *reinterpret_cast<const float4*>(D + (ti + r) * 64 + tj);
            v.x += beta * d.x; v.y += beta * d.y; v.z += beta * d.z; v.w += beta * d.w;
        }
        if (diag != 0.0f) {
            int row = ti + r;
            if (row >= tj && row < tj + 4) (&v.x)[row - tj] += diag;
        }
        *reinterpret_cast<float4*>(C + (ti + r) * 64 + tj) = v;
    }
    __syncthreads();
}

// ---------------------------------------------------------------------------
// Batched matrix sqrt via coupled Newton-Schulz (Higham). One CTA/matrix.
// 9 iterations: worst-case scaled eigenvalue 0.025 -> residual ~2e-6.
// ---------------------------------------------------------------------------
__global__ __launch_bounds__(256) void nssqrt_kernel(
    const float* __restrict__ in, float* __restrict__ out)
{
    extern __shared__ float sh[];          // 4 * 4096 floats
    float *Y = sh, *Z = sh + 4096, *W = sh + 8192, *T = sh + 12288;
    __shared__ float red[256];
    __shared__ float s_s;

    const int tid = threadIdx.x;
    const size_t boff = (size_t)blockIdx.x * MATSZ;

    float fa = 0.0f;
    for (int idx = tid; idx < MATSZ; idx += 256) {
        float v = in[boff + idx];
        Y[idx] = v;
        fa += v * v;
        Z[idx] = ((idx >> 6) == (idx & 63)) ? 1.0f : 0.0f;
    }
    red[tid] = fa;
    __syncthreads();
    #pragma unroll
    for (int s = 128; s > 0; s >>= 1) {
        if (tid < s) red[tid] += red[tid + s];
        __syncthreads();
    }
    if (tid == 0) s_s = fmaxf(sqrtf(red[0]) / 1.8f, 1e-20f);
    __syncthreads();
    float inv_s = 1.0f / s_s;
    for (int idx = tid; idx < MATSZ; idx += 256) Y[idx] *= inv_s;
    __syncthreads();

    for (int it = 0; it < 9; ++it) {
        mm64(Z, Y, 1.0f, 0.0f, nullptr, 0.0f, W, tid);      // W = Z@Y
        mm64(Y, W, -0.5f, 1.5f, Y, 0.0f, T, tid);           // T = 1.5Y - 0.5 Y@W
        if (it < 8) {
            mm64(W, Z, -0.5f, 1.5f, Z, 0.0f, Y, tid);       // Znew -> old Y buffer
            float* nY = T; float* nZ = Y; float* nT = Z;
            Y = nY; Z = nZ; T = nT;
        } else {
            Y = T;
        }
    }
    float rs = sqrtf(s_s);
    for (int idx = tid; idx < MATSZ; idx += 256)
        out[boff + idx] = Y[idx] * rs;
}

// ---------------------------------------------------------------------------
// Tiny (1-2 matrix) coupled Newton-Schulz giving BOTH A^{1/2} and A^{-1/2}.
// ---------------------------------------------------------------------------
__global__ __launch_bounds__(256) void nssmall_kernel(
    const float* __restrict__ inA, float* sqA, float* isqA,
    const float* __restrict__ inB, float* sqB, float* isqB)
{
    extern __shared__ float sh[];          // 4 * 4096 floats
    float *Y = sh, *Z = sh + 4096, *W = sh + 8192, *T = sh + 12288;
    __shared__ float red[256];
    __shared__ float s_s;

    const int tid = threadIdx.x;
    const float* in = blockIdx.x ? inB : inA;
    float* osq  = blockIdx.x ? sqB  : sqA;
    float* oisq = blockIdx.x ? isqB : isqA;

    float fa = 0.0f;
    for (int idx = tid; idx < MATSZ; idx += 256) {
        float v = in[idx];
        Y[idx] = v;
        fa += v * v;
        Z[idx] = ((idx >> 6) == (idx & 63)) ? 1.0f : 0.0f;
    }
    red[tid] = fa;
    __syncthreads();
    #pragma unroll
    for (int s = 128; s > 0; s >>= 1) {
        if (tid < s) red[tid] += red[tid + s];
        __syncthreads();
    }
    if (tid == 0) s_s = fmaxf(sqrtf(red[0]) / 1.8f, 1e-20f);
    __syncthreads();
    float inv_s = 1.0f / s_s;
    for (int idx = tid; idx < MATSZ; idx += 256) Y[idx] *= inv_s;
    __syncthreads();

    for (int it = 0; it < 12; ++it) {
        mm64(Z, Y, 1.0f, 0.0f, nullptr, 0.0f, W, tid);      // W = Z@Y
        mm64(Y, W, -0.5f, 1.5f, Y, 0.0f, T, tid);           // newY -> T
        mm64(W, Z, -0.5f, 1.5f, Z, 0.0f, Y, tid);           // newZ -> old Y
        float* oY = Y; float* oZ = Z;
        Y = T; Z = oY; T = oZ;
    }
    float rs  = sqrtf(s_s);
    float irs = rsqrtf(s_s);
    if (osq)
        for (int idx = tid; idx < MATSZ; idx += 256) osq[idx] = Y[idx] * rs;
    if (oisq)
        for (int idx = tid; idx < MATSZ; idx += 256) oisq[idx] = Z[idx] * irs;
}

// ---------------------------------------------------------------------------
// Matrix exp: scaling-and-squaring + degree-5 Taylor (Horner). 1 CTA/matrix.
// ||B|| <= 0.25 -> remainder ~3.5e-7.
// ---------------------------------------------------------------------------
__global__ __launch_bounds__(256) void expm_kernel(
    const float* __restrict__ in, float* __restrict__ out)
{
    extern __shared__ float sh[];          // 3 * 4096 floats
    float *B = sh, *P = sh + 4096, *Q = sh + 8192;
    __shared__ float red[256];
    __shared__ float sc_s;
    __shared__ int   j_s;

    const int tid = threadIdx.x;
    const size_t boff = (size_t)blockIdx.x * MATSZ;

    float fa = 0.0f;
    for (int idx = tid; idx < MATSZ; idx += 256) {
        float v = in[boff + idx];
        B[idx] = v;
        fa += v * v;
    }
    red[tid] = fa;
    __syncthreads();
    #pragma unroll
    for (int s = 128; s > 0; s >>= 1) {
        if (tid < s) red[tid] += red[tid + s];
        __syncthreads();
    }
    if (tid == 0) {
        float F = sqrtf(red[0]);
        int j = 0;
        while (F > 0.25f && j < 40) { F *= 0.5f; ++j; }
        j_s = j;
        sc_s = exp2f((float)(-j));
    }
    __syncthreads();
    const int j = j_s;
    float sc = sc_s;
    for (int idx = tid; idx < MATSZ; idx += 256) B[idx] *= sc;
    __syncthreads();

    // Horner init: P = c5*B + c4*I  (degree-5 Taylor)
    const float c5 = 1.0f / 120.0f, c4 = 1.0f / 24.0f;
    for (int idx = tid; idx < MATSZ; idx += 256) {
        float v = c5 * B[idx];
        if ((idx >> 6) == (idx & 63)) v += c4;
        P[idx] = v;
    }
    __syncthreads();
    const float cs[4] = { 1.0f / 6.0f, 0.5f, 1.0f, 1.0f };
    float *cur = P, *oth = Q;
    #pragma unroll
    for (int k = 0; k < 4; ++k) {
        mm64(cur, B, 1.0f, 0.0f, nullptr, cs[k], oth, tid);
        float* t = cur; cur = oth; oth = t;
    }
    for (int t = 0; t < j; ++t) {
        mm64(cur, cur, 1.0f, 0.0f, nullptr, 0.0f, oth, tid);
        float* tt = cur; cur = oth; oth = tt;
    }
    for (int idx = tid; idx < MATSZ; idx += 256)
        out[boff + idx] = cur[idx];
}

// ---------------------------------------------------------------------------
// One-sided (Hestenes) Jacobi, symmetric 64x64 — half-warp float4 version
// (round-9 winner, unchanged).
// ---------------------------------------------------------------------------
__global__ __launch_bounds__(512) void jac1s512(
    const float* __restrict__ in, float* __restrict__ out1,
    float* __restrict__ out2, int f1, int f2, int useShift, int nsweeps)
{
    __shared__ float  As[64 * 68];
    __shared__ float  norms[64];
    __shared__ float  gv[64], gv2[64];
    __shared__ float  red[512];
    __shared__ float  shift_s;
    __shared__ uchar2 ptab[63 * 32];

    const int tid  = threadIdx.x;
    const int lane = tid & 31;
    const int wid  = tid >> 5;
    const int sl   = lane & 15;
    const int k    = (wid << 1) | (lane >> 4);
    const size_t boff = (size_t)blockIdx.x * MATSZ;

    for (int i = tid; i < 63 * 32; i += 512) {
        int r = i >> 5, kk = i & 31;
        int p, q;
        if (kk == 0) { p = 63; q = r; }
        else {
            int a1 = r + kk;      p = (a1 < 63) ? a1 : a1 - 63;
            int a2 = r + 63 - kk; q = (a2 < 63) ? a2 : a2 - 63;
        }
        ptab[i] = make_uchar2((unsigned char)p, (unsigned char)q);
    }

    float fa = 0.0f;
    for (int idx = tid; idx < MATSZ; idx += 512) {
        int c = idx >> 6, r = idx & 63;
        float v = in[boff + idx];
        As[c * 68 + r] = v;
        fa += v * v;
    }
    red[tid] = fa;
    __syncthreads();
    if (useShift) {
        #pragma unroll
        for (int s = 256; s > 0; s >>= 1) {
            if (tid < s) red[tid] += red[tid + s];
            __syncthreads();
        }
        if (tid == 0) shift_s = sqrtf(red[0]) * 1.000001f + 1e-20f;
        __syncthreads();
        if (tid < 64) As[tid * 68 + tid] += shift_s;
    } else {
        if (tid == 0) shift_s = 0.0f;
    }
    __syncthreads();

    for (int j = k; j < 64; j += 32) {
        float4 a = *reinterpret_cast<const float4*>(As + j * 68 + sl * 4);
        float s = a.x * a.x + a.y * a.y + a.z * a.z + a.w * a.w;
        #pragma unroll
        for (int o = 8; o; o >>= 1) s += __shfl_xor_sync(0xFFFFFFFFu, s, o);
        if (sl == 0) norms[j] = s;
    }
    __syncthreads();

    for (int sw = 0; sw < nsweeps; ++sw) {
        for (int r = 0; r < 63; ++r) {
            uchar2 pq = ptab[(r << 5) | k];
            const int p = pq.x, q = pq.y;
            float4* cp = reinterpret_cast<float4*>(As + p * 68);
            float4* cq = reinterpret_cast<float4*>(As + q * 68);
            float4 ap = cp[sl];
            float4 aq = cq[sl];
            float g = ap.x * aq.x + ap.y * aq.y + ap.z * aq.z + ap.w * aq.w;
            #pragma unroll
            for (int o = 8; o; o >>= 1) g += __shfl_xor_sync(0xFFFFFFFFu, g, o);
            if (g != 0.0f) {
                float al = norms[p], be = norms[q];
                float tau = (be - al) / (2.0f * g);
                float t = 1.0f / (fabsf(tau) + sqrtf(1.0f + tau * tau));
                if (tau < 0.0f) t = -t;
                float c = rsqrtf(1.0f + t * t);
                float s = t * c;
                float4 np, nq;
                np.x = c * ap.x - s * aq.x;  nq.x = s * ap.x + c * aq.x;
                np.y = c * ap.y - s * aq.y;  nq.y = s * ap.y + c * aq.y;
                np.z = c * ap.z - s * aq.z;  nq.z = s * ap.z + c * aq.z;
                np.w = c * ap.w - s * aq.w;  nq.w = s * ap.w + c * aq.w;
                cp[sl] = np;
                cq[sl] = nq;
                if (sl == 0) {
                    float cc = c * c, ss = s * s, cs2 = 2.0f * c * s;
                    norms[p] = cc * al - cs2 * g + ss * be;
                    norms[q] = ss * al + cs2 * g + cc * be;
                }
            }
            __syncthreads();
        }
    }

    for (int j = k; j < 64; j += 32) {
        float4 a = *reinterpret_cast<const float4*>(As + j * 68 + sl * 4);
        float s = a.x * a.x + a.y * a.y + a.z * a.z + a.w * a.w;
        #pragma unroll
        for (int o = 8; o; o >>= 1) s += __shfl_xor_sync(0xFFFFFFFFu, s, o);
        if (sl == 0) {
            s = fmaxf(s, 1e-30f);
            float lam = sqrtf(s) - shift_s;
            gv[j] = apply_fn(f1, lam) / s;
            if (f2 != F_NONE) gv2[j] = apply_fn(f2, lam) / s;
        }
    }
    __syncthreads();

    const int ti = (tid >> 4) * 2;
    const int tj = (tid & 15) << 2;
    {
        float acc[2][4] = {};
        #pragma unroll 4
        for (int kk = 0; kk < 64; ++kk) {
            const float* ck = As + kk * 68;
            float gk = gv[kk];
            float a0 = gk * ck[ti], a1 = gk * ck[ti + 1];
            float b0 = ck[tj], b1 = ck[tj + 1], b2 = ck[tj + 2], b3 = ck[tj + 3];
            acc[0][0] += a0 * b0; acc[0][1] += a0 * b1; acc[0][2] += a0 * b2; acc[0][3] += a0 * b3;
            acc[1][0] += a1 * b0; acc[1][1] += a1 * b1; acc[1][2] += a1 * b2; acc[1][3] += a1 * b3;
        }
        #pragma unroll
        for (int r = 0; r < 2; ++r) {
            float4 v = make_float4(acc[r][0], acc[r][1], acc[r][2], acc[r][3]);
            *reinterpret_cast<float4*>(out1 + boff + (size_t)(ti + r) * 64 + tj) = v;
        }
    }
    if (f2 != F_NONE) {
        float acc[2][4] = {};
        #pragma unroll 4
        for (int kk = 0; kk < 64; ++kk) {
            const float* ck = As + kk * 68;
            float gk = gv2[kk];
            float a0 = gk * ck[ti], a1 = gk * ck[ti + 1];
            float b0 = ck[tj], b1 = ck[tj + 1], b2 = ck[tj + 2], b3 = ck[tj + 3];
            acc[0][0] += a0 * b0; acc[0][1] += a0 * b1; acc[0][2] += a0 * b2; acc[0][3] += a0 * b3;
            acc[1][0] += a1 * b0; acc[1][1] += a1 * b1; acc[1][2] += a1 * b2; acc[1][3] += a1 * b3;
        }
        #pragma unroll
        for (int r = 0; r < 2; ++r) {
            float4 v = make_float4(acc[r][0], acc[r][1], acc[r][2], acc[r][3]);
            *reinterpret_cast<float4*>(out2 + boff + (size_t)(ti + r) * 64 + tj) = v;
        }
    }
}

// out_b = scale * L @ X_b @ R  (L, R broadcast, both plain row-major)
__global__ __launch_bounds__(256) void cong_kernel(
    const float* __restrict__ Lm, const float* __restrict__ Xb,
    const float* __restrict__ Rm, float* __restrict__ out, int useScale)
{
    __shared__ float Ls[MATSZ], Rs[MATSZ], Xs[MATSZ];
    const int tid = threadIdx.x;
    const size_t boff = (size_t)blockIdx.x * MATSZ;
    for (int i = tid; i < MATSZ; i += 256) {
        Ls[i] = Lm[i]; Rs[i] = Rm[i]; Xs[i] = Xb[boff + i];
    }
    __syncthreads();

    const int ti = (tid >> 4) << 2, tj = (tid & 15) << 2;
    float acc[4][4] = {};
    tile_mm_nn(Ls, Xs, acc, ti, tj);          // T = L @ X
    __syncthreads();
    #pragma unroll
    for (int r = 0; r < 4; ++r)
        #pragma unroll
        for (int c = 0; c < 4; ++c) Xs[(ti + r) * 64 + tj + c] = acc[r][c];
    __syncthreads();

    float sc = useScale ? g_scal[0] : 1.0f;
    float acc2[4][4] = {};
    tile_mm_nn(Xs, Rs, acc2, ti, tj);         // out = T @ R
    #pragma unroll
    for (int r = 0; r < 4; ++r) {
        float4 v = make_float4(acc2[r][0] * sc, acc2[r][1] * sc,
                               acc2[r][2] * sc, acc2[r][3] * sc);
        *reinterpret_cast<float4*>(out + boff + (size_t)(ti + r) * 64 + tj) = v;
    }
}

// out_b = A_b @ B_(b*strideB)   (strideB = 0 broadcasts B)
__global__ __launch_bounds__(256) void gemmB_kernel(
    const float* __restrict__ A, const float* __restrict__ Bm, int strideB,
    float* __restrict__ out)
{
    __shared__ float As_[MATSZ], Bs_[MATSZ];
    const int tid = threadIdx.x;
    const size_t boff = (size_t)blockIdx.x * MATSZ;
    const float* Bb = Bm + (size_t)blockIdx.x * strideB;
    for (int i = tid; i < MATSZ; i += 256) { As_[i] = A[boff + i]; Bs_[i] = Bb[i]; }
    __syncthreads();
    const int ti = (tid >> 4) << 2, tj = (tid & 15) << 2;
    float acc[4][4] = {};
    tile_mm_nn(As_, Bs_, acc, ti, tj);
    #pragma unroll
    for (int r = 0; r < 4; ++r) {
        float4 v = make_float4(acc[r][0], acc[r][1], acc[r][2], acc[r][3]);
        *reinterpret_cast<float4*>(out + boff + (size_t)(ti + r) * 64 + tj) = v;
    }
}

// single 64x64 gemm: C = op(A) @ B
__global__ __launch_bounds__(256) void gemm1_kernel(
    const float* __restrict__ A, const float* __restrict__ B,
    float* __restrict__ C, int transA)
{
    __shared__ float As_[MATSZ], Bs_[MATSZ];
    const int tid = threadIdx.x;
    for (int i = tid; i < MATSZ; i += 256) { As_[i] = A[i]; Bs_[i] = B[i]; }
    __syncthreads();
    const int ti = (tid >> 4) << 2, tj = (tid & 15) << 2;
    float acc[4][4] = {};
    if (transA) tile_mm_tn(As_, Bs_, acc, ti, tj);
    else        tile_mm_nn(As_, Bs_, acc, ti, tj);
    #pragma unroll
    for (int r = 0; r < 4; ++r) {
        float4 v = make_float4(acc[r][0], acc[r][1], acc[r][2], acc[r][3]);
        *reinterpret_cast<float4*>(C + (size_t)(ti + r) * 64 + tj) = v;
    }
}

// out[e] = mean_b in[b*4096 + e]
__global__ void mean_kernel(const float* __restrict__ in, float* __restrict__ out)
{
    int e = blockIdx.x * blockDim.x + threadIdx.x;
    double a0 = 0, a1 = 0, a2 = 0, a3 = 0;
    for (int b = 0; b < NB; b += 4) {
        a0 += (double)in[(size_t)(b + 0) * MATSZ + e];
        a1 += (double)in[(size_t)(b + 1) * MATSZ + e];
        a2 += (double)in[(size_t)(b + 2) * MATSZ + e];
        a3 += (double)in[(size_t)(b + 3) * MATSZ + e];
    }
    out[e] = (float)((a0 + a1 + a2 + a3) * (1.0 / (double)NB));
}

// deterministic two-pass sum of squares
__global__ __launch_bounds__(256) void sumsq_kernel(const float* __restrict__ in)
{
    __shared__ double sh[256];
    const int tid = threadIdx.x;
    const size_t base = (size_t)blockIdx.x * 65536;
    double a = 0;
    for (int i = tid; i < 65536; i += 256) {
        float v = in[base + i];
        a += (double)v * (double)v;
    }
    sh[tid] = a;
    __syncthreads();
    for (int s = 128; s > 0; s >>= 1) {
        if (tid < s) sh[tid] += sh[tid + s];
        __syncthreads();
    }
    if (tid == 0) g_part[blockIdx.x] = sh[0];
}

__global__ void finalize_kernel(const float* __restrict__ shift)
{
    __shared__ double sh[256];
    const int tid = threadIdx.x;
    sh[tid] = g_part[tid];
    __syncthreads();
    for (int s = 128; s > 0; s >>= 1) {
        if (tid < s) sh[tid] += sh[tid + s];
        __syncthreads();
    }
    if (tid == 0) {
        double var = sh[0] / (double)NB;
        g_scal[0] = shift[0] / (float)sqrt(var + 1e-5);
    }
}

extern "C" void kernel_launch(void* const* d_in, const int* in_sizes, int n_in,
                              void* d_out, int out_size)
{
    const float* X     = (const float*)d_in[0];
    const float* W     = (const float*)d_in[1];
    const float* M     = (const float*)d_in[2];
    const float* shift = (const float*)d_in[3];
    float* out = (float*)d_out;

    float *bufA, *bufB, *bufC, *bufD, *sm;
    cudaGetSymbolAddress((void**)&bufA, g_bufA);
    cudaGetSymbolAddress((void**)&bufB, g_bufB);
    cudaGetSymbolAddress((void**)&bufC, g_bufC);
    cudaGetSymbolAddress((void**)&bufD, g_bufD);
    cudaGetSymbolAddress((void**)&sm,   g_small);

    cudaFuncSetAttribute(nssqrt_kernel,  cudaFuncAttributeMaxDynamicSharedMemorySize, 65536);
    cudaFuncSetAttribute(nssmall_kernel, cudaFuncAttributeMaxDynamicSharedMemorySize, 65536);
    cudaFuncSetAttribute(expm_kernel,    cudaFuncAttributeMaxDynamicSharedMemorySize, 49152);

    #define SLOT(i) (sm + (i) * MATSZ)
    // slots: 0 Mh, 1 Mnh, 2 Wh, 3 tmp, 4 Wc, 5 Wch, 6 Wcnh, 7 P, 8 Q, 9 R,
    //        10 G0, 11 G0h, 12 G0nh, 13 Tm, 14 expTm, 15 G, 16 mnh, 17 Pt, 18 Qt

    // parameter prep: tiny Newton-Schulz (sqrt + invsqrt)
    nssmall_kernel<<<2, 256, 65536>>>(M, SLOT(0), SLOT(1),   // Mh, Mnh
                                      W, SLOT(2), nullptr);  // Wh
    gemm1_kernel<<<1, 256>>>(SLOT(1), SLOT(2), SLOT(3), 0);  // Mnh Wh
    gemm1_kernel<<<1, 256>>>(SLOT(3), SLOT(1), SLOT(4), 0);  // Wc
    nssmall_kernel<<<1, 256, 65536>>>(SLOT(4), SLOT(5), SLOT(6),  // Wch, Wcnh
                                      SLOT(4), nullptr, nullptr);
    gemm1_kernel<<<1, 256>>>(SLOT(6), SLOT(2), SLOT(7), 0);  // P  = Wcnh Wh
    gemm1_kernel<<<1, 256>>>(SLOT(2), SLOT(6), SLOT(17), 0); // Pt = Wh Wcnh = P^T
    gemm1_kernel<<<1, 256>>>(SLOT(0), SLOT(5), SLOT(8), 0);  // Q  = Mh Wch
    gemm1_kernel<<<1, 256>>>(SLOT(5), SLOT(0), SLOT(18), 0); // Qt = Wch Mh = Q^T
    gemm1_kernel<<<1, 256>>>(SLOT(8), SLOT(8), SLOT(9), 1);  // R = Q^T Q

    // Xp = X^{1/2} (Newton-Schulz); Xc = Mnh Xp Mnh
    nssqrt_kernel<<<NB, 256, 65536>>>(X, bufA);
    cong_kernel<<<NB, 256>>>(SLOT(1), bufA, SLOT(1), bufB, 0);     // Xc

    // bary_geom: 1 Karcher step from arithmetic mean
    mean_kernel<<<16, 256>>>(bufB, SLOT(10));                      // G0
    nssmall_kernel<<<1, 256, 65536>>>(SLOT(10), SLOT(11), SLOT(12),
                                      SLOT(10), nullptr, nullptr); // G0h, G0nh
    cong_kernel<<<NB, 256>>>(SLOT(12), bufB, SLOT(12), bufC, 0);
    jac1s512<<<NB, 512>>>(bufC, bufA, bufA, F_LOG, F_NONE, 0, 6);
    mean_kernel<<<16, 256>>>(bufA, SLOT(13));                      // Tm
    expm_kernel<<<1, 256, 49152>>>(SLOT(13), SLOT(14));            // expTm
    gemm1_kernel<<<1, 256>>>(SLOT(11), SLOT(14), SLOT(3), 0);
    gemm1_kernel<<<1, 256>>>(SLOT(3), SLOT(11), SLOT(15), 0);      // G
    nssmall_kernel<<<1, 256, 65536>>>(SLOT(15), nullptr, SLOT(16),
                                      SLOT(15), nullptr, nullptr); // mnh

    // tangent at I, variance, scale
    cong_kernel<<<NB, 256>>>(SLOT(16), bufB, SLOT(16), bufC, 0);
    jac1s512<<<NB, 512>>>(bufC, bufD, bufD, F_LOG, F_NONE, 0, 6);  // T0
    sumsq_kernel<<<256, 256>>>(bufD);
    finalize_kernel<<<1, 256>>>(shift);

    // arg = factor * P T0 P^T ; E = exp(arg)
    cong_kernel<<<NB, 256>>>(SLOT(7), bufD, SLOT(17), bufC, 1);    // P T0 Pt
    expm_kernel<<<NB, 256, 49152>>>(bufC, bufA);                   // E

    // out = Q (E R E) Q^T
    gemmB_kernel<<<NB, 256>>>(bufA, SLOT(9), 0, bufC);             // E R
    gemmB_kernel<<<NB, 256>>>(bufC, bufA, MATSZ, bufD);            // (E R) E
    cong_kernel<<<NB, 256>>>(SLOT(8), bufD, SLOT(18), out, 0);     // Q .. Qt
    #undef SLOT
}

// round 12
// speedup vs baseline: 2.1537x; 1.1515x over previous
#include <cuda_runtime.h>
#include <math.h>

#define NN 64
#define MATSZ 4096
#define NB 4096

enum { F_NONE = -1, F_SQRT = 0, F_INVSQRT = 1, F_LOG = 2, F_EXP = 3 };

// device-global scratch (no runtime allocation allowed)
__device__ float  g_bufA[(size_t)NB * MATSZ];
__device__ float  g_bufB[(size_t)NB * MATSZ];
__device__ float  g_bufC[(size_t)NB * MATSZ];
__device__ float  g_bufD[(size_t)NB * MATSZ];
__device__ float  g_small[20 * MATSZ];
__device__ double g_part[256];
__device__ double g_meanpart[32 * MATSZ];
__device__ float  g_scal[4];

// Blackwell packed fp32x2 (FFMA2) — PTX-only, ptxas never auto-fuses.
#define PACKF2(d, lo, hi) asm("mov.b64 %0, {%1, %2};" : "=l"(d) : "f"(lo), "f"(hi))
#define UNPACKF2(lo, hi, d) asm("mov.b64 {%0, %1}, %2;" : "=f"(lo), "=f"(hi) : "l"(d))
#define FMAF2(acc, a, b) asm("fma.rn.f32x2 %0, %1, %2, %0;" : "+l"(acc) : "l"(a), "l"(b))

__device__ __forceinline__ float apply_fn(int f, float w) {
    switch (f) {
        case F_SQRT:    return sqrtf(fmaxf(w, 0.0f));
        case F_INVSQRT: return rsqrtf(fmaxf(w, 1e-30f));
        case F_LOG:     return logf(fmaxf(w, 1e-30f));
        case F_EXP:     return expf(w);
    }
    return w;
}

__device__ __forceinline__ float f4c(const float4& v, int k) {
    return k == 0 ? v.x : k == 1 ? v.y : k == 2 ? v.z : v.w;
}

// ---------------------------------------------------------------------------
// 256-thread 4x4-tile inner product with packed f32x2 accumulation.
// ---------------------------------------------------------------------------
__device__ __forceinline__ void tile_mm_nn(const float* __restrict__ A,
                                           const float* __restrict__ B,
                                           float acc[4][4], int ti, int tj)
{
    unsigned long long p01[4], p23[4];
    #pragma unroll
    for (int r = 0; r < 4; ++r) {
        PACKF2(p01[r], acc[r][0], acc[r][1]);
        PACKF2(p23[r], acc[r][2], acc[r][3]);
    }
    #pragma unroll 4
    for (int k4 = 0; k4 < 64; k4 += 4) {
        float4 av[4];
        #pragma unroll
        for (int r = 0; r < 4; ++r)
            av[r] = *reinterpret_cast<const float4*>(A + (ti + r) * 64 + k4);
        #pragma unroll
        for (int kk = 0; kk < 4; ++kk) {
            float4 b = *reinterpret_cast<const float4*>(B + (k4 + kk) * 64 + tj);
            unsigned long long b01, b23;
            PACKF2(b01, b.x, b.y);
            PACKF2(b23, b.z, b.w);
            #pragma unroll
            for (int r = 0; r < 4; ++r) {
                float a = f4c(av[r], kk);
                unsigned long long aa;
                PACKF2(aa, a, a);
                FMAF2(p01[r], aa, b01);
                FMAF2(p23[r], aa, b23);
            }
        }
    }
    #pragma unroll
    for (int r = 0; r < 4; ++r) {
        UNPACKF2(acc[r][0], acc[r][1], p01[r]);
        UNPACKF2(acc[r][2], acc[r][3], p23[r]);
    }
}

// scalar transposed-A tile (tiny gemm1 only)
__device__ __forceinline__ void tile_mm_tn(const float* __restrict__ A,
                                           const float* __restrict__ B,
                                           float acc[4][4], int ti, int tj)
{
    #pragma unroll 4
    for (int k = 0; k < 64; ++k) {
        float a[4];
        #pragma unroll
        for (int r = 0; r < 4; ++r) a[r] = A[k * 64 + ti + r];
        float4 b = *reinterpret_cast<const float4*>(B + k * 64 + tj);
        #pragma unroll
        for (int r = 0; r < 4; ++r) {
            acc[r][0] += a[r] * b.x; acc[r][1] += a[r] * b.y;
            acc[r][2] += a[r] * b.z; acc[r][3] += a[r] * b.w;
        }
    }
}

// ---------------------------------------------------------------------------
// In-shared 64x64 GEMM: C = alpha*(A@B) + beta*D + diag*I. 256 threads.
// ---------------------------------------------------------------------------
__device__ __forceinline__ void mm64(const float* __restrict__ A,
                                     const float* __restrict__ B,
                                     float alpha, float beta,
                                     const float* __restrict__ D,
                                     float diag, float* __restrict__ C, int tid)
{
    const int ti = (tid >> 4) << 2, tj = (tid & 15) << 2;
    float acc[4][4] = {};
    tile_mm_nn(A, B, acc, ti, tj);
    __syncthreads();
    #pragma unroll
    for (int r = 0; r < 4; ++r) {
        float4 v;
        v.x = alpha * acc[r][0]; v.y = alpha * acc[r][1];
        v.z = alpha * acc[r][2]; v.w = alpha * acc[r][3];
        if (beta != 0.0f) {
            float4 d = *reinterpret_cast<const float4*>(D + (ti + r) * 64 + tj);
            v.x += beta * d.x; v.y += beta * d.y; v.z += beta * d.z; v.w += beta * d.w;
        }
        if (diag != 0.0f) {
            int row = ti + r;
            if (row >= tj && row < tj + 4) (&v.x)[row - tj] += diag;
        }
        *reinterpret_cast<float4*>(C + (ti + r) * 64 + tj) = v;
    }
    __syncthreads();
}

// ---------------------------------------------------------------------------
// 1024-thread in-shared 64x64 GEMM (2x2 tiles; A-loads are warp-broadcast).
// Lower latency for single-CTA (serial-chain) use.
// ---------------------------------------------------------------------------
__device__ __forceinline__ void mm64w(const float* __restrict__ A,
                                      const float* __restrict__ B,
                                      float alpha, float beta,
                                      const float* __restrict__ D,
                                      float diag, float* __restrict__ C, int tid)
{
    const int ti = (tid >> 5) << 1;   // rows, constant within a warp
    const int tj = (tid & 31) << 1;   // cols
    unsigned long long p0, p1;
    PACKF2(p0, 0.0f, 0.0f);
    PACKF2(p1, 0.0f, 0.0f);
    #pragma unroll 4
    for (int k4 = 0; k4 < 64; k4 += 4) {
        float4 a0 = *reinterpret_cast<const float4*>(A + ti * 64 + k4);
        float4 a1 = *reinterpret_cast<const float4*>(A + (ti + 1) * 64 + k4);
        #pragma unroll
        for (int kk = 0; kk < 4; ++kk) {
            float2 b = *reinterpret_cast<const float2*>(B + (k4 + kk) * 64 + tj);
            unsigned long long bb, aa0, aa1;
            PACKF2(bb, b.x, b.y);
            float f0 = f4c(a0, kk), f1 = f4c(a1, kk);
            PACKF2(aa0, f0, f0);
            PACKF2(aa1, f1, f1);
            FMAF2(p0, aa0, bb);
            FMAF2(p1, aa1, bb);
        }
    }
    float acc[2][2];
    UNPACKF2(acc[0][0], acc[0][1], p0);
    UNPACKF2(acc[1][0], acc[1][1], p1);
    __syncthreads();
    #pragma unroll
    for (int r = 0; r < 2; ++r) {
        float2 v;
        v.x = alpha * acc[r][0];
        v.y = alpha * acc[r][1];
        if (beta != 0.0f) {
            float2 d = *reinterpret_cast<const float2*>(D + (ti + r) * 64 + tj);
            v.x += beta * d.x; v.y += beta * d.y;
        }
        if (diag != 0.0f) {
            int row = ti + r;
            if (row == tj)     v.x += diag;
            if (row == tj + 1) v.y += diag;
        }
        *reinterpret_cast<float2*>(C + (ti + r) * 64 + tj) = v;
    }
    __syncthreads();
}

template <int TPB>
__device__ __forceinline__ void mmX(const float* A, const float* B,
                                    float alpha, float beta, const float* D,
                                    float diag, float* C, int tid)
{
    if (TPB == 256) mm64(A, B, alpha, beta, D, diag, C, tid);
    else            mm64w(A, B, alpha, beta, D, diag, C, tid);
}

// ---------------------------------------------------------------------------
// Batched matrix sqrt via coupled Newton-Schulz. One CTA/matrix, 8 iters
// (X spectrum [0.5, 4.5] by construction -> scaled residual ~7e-8).
// ---------------------------------------------------------------------------
__global__ __launch_bounds__(256) void nssqrt_kernel(
    const float* __restrict__ in, float* __restrict__ out)
{
    extern __shared__ float sh[];          // 4 * 4096 floats
    float *Y = sh, *Z = sh + 4096, *W = sh + 8192, *T = sh + 12288;
    __shared__ float red[256];
    __shared__ float s_s;

    const int tid = threadIdx.x;
    const size_t boff = (size_t)blockIdx.x * MATSZ;

    float fa = 0.0f;
    for (int idx = tid; idx < MATSZ; idx += 256) {
        float v = in[boff + idx];
        Y[idx] = v;
        fa += v * v;
        Z[idx] = ((idx >> 6) == (idx & 63)) ? 1.0f : 0.0f;
    }
    red[tid] = fa;
    __syncthreads();
    #pragma unroll
    for (int s = 128; s > 0; s >>= 1) {
        if (tid < s) red[tid] += red[tid + s];
        __syncthreads();
    }
    if (tid == 0) s_s = fmaxf(sqrtf(red[0]) / 1.8f, 1e-20f);
    __syncthreads();
    float inv_s = 1.0f / s_s;
    for (int idx = tid; idx < MATSZ; idx += 256) Y[idx] *= inv_s;
    __syncthreads();

    for (int it = 0; it < 8; ++it) {
        mm64(Z, Y, 1.0f, 0.0f, nullptr, 0.0f, W, tid);      // W = Z@Y
        mm64(Y, W, -0.5f, 1.5f, Y, 0.0f, T, tid);           // T = 1.5Y - 0.5 Y@W
        if (it < 7) {
            mm64(W, Z, -0.5f, 1.5f, Z, 0.0f, Y, tid);       // Znew -> old Y buffer
            float* nY = T; float* nZ = Y; float* nT = Z;
            Y = nY; Z = nZ; T = nT;
        } else {
            Y = T;
        }
    }
    float rs = sqrtf(s_s);
    for (int idx = tid; idx < MATSZ; idx += 256)
        out[boff + idx] = Y[idx] * rs;
}

// ---------------------------------------------------------------------------
// Tiny (1-2 matrix) coupled Newton-Schulz: A^{1/2} and A^{-1/2}. 1024 thr.
// ---------------------------------------------------------------------------
__global__ __launch_bounds__(1024) void nssmall_kernel(
    const float* __restrict__ inA, float* sqA, float* isqA,
    const float* __restrict__ inB, float* sqB, float* isqB)
{
    extern __shared__ float sh[];          // 4 * 4096 floats
    float *Y = sh, *Z = sh + 4096, *W = sh + 8192, *T = sh + 12288;
    __shared__ float red[1024];
    __shared__ float s_s;

    const int tid = threadIdx.x;
    const float* in = blockIdx.x ? inB : inA;
    float* osq  = blockIdx.x ? sqB  : sqA;
    float* oisq = blockIdx.x ? isqB : isqA;

    float fa = 0.0f;
    for (int idx = tid; idx < MATSZ; idx += 1024) {
        float v = in[idx];
        Y[idx] = v;
        fa += v * v;
        Z[idx] = ((idx >> 6) == (idx & 63)) ? 1.0f : 0.0f;
    }
    red[tid] = fa;
    __syncthreads();
    #pragma unroll
    for (int s = 512; s > 0; s >>= 1) {
        if (tid < s) red[tid] += red[tid + s];
        __syncthreads();
    }
    if (tid == 0) s_s = fmaxf(sqrtf(red[0]) / 1.8f, 1e-20f);
    __syncthreads();
    float inv_s = 1.0f / s_s;
    for (int idx = tid; idx < MATSZ; idx += 1024) Y[idx] *= inv_s;
    __syncthreads();

    for (int it = 0; it < 12; ++it) {
        mm64w(Z, Y, 1.0f, 0.0f, nullptr, 0.0f, W, tid);     // W = Z@Y
        mm64w(Y, W, -0.5f, 1.5f, Y, 0.0f, T, tid);          // newY -> T
        mm64w(W, Z, -0.5f, 1.5f, Z, 0.0f, Y, tid);          // newZ -> old Y
        float* oY = Y; float* oZ = Z;
        Y = T; Z = oY; T = oZ;
    }
    float rs  = sqrtf(s_s);
    float irs = rsqrtf(s_s);
    if (osq)
        for (int idx = tid; idx < MATSZ; idx += 1024) osq[idx] = Y[idx] * rs;
    if (oisq)
        for (int idx = tid; idx < MATSZ; idx += 1024) oisq[idx] = Z[idx] * irs;
}

// ---------------------------------------------------------------------------
// Matrix exp: scaling-and-squaring + degree-5 Taylor (Horner).
// ---------------------------------------------------------------------------
template <int TPB>
__global__ __launch_bounds__(TPB) void expm_kernel(
    const float* __restrict__ in, float* __restrict__ out)
{
    extern __shared__ float sh[];          // 3 * 4096 floats
    float *B = sh, *P = sh + 4096, *Q = sh + 8192;
    __shared__ float red[TPB];
    __shared__ float sc_s;
    __shared__ int   j_s;

    const int tid = threadIdx.x;
    const size_t boff = (size_t)blockIdx.x * MATSZ;

    float fa = 0.0f;
    for (int idx = tid; idx < MATSZ; idx += TPB) {
        float v = in[boff + idx];
        B[idx] = v;
        fa += v * v;
    }
    red[tid] = fa;
    __syncthreads();
    #pragma unroll
    for (int s = TPB / 2; s > 0; s >>= 1) {
        if (tid < s) red[tid] += red[tid + s];
        __syncthreads();
    }
    if (tid == 0) {
        float F = sqrtf(red[0]);
        int j = 0;
        while (F > 0.25f && j < 40) { F *= 0.5f; ++j; }
        j_s = j;
        sc_s = exp2f((float)(-j));
    }
    __syncthreads();
    const int j = j_s;
    float sc = sc_s;
    for (int idx = tid; idx < MATSZ; idx += TPB) B[idx] *= sc;
    __syncthreads();

    const float c5 = 1.0f / 120.0f, c4 = 1.0f / 24.0f;
    for (int idx = tid; idx < MATSZ; idx += TPB) {
        float v = c5 * B[idx];
        if ((idx >> 6) == (idx & 63)) v += c4;
        P[idx] = v;
    }
    __syncthreads();
    const float cs[4] = { 1.0f / 6.0f, 0.5f, 1.0f, 1.0f };
    float *cur = P, *oth = Q;
    #pragma unroll
    for (int k = 0; k < 4; ++k) {
        mmX<TPB>(cur, B, 1.0f, 0.0f, nullptr, cs[k], oth, tid);
        float* t = cur; cur = oth; oth = t;
    }
    for (int t = 0; t < j; ++t) {
        mmX<TPB>(cur, cur, 1.0f, 0.0f, nullptr, 0.0f, oth, tid);
        float* tt = cur; cur = oth; oth = tt;
    }
    for (int idx = tid; idx < MATSZ; idx += TPB)
        out[boff + idx] = cur[idx];
}

// ---------------------------------------------------------------------------
// One-sided (Hestenes) Jacobi, symmetric 64x64 — half-warp float4 version.
// ---------------------------------------------------------------------------
__global__ __launch_bounds__(512) void jac1s512(
    const float* __restrict__ in, float* __restrict__ out1,
    float* __restrict__ out2, int f1, int f2, int useShift, int nsweeps)
{
    __shared__ float  As[64 * 68];
    __shared__ float  norms[64];
    __shared__ float  gv[64], gv2[64];
    __shared__ float  red[512];
    __shared__ float  shift_s;
    __shared__ uchar2 ptab[63 * 32];

    const int tid  = threadIdx.x;
    const int lane = tid & 31;
    const int wid  = tid >> 5;
    const int sl   = lane & 15;
    const int k    = (wid << 1) | (lane >> 4);
    const size_t boff = (size_t)blockIdx.x * MATSZ;

    for (int i = tid; i < 63 * 32; i += 512) {
        int r = i >> 5, kk = i & 31;
        int p, q;
        if (kk == 0) { p = 63; q = r; }
        else {
            int a1 = r + kk;      p = (a1 < 63) ? a1 : a1 - 63;
            int a2 = r + 63 - kk; q = (a2 < 63) ? a2 : a2 - 63;
        }
        ptab[i] = make_uchar2((unsigned char)p, (unsigned char)q);
    }

    float fa = 0.0f;
    for (int idx = tid; idx < MATSZ; idx += 512) {
        int c = idx >> 6, r = idx & 63;
        float v = in[boff + idx];
        As[c * 68 + r] = v;
        fa += v * v;
    }
    red[tid] = fa;
    __syncthreads();
    if (useShift) {
        #pragma unroll
        for (int s = 256; s > 0; s >>= 1) {
            if (tid < s) red[tid] += red[tid + s];
            __syncthreads();
        }
        if (tid == 0) shift_s = sqrtf(red[0]) * 1.000001f + 1e-20f;
        __syncthreads();
        if (tid < 64) As[tid * 68 + tid] += shift_s;
    } else {
        if (tid == 0) shift_s = 0.0f;
    }
    __syncthreads();

    for (int j = k; j < 64; j += 32) {
        float4 a = *reinterpret_cast<const float4*>(As + j * 68 + sl * 4);
        float s = a.x * a.x + a.y * a.y + a.z * a.z + a.w * a.w;
        #pragma unroll
        for (int o = 8; o; o >>= 1) s += __shfl_xor_sync(0xFFFFFFFFu, s, o);
        if (sl == 0) norms[j] = s;
    }
    __syncthreads();

    for (int sw = 0; sw < nsweeps; ++sw) {
        for (int r = 0; r < 63; ++r) {
            uchar2 pq = ptab[(r << 5) | k];
            const int p = pq.x, q = pq.y;
            float4* cp = reinterpret_cast<float4*>(As + p * 68);
            float4* cq = reinterpret_cast<float4*>(As + q * 68);
            float4 ap = cp[sl];
            float4 aq = cq[sl];
            float g = ap.x * aq.x + ap.y * aq.y + ap.z * aq.z + ap.w * aq.w;
            #pragma unroll
            for (int o = 8; o; o >>= 1) g += __shfl_xor_sync(0xFFFFFFFFu, g, o);
            if (g != 0.0f) {
                float al = norms[p], be = norms[q];
                float tau = (be - al) / (2.0f * g);
                float t = 1.0f / (fabsf(tau) + sqrtf(1.0f + tau * tau));
                if (tau < 0.0f) t = -t;
                float c = rsqrtf(1.0f + t * t);
                float s = t * c;
                float4 np, nq;
                np.x = c * ap.x - s * aq.x;  nq.x = s * ap.x + c * aq.x;
                np.y = c * ap.y - s * aq.y;  nq.y = s * ap.y + c * aq.y;
                np.z = c * ap.z - s * aq.z;  nq.z = s * ap.z + c * aq.z;
                np.w = c * ap.w - s * aq.w;  nq.w = s * ap.w + c * aq.w;
                cp[sl] = np;
                cq[sl] = nq;
                if (sl == 0) {
                    float cc = c * c, ss = s * s, cs2 = 2.0f * c * s;
                    norms[p] = cc * al - cs2 * g + ss * be;
                    norms[q] = ss * al + cs2 * g + cc * be;
                }
            }
            __syncthreads();
        }
    }

    for (int j = k; j < 64; j += 32) {
        float4 a = *reinterpret_cast<const float4*>(As + j * 68 + sl * 4);
        float s = a.x * a.x + a.y * a.y + a.z * a.z + a.w * a.w;
        #pragma unroll
        for (int o = 8; o; o >>= 1) s += __shfl_xor_sync(0xFFFFFFFFu, s, o);
        if (sl == 0) {
            s = fmaxf(s, 1e-30f);
            float lam = sqrtf(s) - shift_s;
            gv[j] = apply_fn(f1, lam) / s;
            if (f2 != F_NONE) gv2[j] = apply_fn(f2, lam) / s;
        }
    }
    __syncthreads();

    const int ti = (tid >> 4) * 2;
    const int tj = (tid & 15) << 2;
    {
        float acc[2][4] = {};
        #pragma unroll 4
        for (int kk = 0; kk < 64; ++kk) {
            const float* ck = As + kk * 68;
            float gk = gv[kk];
            float a0 = gk * ck[ti], a1 = gk * ck[ti + 1];
            float b0 = ck[tj], b1 = ck[tj + 1], b2 = ck[tj + 2], b3 = ck[tj + 3];
            acc[0][0] += a0 * b0; acc[0][1] += a0 * b1; acc[0][2] += a0 * b2; acc[0][3] += a0 * b3;
            acc[1][0] += a1 * b0; acc[1][1] += a1 * b1; acc[1][2] += a1 * b2; acc[1][3] += a1 * b3;
        }
        #pragma unroll
        for (int r = 0; r < 2; ++r) {
            float4 v = make_float4(acc[r][0], acc[r][1], acc[r][2], acc[r][3]);
            *reinterpret_cast<float4*>(out1 + boff + (size_t)(ti + r) * 64 + tj) = v;
        }
    }
    if (f2 != F_NONE) {
        float acc[2][4] = {};
        #pragma unroll 4
        for (int kk = 0; kk < 64; ++kk) {
            const float* ck = As + kk * 68;
            float gk = gv2[kk];
            float a0 = gk * ck[ti], a1 = gk * ck[ti + 1];
            float b0 = ck[tj], b1 = ck[tj + 1], b2 = ck[tj + 2], b3 = ck[tj + 3];
            acc[0][0] += a0 * b0; acc[0][1] += a0 * b1; acc[0][2] += a0 * b2; acc[0][3] += a0 * b3;
            acc[1][0] += a1 * b0; acc[1][1] += a1 * b1; acc[1][2] += a1 * b2; acc[1][3] += a1 * b3;
        }
        #pragma unroll
        for (int r = 0; r < 2; ++r) {
            float4 v = make_float4(acc[r][0], acc[r][1], acc[r][2], acc[r][3]);
            *reinterpret_cast<float4*>(out2 + boff + (size_t)(ti + r) * 64 + tj) = v;
        }
    }
}

// out_b = scale * L @ X_b @ R  (L, R broadcast, both plain row-major)
__global__ __launch_bounds__(256) void cong_kernel(
    const float* __restrict__ Lm, const float* __restrict__ Xb,
    const float* __restrict__ Rm, float* __restrict__ out, int useScale)
{
    __shared__ float Ls[MATSZ], Rs[MATSZ], Xs[MATSZ];
    const int tid = threadIdx.x;
    const size_t boff = (size_t)blockIdx.x * MATSZ;
    for (int i = tid; i < MATSZ; i += 256) {
        Ls[i] = Lm[i]; Rs[i] = Rm[i]; Xs[i] = Xb[boff + i];
    }
    __syncthreads();

    const int ti = (tid >> 4) << 2, tj = (tid & 15) << 2;
    float acc[4][4] = {};
    tile_mm_nn(Ls, Xs, acc, ti, tj);          // T = L @ X
    __syncthreads();
    #pragma unroll
    for (int r = 0; r < 4; ++r)
        #pragma unroll
        for (int c = 0; c < 4; ++c) Xs[(ti + r) * 64 + tj + c] = acc[r][c];
    __syncthreads();

    float sc = useScale ? g_scal[0] : 1.0f;
    float acc2[4][4] = {};
    tile_mm_nn(Xs, Rs, acc2, ti, tj);         // out = T @ R
    #pragma unroll
    for (int r = 0; r < 4; ++r) {
        float4 v = make_float4(acc2[r][0] * sc, acc2[r][1] * sc,
                               acc2[r][2] * sc, acc2[r][3] * sc);
        *reinterpret_cast<float4*>(out + boff + (size_t)(ti + r) * 64 + tj) = v;
    }
}

// out_b = A_b @ B_(b*strideB)   (strideB = 0 broadcasts B)
__global__ __launch_bounds__(256) void gemmB_kernel(
    const float* __restrict__ A, const float* __restrict__ Bm, int strideB,
    float* __restrict__ out)
{
    __shared__ float As_[MATSZ], Bs_[MATSZ];
    const int tid = threadIdx.x;
    const size_t boff = (size_t)blockIdx.x * MATSZ;
    const float* Bb = Bm + (size_t)blockIdx.x * strideB;
    for (int i = tid; i < MATSZ; i += 256) { As_[i] = A[boff + i]; Bs_[i] = Bb[i]; }
    __syncthreads();
    const int ti = (tid >> 4) << 2, tj = (tid & 15) << 2;
    float acc[4][4] = {};
    tile_mm_nn(As_, Bs_, acc, ti, tj);
    #pragma unroll
    for (int r = 0; r < 4; ++r) {
        float4 v = make_float4(acc[r][0], acc[r][1], acc[r][2], acc[r][3]);
        *reinterpret_cast<float4*>(out + boff + (size_t)(ti + r) * 64 + tj) = v;
    }
}

// single 64x64 gemm: C = op(A) @ B
__global__ __launch_bounds__(256) void gemm1_kernel(
    const float* __restrict__ A, const float* __restrict__ B,
    float* __restrict__ C, int transA)
{
    __shared__ float As_[MATSZ], Bs_[MATSZ];
    const int tid = threadIdx.x;
    for (int i = tid; i < MATSZ; i += 256) { As_[i] = A[i]; Bs_[i] = B[i]; }
    __syncthreads();
    const int ti = (tid >> 4) << 2, tj = (tid & 15) << 2;
    float acc[4][4] = {};
    if (transA) tile_mm_tn(As_, Bs_, acc, ti, tj);
    else        tile_mm_nn(As_, Bs_, acc, ti, tj);
    #pragma unroll
    for (int r = 0; r < 4; ++r) {
        float4 v = make_float4(acc[r][0], acc[r][1], acc[r][2], acc[r][3]);
        *reinterpret_cast<float4*>(C + (size_t)(ti + r) * 64 + tj) = v;
    }
}

// two-phase batch mean: phase 1, 512 blocks (32 bchunks x 16 eblocks)
__global__ __launch_bounds__(256) void mean1_kernel(const float* __restrict__ in)
{
    const int bc = blockIdx.x >> 4;
    const int e  = ((blockIdx.x & 15) << 8) + threadIdx.x;
    const float* base = in + (size_t)bc * 128 * MATSZ + e;
    double a0 = 0, a1 = 0, a2 = 0, a3 = 0;
    for (int b = 0; b < 128; b += 4) {
        a0 += (double)base[(size_t)(b + 0) * MATSZ];
        a1 += (double)base[(size_t)(b + 1) * MATSZ];
        a2 += (double)base[(size_t)(b + 2) * MATSZ];
        a3 += (double)base[(size_t)(b + 3) * MATSZ];
    }
    g_meanpart[bc * MATSZ + e] = (a0 + a1) + (a2 + a3);
}

// phase 2: 16 blocks x 256 threads, deterministic order over 32 chunks
__global__ __launch_bounds__(256) void mean2_kernel(float* __restrict__ out)
{
    const int e = (blockIdx.x << 8) + threadIdx.x;
    double a = 0;
    #pragma unroll
    for (int c = 0; c < 32; ++c) a += g_meanpart[c * MATSZ + e];
    out[e] = (float)(a * (1.0 / (double)NB));
}

// deterministic two-pass sum of squares
__global__ __launch_bounds__(256) void sumsq_kernel(const float* __restrict__ in)
{
    __shared__ double sh[256];
    const int tid = threadIdx.x;
    const size_t base = (size_t)blockIdx.x * 65536;
    double a = 0;
    for (int i = tid; i < 65536; i += 256) {
        float v = in[base + i];
        a += (double)v * (double)v;
    }
    sh[tid] = a;
    __syncthreads();
    for (int s = 128; s > 0; s >>= 1) {
        if (tid < s) sh[tid] += sh[tid + s];
        __syncthreads();
    }
    if (tid == 0) g_part[blockIdx.x] = sh[0];
}

__global__ void finalize_kernel(const float* __restrict__ shift)
{
    __shared__ double sh[256];
    const int tid = threadIdx.x;
    sh[tid] = g_part[tid];
    __syncthreads();
    for (int s = 128; s > 0; s >>= 1) {
        if (tid < s) sh[tid] += sh[tid + s];
        __syncthreads();
    }
    if (tid == 0) {
        double var = sh[0] / (double)NB;
        g_scal[0] = shift[0] / (float)sqrt(var + 1e-5);
    }
}

extern "C" void kernel_launch(void* const* d_in, const int* in_sizes, int n_in,
                              void* d_out, int out_size)
{
    const float* X     = (const float*)d_in[0];
    const float* W     = (const float*)d_in[1];
    const float* M     = (const float*)d_in[2];
    const float* shift = (const float*)d_in[3];
    float* out = (float*)d_out;

    float *bufA, *bufB, *bufC, *bufD, *sm;
    cudaGetSymbolAddress((void**)&bufA, g_bufA);
    cudaGetSymbolAddress((void**)&bufB, g_bufB);
    cudaGetSymbolAddress((void**)&bufC, g_bufC);
    cudaGetSymbolAddress((void**)&bufD, g_bufD);
    cudaGetSymbolAddress((void**)&sm,   g_small);

    cudaFuncSetAttribute(nssqrt_kernel,  cudaFuncAttributeMaxDynamicSharedMemorySize, 65536);
    cudaFuncSetAttribute(nssmall_kernel, cudaFuncAttributeMaxDynamicSharedMemorySize, 65536);
    cudaFuncSetAttribute(expm_kernel<256>,  cudaFuncAttributeMaxDynamicSharedMemorySize, 49152);
    cudaFuncSetAttribute(expm_kernel<1024>, cudaFuncAttributeMaxDynamicSharedMemorySize, 49152);

    // fork-join resources (created once; captured graph identical every call)
    static cudaStream_t s2 = [] {
        cudaStream_t s; cudaStreamCreateWithFlags(&s, cudaStreamNonBlocking); return s;
    }();
    static cudaEvent_t evFork = [] {
        cudaEvent_t e; cudaEventCreateWithFlags(&e, cudaEventDisableTiming); return e;
    }();
    static cudaEvent_t evMnh = [] {
        cudaEvent_t e; cudaEventCreateWithFlags(&e, cudaEventDisableTiming); return e;
    }();
    static cudaEvent_t evPrep = [] {
        cudaEvent_t e; cudaEventCreateWithFlags(&e, cudaEventDisableTiming); return e;
    }();

    #define SLOT(i) (sm + (i) * MATSZ)
    // slots: 0 Mh, 1 Mnh, 2 Wh, 3 prep-tmp, 4 Wc, 5 Wch, 6 Wcnh, 7 P, 8 Q, 9 R,
    //        10 G0, 11 G0h, 12 G0nh, 13 Tm, 14 expTm, 15 G, 16 mnh, 17 Pt,
    //        18 Qt, 19 mid-tmp

    // ---- fork: parameter prep on s2, concurrent with nssqrt on stream0 ----
    cudaEventRecord(evFork, 0);
    cudaStreamWaitEvent(s2, evFork, 0);
    nssmall_kernel<<<2, 1024, 65536, s2>>>(M, SLOT(0), SLOT(1),   // Mh, Mnh
                                           W, SLOT(2), nullptr);  // Wh
    cudaEventRecord(evMnh, s2);
    gemm1_kernel<<<1, 256, 0, s2>>>(SLOT(1), SLOT(2), SLOT(3), 0);   // Mnh Wh
    gemm1_kernel<<<1, 256, 0, s2>>>(SLOT(3), SLOT(1), SLOT(4), 0);   // Wc
    nssmall_kernel<<<1, 1024, 65536, s2>>>(SLOT(4), SLOT(5), SLOT(6),
                                           SLOT(4), nullptr, nullptr); // Wch, Wcnh
    gemm1_kernel<<<1, 256, 0, s2>>>(SLOT(6), SLOT(2), SLOT(7), 0);   // P  = Wcnh Wh
    gemm1_kernel<<<1, 256, 0, s2>>>(SLOT(2), SLOT(6), SLOT(17), 0);  // Pt = Wh Wcnh
    gemm1_kernel<<<1, 256, 0, s2>>>(SLOT(0), SLOT(5), SLOT(8), 0);   // Q  = Mh Wch
    gemm1_kernel<<<1, 256, 0, s2>>>(SLOT(5), SLOT(0), SLOT(18), 0);  // Qt = Wch Mh
    gemm1_kernel<<<1, 256, 0, s2>>>(SLOT(8), SLOT(8), SLOT(9), 1);   // R = Q^T Q
    cudaEventRecord(evPrep, s2);

    // ---- stream0: Xp = X^{1/2}; join Mnh; Xc = Mnh Xp Mnh ----
    nssqrt_kernel<<<NB, 256, 65536>>>(X, bufA);
    cudaStreamWaitEvent(0, evMnh, 0);
    cong_kernel<<<NB, 256>>>(SLOT(1), bufA, SLOT(1), bufB, 0);       // Xc

    // bary_geom: 1 Karcher step from arithmetic mean
    mean1_kernel<<<512, 256>>>(bufB);
    mean2_kernel<<<16, 256>>>(SLOT(10));                             // G0
    nssmall_kernel<<<1, 1024, 65536>>>(SLOT(10), SLOT(11), SLOT(12),
                                       SLOT(10), nullptr, nullptr);  // G0h, G0nh
    cong_kernel<<<NB, 256>>>(SLOT(12), bufB, SLOT(12), bufC, 0);
    jac1s512<<<NB, 512>>>(bufC, bufA, bufA, F_LOG, F_NONE, 0, 6);
    mean1_kernel<<<512, 256>>>(bufA);
    mean2_kernel<<<16, 256>>>(SLOT(13));                             // Tm
    expm_kernel<1024><<<1, 1024, 49152>>>(SLOT(13), SLOT(14));       // expTm
    gemm1_kernel<<<1, 256>>>(SLOT(11), SLOT(14), SLOT(19), 0);
    gemm1_kernel<<<1, 256>>>(SLOT(19), SLOT(11), SLOT(15), 0);       // G
    nssmall_kernel<<<1, 1024, 65536>>>(SLOT(15), nullptr, SLOT(16),
                                       SLOT(15), nullptr, nullptr);  // mnh

    // tangent at I, variance, scale
    cong_kernel<<<NB, 256>>>(SLOT(16), bufB, SLOT(16), bufC, 0);
    jac1s512<<<NB, 512>>>(bufC, bufD, bufD, F_LOG, F_NONE, 0, 6);    // T0
    sumsq_kernel<<<256, 256>>>(bufD);
    finalize_kernel<<<1, 256>>>(shift);

    // join full prep; arg = factor * P T0 P^T ; E = exp(arg)
    cudaStreamWaitEvent(0, evPrep, 0);
    cong_kernel<<<NB, 256>>>(SLOT(7), bufD, SLOT(17), bufC, 1);      // P T0 Pt
    expm_kernel<256><<<NB, 256, 49152>>>(bufC, bufA);                // E

    // out = Q (E R E) Q^T
    gemmB_kernel<<<NB, 256>>>(bufA, SLOT(9), 0, bufC);               // E R
    gemmB_kernel<<<NB, 256>>>(bufC, bufA, MATSZ, bufD);              // (E R) E
    cong_kernel<<<NB, 256>>>(SLOT(8), bufD, SLOT(18), out, 0);       // Q .. Qt
    #undef SLOT
}

// round 13
// speedup vs baseline: 2.2037x; 1.0232x over previous
#include <cuda_runtime.h>
#include <math.h>

#define NN 64
#define MATSZ 4096
#define NB 4096

enum { F_NONE = -1, F_SQRT = 0, F_INVSQRT = 1, F_LOG = 2, F_EXP = 3 };

// device-global scratch (no runtime allocation allowed)
__device__ float  g_bufA[(size_t)NB * MATSZ];
__device__ float  g_bufB[(size_t)NB * MATSZ];
__device__ float  g_bufC[(size_t)NB * MATSZ];
__device__ float  g_bufD[(size_t)NB * MATSZ];
__device__ float  g_small[20 * MATSZ];
__device__ double g_part[256];
__device__ double g_meanpart[32 * MATSZ];
__device__ float  g_scal[4];

// Blackwell packed fp32x2 (FFMA2) — PTX-only, ptxas never auto-fuses.
#define PACKF2(d, lo, hi) asm("mov.b64 %0, {%1, %2};" : "=l"(d) : "f"(lo), "f"(hi))
#define UNPACKF2(lo, hi, d) asm("mov.b64 {%0, %1}, %2;" : "=f"(lo), "=f"(hi) : "l"(d))
#define FMAF2(acc, a, b) asm("fma.rn.f32x2 %0, %1, %2, %0;" : "+l"(acc) : "l"(a), "l"(b))

__device__ __forceinline__ float apply_fn(int f, float w) {
    switch (f) {
        case F_SQRT:    return sqrtf(fmaxf(w, 0.0f));
        case F_INVSQRT: return rsqrtf(fmaxf(w, 1e-30f));
        case F_LOG:     return logf(fmaxf(w, 1e-30f));
        case F_EXP:     return expf(w);
    }
    return w;
}

__device__ __forceinline__ float f4c(const float4& v, int k) {
    return k == 0 ? v.x : k == 1 ? v.y : k == 2 ? v.z : v.w;
}

// ---------------------------------------------------------------------------
// 256-thread 4x4-tile inner product with packed f32x2 accumulation.
// ---------------------------------------------------------------------------
__device__ __forceinline__ void tile_mm_nn(const float* __restrict__ A,
                                           const float* __restrict__ B,
                                           float acc[4][4], int ti, int tj)
{
    unsigned long long p01[4], p23[4];
    #pragma unroll
    for (int r = 0; r < 4; ++r) {
        PACKF2(p01[r], acc[r][0], acc[r][1]);
        PACKF2(p23[r], acc[r][2], acc[r][3]);
    }
    #pragma unroll 4
    for (int k4 = 0; k4 < 64; k4 += 4) {
        float4 av[4];
        #pragma unroll
        for (int r = 0; r < 4; ++r)
            av[r] = *reinterpret_cast<const float4*>(A + (ti + r) * 64 + k4);
        #pragma unroll
        for (int kk = 0; kk < 4; ++kk) {
            float4 b = *reinterpret_cast<const float4*>(B + (k4 + kk) * 64 + tj);
            unsigned long long b01, b23;
            PACKF2(b01, b.x, b.y);
            PACKF2(b23, b.z, b.w);
            #pragma unroll
            for (int r = 0; r < 4; ++r) {
                float a = f4c(av[r], kk);
                unsigned long long aa;
                PACKF2(aa, a, a);
                FMAF2(p01[r], aa, b01);
                FMAF2(p23[r], aa, b23);
            }
        }
    }
    #pragma unroll
    for (int r = 0; r < 4; ++r) {
        UNPACKF2(acc[r][0], acc[r][1], p01[r]);
        UNPACKF2(acc[r][2], acc[r][3], p23[r]);
    }
}

// scalar transposed-A tile (tiny gemm1 only)
__device__ __forceinline__ void tile_mm_tn(const float* __restrict__ A,
                                           const float* __restrict__ B,
                                           float acc[4][4], int ti, int tj)
{
    #pragma unroll 4
    for (int k = 0; k < 64; ++k) {
        float a[4];
        #pragma unroll
        for (int r = 0; r < 4; ++r) a[r] = A[k * 64 + ti + r];
        float4 b = *reinterpret_cast<const float4*>(B + k * 64 + tj);
        #pragma unroll
        for (int r = 0; r < 4; ++r) {
            acc[r][0] += a[r] * b.x; acc[r][1] += a[r] * b.y;
            acc[r][2] += a[r] * b.z; acc[r][3] += a[r] * b.w;
        }
    }
}

// ---------------------------------------------------------------------------
// In-shared 64x64 GEMM: C = alpha*(A@B) + beta*D + diag*I. 256 threads.
// ---------------------------------------------------------------------------
__device__ __forceinline__ void mm64(const float* __restrict__ A,
                                     const float* __restrict__ B,
                                     float alpha, float beta,
                                     const float* __restrict__ D,
                                     float diag, float* __restrict__ C, int tid)
{
    const int ti = (tid >> 4) << 2, tj = (tid & 15) << 2;
    float acc[4][4] = {};
    tile_mm_nn(A, B, acc, ti, tj);
    __syncthreads();
    #pragma unroll
    for (int r = 0; r < 4; ++r) {
        float4 v;
        v.x = alpha * acc[r][0]; v.y = alpha * acc[r][1];
        v.z = alpha * acc[r][2]; v.w = alpha * acc[r][3];
        if (beta != 0.0f) {
            float4 d = *reinterpret_cast<const float4*>(D + (ti + r) * 64 + tj);
            v.x += beta * d.x; v.y += beta * d.y; v.z += beta * d.z; v.w += beta * d.w;
        }
        if (diag != 0.0f) {
            int row = ti + r;
            if (row >= tj && row < tj + 4) (&v.x)[row - tj] += diag;
        }
        *reinterpret_cast<float4*>(C + (ti + r) * 64 + tj) = v;
    }
    __syncthreads();
}

// ---------------------------------------------------------------------------
// Batched matrix sqrt via coupled Newton-Schulz. One CTA/matrix, 8 iters.
// ---------------------------------------------------------------------------
__global__ __launch_bounds__(256) void nssqrt_kernel(
    const float* __restrict__ in, float* __restrict__ out)
{
    extern __shared__ float sh[];          // 4 * 4096 floats
    float *Y = sh, *Z = sh + 4096, *W = sh + 8192, *T = sh + 12288;
    __shared__ float red[256];
    __shared__ float s_s;

    const int tid = threadIdx.x;
    const size_t boff = (size_t)blockIdx.x * MATSZ;

    float fa = 0.0f;
    for (int idx = tid; idx < MATSZ; idx += 256) {
        float v = in[boff + idx];
        Y[idx] = v;
        fa += v * v;
        Z[idx] = ((idx >> 6) == (idx & 63)) ? 1.0f : 0.0f;
    }
    red[tid] = fa;
    __syncthreads();
    #pragma unroll
    for (int s = 128; s > 0; s >>= 1) {
        if (tid < s) red[tid] += red[tid + s];
        __syncthreads();
    }
    if (tid == 0) s_s = fmaxf(sqrtf(red[0]) / 1.8f, 1e-20f);
    __syncthreads();
    float inv_s = 1.0f / s_s;
    for (int idx = tid; idx < MATSZ; idx += 256) Y[idx] *= inv_s;
    __syncthreads();

    for (int it = 0; it < 8; ++it) {
        mm64(Z, Y, 1.0f, 0.0f, nullptr, 0.0f, W, tid);      // W = Z@Y
        mm64(Y, W, -0.5f, 1.5f, Y, 0.0f, T, tid);           // T = 1.5Y - 0.5 Y@W
        if (it < 7) {
            mm64(W, Z, -0.5f, 1.5f, Z, 0.0f, Y, tid);       // Znew -> old Y buffer
            float* nY = T; float* nZ = Y; float* nT = Z;
            Y = nY; Z = nZ; T = nT;
        } else {
            Y = T;
        }
    }
    float rs = sqrtf(s_s);
    for (int idx = tid; idx < MATSZ; idx += 256)
        out[boff + idx] = Y[idx] * rs;
}

// ---------------------------------------------------------------------------
// Tiny (1-2 matrix) coupled Newton-Schulz: A^{1/2} and A^{-1/2}. 256 thr
// (measured faster than 1024-thread variant on 1-CTA serial chains).
// ---------------------------------------------------------------------------
__global__ __launch_bounds__(256) void nssmall_kernel(
    const float* __restrict__ inA, float* sqA, float* isqA,
    const float* __restrict__ inB, float* sqB, float* isqB)
{
    extern __shared__ float sh[];          // 4 * 4096 floats
    float *Y = sh, *Z = sh + 4096, *W = sh + 8192, *T = sh + 12288;
    __shared__ float red[256];
    __shared__ float s_s;

    const int tid = threadIdx.x;
    const float* in = blockIdx.x ? inB : inA;
    float* osq  = blockIdx.x ? sqB  : sqA;
    float* oisq = blockIdx.x ? isqB : isqA;

    float fa = 0.0f;
    for (int idx = tid; idx < MATSZ; idx += 256) {
        float v = in[idx];
        Y[idx] = v;
        fa += v * v;
        Z[idx] = ((idx >> 6) == (idx & 63)) ? 1.0f : 0.0f;
    }
    red[tid] = fa;
    __syncthreads();
    #pragma unroll
    for (int s = 128; s > 0; s >>= 1) {
        if (tid < s) red[tid] += red[tid + s];
        __syncthreads();
    }
    if (tid == 0) s_s = fmaxf(sqrtf(red[0]) / 1.8f, 1e-20f);
    __syncthreads();
    float inv_s = 1.0f / s_s;
    for (int idx = tid; idx < MATSZ; idx += 256) Y[idx] *= inv_s;
    __syncthreads();

    for (int it = 0; it < 12; ++it) {
        mm64(Z, Y, 1.0f, 0.0f, nullptr, 0.0f, W, tid);      // W = Z@Y
        mm64(Y, W, -0.5f, 1.5f, Y, 0.0f, T, tid);           // newY -> T
        mm64(W, Z, -0.5f, 1.5f, Z, 0.0f, Y, tid);           // newZ -> old Y
        float* oY = Y; float* oZ = Z;
        Y = T; Z = oY; T = oZ;
    }
    float rs  = sqrtf(s_s);
    float irs = rsqrtf(s_s);
    if (osq)
        for (int idx = tid; idx < MATSZ; idx += 256) osq[idx] = Y[idx] * rs;
    if (oisq)
        for (int idx = tid; idx < MATSZ; idx += 256) oisq[idx] = Z[idx] * irs;
}

// ---------------------------------------------------------------------------
// Matrix exp: scaling-and-squaring + degree-5 Taylor (Horner). 256 threads.
// ---------------------------------------------------------------------------
__global__ __launch_bounds__(256) void expm_kernel(
    const float* __restrict__ in, float* __restrict__ out)
{
    extern __shared__ float sh[];          // 3 * 4096 floats
    float *B = sh, *P = sh + 4096, *Q = sh + 8192;
    __shared__ float red[256];
    __shared__ float sc_s;
    __shared__ int   j_s;

    const int tid = threadIdx.x;
    const size_t boff = (size_t)blockIdx.x * MATSZ;

    float fa = 0.0f;
    for (int idx = tid; idx < MATSZ; idx += 256) {
        float v = in[boff + idx];
        B[idx] = v;
        fa += v * v;
    }
    red[tid] = fa;
    __syncthreads();
    #pragma unroll
    for (int s = 128; s > 0; s >>= 1) {
        if (tid < s) red[tid] += red[tid + s];
        __syncthreads();
    }
    if (tid == 0) {
        float F = sqrtf(red[0]);
        int j = 0;
        while (F > 0.25f && j < 40) { F *= 0.5f; ++j; }
        j_s = j;
        sc_s = exp2f((float)(-j));
    }
    __syncthreads();
    const int j = j_s;
    float sc = sc_s;
    for (int idx = tid; idx < MATSZ; idx += 256) B[idx] *= sc;
    __syncthreads();

    const float c5 = 1.0f / 120.0f, c4 = 1.0f / 24.0f;
    for (int idx = tid; idx < MATSZ; idx += 256) {
        float v = c5 * B[idx];
        if ((idx >> 6) == (idx & 63)) v += c4;
        P[idx] = v;
    }
    __syncthreads();
    const float cs[4] = { 1.0f / 6.0f, 0.5f, 1.0f, 1.0f };
    float *cur = P, *oth = Q;
    #pragma unroll
    for (int k = 0; k < 4; ++k) {
        mm64(cur, B, 1.0f, 0.0f, nullptr, cs[k], oth, tid);
        float* t = cur; cur = oth; oth = t;
    }
    for (int t = 0; t < j; ++t) {
        mm64(cur, cur, 1.0f, 0.0f, nullptr, 0.0f, oth, tid);
        float* tt = cur; cur = oth; oth = tt;
    }
    for (int idx = tid; idx < MATSZ; idx += 256)
        out[boff + idx] = cur[idx];
}

// ---------------------------------------------------------------------------
// One-sided (Hestenes) Jacobi, symmetric 64x64 — half-warp float4 version.
// Reconstruction loads vectorized (stride 68 floats = 272B, 16B-aligned).
// ---------------------------------------------------------------------------
__global__ __launch_bounds__(512) void jac1s512(
    const float* __restrict__ in, float* __restrict__ out1,
    float* __restrict__ out2, int f1, int f2, int useShift, int nsweeps)
{
    __shared__ float  As[64 * 68];
    __shared__ float  norms[64];
    __shared__ float  gv[64], gv2[64];
    __shared__ float  red[512];
    __shared__ float  shift_s;
    __shared__ uchar2 ptab[63 * 32];

    const int tid  = threadIdx.x;
    const int lane = tid & 31;
    const int wid  = tid >> 5;
    const int sl   = lane & 15;
    const int k    = (wid << 1) | (lane >> 4);
    const size_t boff = (size_t)blockIdx.x * MATSZ;

    for (int i = tid; i < 63 * 32; i += 512) {
        int r = i >> 5, kk = i & 31;
        int p, q;
        if (kk == 0) { p = 63; q = r; }
        else {
            int a1 = r + kk;      p = (a1 < 63) ? a1 : a1 - 63;
            int a2 = r + 63 - kk; q = (a2 < 63) ? a2 : a2 - 63;
        }
        ptab[i] = make_uchar2((unsigned char)p, (unsigned char)q);
    }

    float fa = 0.0f;
    for (int idx = tid; idx < MATSZ; idx += 512) {
        int c = idx >> 6, r = idx & 63;
        float v = in[boff + idx];
        As[c * 68 + r] = v;
        fa += v * v;
    }
    red[tid] = fa;
    __syncthreads();
    if (useShift) {
        #pragma unroll
        for (int s = 256; s > 0; s >>= 1) {
            if (tid < s) red[tid] += red[tid + s];
            __syncthreads();
        }
        if (tid == 0) shift_s = sqrtf(red[0]) * 1.000001f + 1e-20f;
        __syncthreads();
        if (tid < 64) As[tid * 68 + tid] += shift_s;
    } else {
        if (tid == 0) shift_s = 0.0f;
    }
    __syncthreads();

    for (int j = k; j < 64; j += 32) {
        float4 a = *reinterpret_cast<const float4*>(As + j * 68 + sl * 4);
        float s = a.x * a.x + a.y * a.y + a.z * a.z + a.w * a.w;
        #pragma unroll
        for (int o = 8; o; o >>= 1) s += __shfl_xor_sync(0xFFFFFFFFu, s, o);
        if (sl == 0) norms[j] = s;
    }
    __syncthreads();

    for (int sw = 0; sw < nsweeps; ++sw) {
        for (int r = 0; r < 63; ++r) {
            uchar2 pq = ptab[(r << 5) | k];
            const int p = pq.x, q = pq.y;
            float4* cp = reinterpret_cast<float4*>(As + p * 68);
            float4* cq = reinterpret_cast<float4*>(As + q * 68);
            float4 ap = cp[sl];
            float4 aq = cq[sl];
            float g = ap.x * aq.x + ap.y * aq.y + ap.z * aq.z + ap.w * aq.w;
            #pragma unroll
            for (int o = 8; o; o >>= 1) g += __shfl_xor_sync(0xFFFFFFFFu, g, o);
            if (g != 0.0f) {
                float al = norms[p], be = norms[q];
                float tau = (be - al) / (2.0f * g);
                float t = 1.0f / (fabsf(tau) + sqrtf(1.0f + tau * tau));
                if (tau < 0.0f) t = -t;
                float c = rsqrtf(1.0f + t * t);
                float s = t * c;
                float4 np, nq;
                np.x = c * ap.x - s * aq.x;  nq.x = s * ap.x + c * aq.x;
                np.y = c * ap.y - s * aq.y;  nq.y = s * ap.y + c * aq.y;
                np.z = c * ap.z - s * aq.z;  nq.z = s * ap.z + c * aq.z;
                np.w = c * ap.w - s * aq.w;  nq.w = s * ap.w + c * aq.w;
                cp[sl] = np;
                cq[sl] = nq;
                if (sl == 0) {
                    float cc = c * c, ss = s * s, cs2 = 2.0f * c * s;
                    norms[p] = cc * al - cs2 * g + ss * be;
                    norms[q] = ss * al + cs2 * g + cc * be;
                }
            }
            __syncthreads();
        }
    }

    for (int j = k; j < 64; j += 32) {
        float4 a = *reinterpret_cast<const float4*>(As + j * 68 + sl * 4);
        float s = a.x * a.x + a.y * a.y + a.z * a.z + a.w * a.w;
        #pragma unroll
        for (int o = 8; o; o >>= 1) s += __shfl_xor_sync(0xFFFFFFFFu, s, o);
        if (sl == 0) {
            s = fmaxf(s, 1e-30f);
            float lam = sqrtf(s) - shift_s;
            gv[j] = apply_fn(f1, lam) / s;
            if (f2 != F_NONE) gv2[j] = apply_fn(f2, lam) / s;
        }
    }
    __syncthreads();

    const int ti = (tid >> 4) * 2;
    const int tj = (tid & 15) << 2;
    {
        float acc[2][4] = {};
        #pragma unroll 4
        for (int kk = 0; kk < 64; ++kk) {
            const float* ck = As + kk * 68;
            float gk = gv[kk];
            float2 ar = *reinterpret_cast<const float2*>(ck + ti);
            float4 b  = *reinterpret_cast<const float4*>(ck + tj);
            float a0 = gk * ar.x, a1 = gk * ar.y;
            acc[0][0] += a0 * b.x; acc[0][1] += a0 * b.y; acc[0][2] += a0 * b.z; acc[0][3] += a0 * b.w;
            acc[1][0] += a1 * b.x; acc[1][1] += a1 * b.y; acc[1][2] += a1 * b.z; acc[1][3] += a1 * b.w;
        }
        #pragma unroll
        for (int r = 0; r < 2; ++r) {
            float4 v = make_float4(acc[r][0], acc[r][1], acc[r][2], acc[r][3]);
            *reinterpret_cast<float4*>(out1 + boff + (size_t)(ti + r) * 64 + tj) = v;
        }
    }
    if (f2 != F_NONE) {
        float acc[2][4] = {};
        #pragma unroll 4
        for (int kk = 0; kk < 64; ++kk) {
            const float* ck = As + kk * 68;
            float gk = gv2[kk];
            float2 ar = *reinterpret_cast<const float2*>(ck + ti);
            float4 b  = *reinterpret_cast<const float4*>(ck + tj);
            float a0 = gk * ar.x, a1 = gk * ar.y;
            acc[0][0] += a0 * b.x; acc[0][1] += a0 * b.y; acc[0][2] += a0 * b.z; acc[0][3] += a0 * b.w;
            acc[1][0] += a1 * b.x; acc[1][1] += a1 * b.y; acc[1][2] += a1 * b.z; acc[1][3] += a1 * b.w;
        }
        #pragma unroll
        for (int r = 0; r < 2; ++r) {
            float4 v = make_float4(acc[r][0], acc[r][1], acc[r][2], acc[r][3]);
            *reinterpret_cast<float4*>(out2 + boff + (size_t)(ti + r) * 64 + tj) = v;
        }
    }
}

// out_b = scale * L @ X_b @ R  (L, R broadcast, both plain row-major)
__global__ __launch_bounds__(256) void cong_kernel(
    const float* __restrict__ Lm, const float* __restrict__ Xb,
    const float* __restrict__ Rm, float* __restrict__ out, int useScale)
{
    __shared__ float Ls[MATSZ], Rs[MATSZ], Xs[MATSZ];
    const int tid = threadIdx.x;
    const size_t boff = (size_t)blockIdx.x * MATSZ;
    for (int i = tid; i < MATSZ; i += 256) {
        Ls[i] = Lm[i]; Rs[i] = Rm[i]; Xs[i] = Xb[boff + i];
    }
    __syncthreads();

    const int ti = (tid >> 4) << 2, tj = (tid & 15) << 2;
    float acc[4][4] = {};
    tile_mm_nn(Ls, Xs, acc, ti, tj);          // T = L @ X
    __syncthreads();
    #pragma unroll
    for (int r = 0; r < 4; ++r)
        #pragma unroll
        for (int c = 0; c < 4; ++c) Xs[(ti + r) * 64 + tj + c] = acc[r][c];
    __syncthreads();

    float sc = useScale ? g_scal[0] : 1.0f;
    float acc2[4][4] = {};
    tile_mm_nn(Xs, Rs, acc2, ti, tj);         // out = T @ R
    #pragma unroll
    for (int r = 0; r < 4; ++r) {
        float4 v = make_float4(acc2[r][0] * sc, acc2[r][1] * sc,
                               acc2[r][2] * sc, acc2[r][3] * sc);
        *reinterpret_cast<float4*>(out + boff + (size_t)(ti + r) * 64 + tj) = v;
    }
}

// out_b = A_b @ A_b  (batched matrix square; single shared operand)
__global__ __launch_bounds__(256) void gemmsq_kernel(
    const float* __restrict__ A, float* __restrict__ out)
{
    __shared__ float As_[MATSZ];
    const int tid = threadIdx.x;
    const size_t boff = (size_t)blockIdx.x * MATSZ;
    for (int i = tid; i < MATSZ; i += 256) As_[i] = A[boff + i];
    __syncthreads();
    const int ti = (tid >> 4) << 2, tj = (tid & 15) << 2;
    float acc[4][4] = {};
    tile_mm_nn(As_, As_, acc, ti, tj);
    #pragma unroll
    for (int r = 0; r < 4; ++r) {
        float4 v = make_float4(acc[r][0], acc[r][1], acc[r][2], acc[r][3]);
        *reinterpret_cast<float4*>(out + boff + (size_t)(ti + r) * 64 + tj) = v;
    }
}

// single 64x64 gemm: C = op(A) @ B
__global__ __launch_bounds__(256) void gemm1_kernel(
    const float* __restrict__ A, const float* __restrict__ B,
    float* __restrict__ C, int transA)
{
    __shared__ float As_[MATSZ], Bs_[MATSZ];
    const int tid = threadIdx.x;
    for (int i = tid; i < MATSZ; i += 256) { As_[i] = A[i]; Bs_[i] = B[i]; }
    __syncthreads();
    const int ti = (tid >> 4) << 2, tj = (tid & 15) << 2;
    float acc[4][4] = {};
    if (transA) tile_mm_tn(As_, Bs_, acc, ti, tj);
    else        tile_mm_nn(As_, Bs_, acc, ti, tj);
    #pragma unroll
    for (int r = 0; r < 4; ++r) {
        float4 v = make_float4(acc[r][0], acc[r][1], acc[r][2], acc[r][3]);
        *reinterpret_cast<float4*>(C + (size_t)(ti + r) * 64 + tj) = v;
    }
}

// two-phase batch mean: phase 1, 512 blocks (32 bchunks x 16 eblocks)
__global__ __launch_bounds__(256) void mean1_kernel(const float* __restrict__ in)
{
    const int bc = blockIdx.x >> 4;
    const int e  = ((blockIdx.x & 15) << 8) + threadIdx.x;
    const float* base = in + (size_t)bc * 128 * MATSZ + e;
    double a0 = 0, a1 = 0, a2 = 0, a3 = 0;
    for (int b = 0; b < 128; b += 4) {
        a0 += (double)base[(size_t)(b + 0) * MATSZ];
        a1 += (double)base[(size_t)(b + 1) * MATSZ];
        a2 += (double)base[(size_t)(b + 2) * MATSZ];
        a3 += (double)base[(size_t)(b + 3) * MATSZ];
    }
    g_meanpart[bc * MATSZ + e] = (a0 + a1) + (a2 + a3);
}

// phase 2: 16 blocks x 256 threads, deterministic order over 32 chunks
__global__ __launch_bounds__(256) void mean2_kernel(float* __restrict__ out)
{
    const int e = (blockIdx.x << 8) + threadIdx.x;
    double a = 0;
    #pragma unroll
    for (int c = 0; c < 32; ++c) a += g_meanpart[c * MATSZ + e];
    out[e] = (float)(a * (1.0 / (double)NB));
}

// deterministic two-pass sum of squares (float4 loads)
__global__ __launch_bounds__(256) void sumsq_kernel(const float* __restrict__ in)
{
    __shared__ double sh[256];
    const int tid = threadIdx.x;
    const size_t base = (size_t)blockIdx.x * 65536;
    double a = 0;
    for (int i = tid * 4; i < 65536; i += 1024) {
        float4 v = *reinterpret_cast<const float4*>(in + base + i);
        a += (double)v.x * v.x + (double)v.y * v.y
           + (double)v.z * v.z + (double)v.w * v.w;
    }
    sh[tid] = a;
    __syncthreads();
    for (int s = 128; s > 0; s >>= 1) {
        if (tid < s) sh[tid] += sh[tid + s];
        __syncthreads();
    }
    if (tid == 0) g_part[blockIdx.x] = sh[0];
}

__global__ void finalize_kernel(const float* __restrict__ shift)
{
    __shared__ double sh[256];
    const int tid = threadIdx.x;
    sh[tid] = g_part[tid];
    __syncthreads();
    for (int s = 128; s > 0; s >>= 1) {
        if (tid < s) sh[tid] += sh[tid + s];
        __syncthreads();
    }
    if (tid == 0) {
        double var = sh[0] / (double)NB;
        g_scal[0] = shift[0] / (float)sqrt(var + 1e-5);
    }
}

extern "C" void kernel_launch(void* const* d_in, const int* in_sizes, int n_in,
                              void* d_out, int out_size)
{
    const float* X     = (const float*)d_in[0];
    const float* W     = (const float*)d_in[1];
    const float* M     = (const float*)d_in[2];
    const float* shift = (const float*)d_in[3];
    float* out = (float*)d_out;

    float *bufA, *bufB, *bufC, *bufD, *sm;
    cudaGetSymbolAddress((void**)&bufA, g_bufA);
    cudaGetSymbolAddress((void**)&bufB, g_bufB);
    cudaGetSymbolAddress((void**)&bufC, g_bufC);
    cudaGetSymbolAddress((void**)&bufD, g_bufD);
    cudaGetSymbolAddress((void**)&sm,   g_small);

    cudaFuncSetAttribute(nssqrt_kernel,  cudaFuncAttributeMaxDynamicSharedMemorySize, 65536);
    cudaFuncSetAttribute(nssmall_kernel, cudaFuncAttributeMaxDynamicSharedMemorySize, 65536);
    cudaFuncSetAttribute(expm_kernel,    cudaFuncAttributeMaxDynamicSharedMemorySize, 49152);

    // fork-join resources (created once; captured graph identical every call)
    static cudaStream_t s2 = [] {
        cudaStream_t s; cudaStreamCreateWithFlags(&s, cudaStreamNonBlocking); return s;
    }();
    static cudaEvent_t evFork = [] {
        cudaEvent_t e; cudaEventCreateWithFlags(&e, cudaEventDisableTiming); return e;
    }();
    static cudaEvent_t evMnh = [] {
        cudaEvent_t e; cudaEventCreateWithFlags(&e, cudaEventDisableTiming); return e;
    }();
    static cudaEvent_t evPrep = [] {
        cudaEvent_t e; cudaEventCreateWithFlags(&e, cudaEventDisableTiming); return e;
    }();

    #define SLOT(i) (sm + (i) * MATSZ)
    // slots: 0 Mh, 1 Mnh, 2 Wh, 3 prep-tmp, 4 Wc, 5 Wch, 6 Wcnh, 7 P,
    //        8 Q, 10 G0, 11 G0h, 12 G0nh, 13 Tm, 14 expTm, 15 G, 16 mnh,
    //        17 Pt, 18 Qt, 19 mid-tmp

    // ---- fork: parameter prep on s2, concurrent with nssqrt on stream0 ----
    cudaEventRecord(evFork, 0);
    cudaStreamWaitEvent(s2, evFork, 0);
    nssmall_kernel<<<2, 256, 65536, s2>>>(M, SLOT(0), SLOT(1),   // Mh, Mnh
                                          W, SLOT(2), nullptr);  // Wh
    cudaEventRecord(evMnh, s2);
    gemm1_kernel<<<1, 256, 0, s2>>>(SLOT(1), SLOT(2), SLOT(3), 0);   // Mnh Wh
    gemm1_kernel<<<1, 256, 0, s2>>>(SLOT(3), SLOT(1), SLOT(4), 0);   // Wc
    nssmall_kernel<<<1, 256, 65536, s2>>>(SLOT(4), SLOT(5), SLOT(6),
                                          SLOT(4), nullptr, nullptr); // Wch, Wcnh
    gemm1_kernel<<<1, 256, 0, s2>>>(SLOT(6), SLOT(2), SLOT(7), 0);   // P  = Wcnh Wh
    gemm1_kernel<<<1, 256, 0, s2>>>(SLOT(2), SLOT(6), SLOT(17), 0);  // Pt = Wh Wcnh
    gemm1_kernel<<<1, 256, 0, s2>>>(SLOT(0), SLOT(5), SLOT(8), 0);   // Q  = Mh Wch
    gemm1_kernel<<<1, 256, 0, s2>>>(SLOT(5), SLOT(0), SLOT(18), 0);  // Qt = Wch Mh
    cudaEventRecord(evPrep, s2);

    // ---- stream0: Xp = X^{1/2}; join Mnh; Xc = Mnh Xp Mnh ----
    nssqrt_kernel<<<NB, 256, 65536>>>(X, bufA);
    cudaStreamWaitEvent(0, evMnh, 0);
    cong_kernel<<<NB, 256>>>(SLOT(1), bufA, SLOT(1), bufB, 0);       // Xc

    // bary_geom: 1 Karcher step from arithmetic mean
    mean1_kernel<<<512, 256>>>(bufB);
    mean2_kernel<<<16, 256>>>(SLOT(10));                             // G0
    nssmall_kernel<<<1, 256, 65536>>>(SLOT(10), SLOT(11), SLOT(12),
                                      SLOT(10), nullptr, nullptr);   // G0h, G0nh
    cong_kernel<<<NB, 256>>>(SLOT(12), bufB, SLOT(12), bufC, 0);
    jac1s512<<<NB, 512>>>(bufC, bufA, bufA, F_LOG, F_NONE, 0, 6);
    mean1_kernel<<<512, 256>>>(bufA);
    mean2_kernel<<<16, 256>>>(SLOT(13));                             // Tm
    expm_kernel<<<1, 256, 49152>>>(SLOT(13), SLOT(14));              // expTm
    gemm1_kernel<<<1, 256>>>(SLOT(11), SLOT(14), SLOT(19), 0);
    gemm1_kernel<<<1, 256>>>(SLOT(19), SLOT(11), SLOT(15), 0);       // G
    nssmall_kernel<<<1, 256, 65536>>>(SLOT(15), nullptr, SLOT(16),
                                      SLOT(15), nullptr, nullptr);   // mnh

    // tangent at I, variance, scale
    cong_kernel<<<NB, 256>>>(SLOT(16), bufB, SLOT(16), bufC, 0);
    jac1s512<<<NB, 512>>>(bufC, bufD, bufD, F_LOG, F_NONE, 0, 6);    // T0
    sumsq_kernel<<<256, 256>>>(bufD);
    finalize_kernel<<<1, 256>>>(shift);

    // join full prep; arg = factor * P T0 P^T ; E = exp(arg)
    cudaStreamWaitEvent(0, evPrep, 0);
    cong_kernel<<<NB, 256>>>(SLOT(7), bufD, SLOT(17), bufC, 1);      // P T0 Pt
    expm_kernel<<<NB, 256, 49152>>>(bufC, bufA);                     // E

    // out = (Q E Qt)^2   [= Q E (QtQ) E Qt]
    cong_kernel<<<NB, 256>>>(SLOT(8), bufA, SLOT(18), bufC, 0);      // Q E Qt
    gemmsq_kernel<<<NB, 256>>>(bufC, out);
    #undef SLOT
}

// round 14
// speedup vs baseline: 2.2487x; 1.0204x over previous
#include <cuda_runtime.h>
#include <math.h>

#define NN 64
#define MATSZ 4096
#define NB 4096

// device-global scratch (no runtime allocation allowed)
__device__ float  g_bufA[(size_t)NB * MATSZ];
__device__ float  g_bufB[(size_t)NB * MATSZ];
__device__ float  g_bufC[(size_t)NB * MATSZ];
__device__ float  g_bufD[(size_t)NB * MATSZ];
__device__ float  g_small[20 * MATSZ];
__device__ double g_meanpart[32 * MATSZ];
__device__ float  g_fro[NB];
__device__ float  g_scal[4];

// Blackwell packed fp32x2 (FFMA2) — PTX-only, ptxas never auto-fuses.
#define PACKF2(d, lo, hi) asm("mov.b64 %0, {%1, %2};" : "=l"(d) : "f"(lo), "f"(hi))
#define UNPACKF2(lo, hi, d) asm("mov.b64 {%0, %1}, %2;" : "=f"(lo), "=f"(hi) : "l"(d))
#define FMAF2(acc, a, b) asm("fma.rn.f32x2 %0, %1, %2, %0;" : "+l"(acc) : "l"(a), "l"(b))

__device__ __forceinline__ float f4c(const float4& v, int k) {
    return k == 0 ? v.x : k == 1 ? v.y : k == 2 ? v.z : v.w;
}

// ---------------------------------------------------------------------------
// 256-thread 4x4-tile inner product with packed f32x2 accumulation.
// ---------------------------------------------------------------------------
__device__ __forceinline__ void tile_mm_nn(const float* __restrict__ A,
                                           const float* __restrict__ B,
                                           float acc[4][4], int ti, int tj)
{
    unsigned long long p01[4], p23[4];
    #pragma unroll
    for (int r = 0; r < 4; ++r) {
        PACKF2(p01[r], acc[r][0], acc[r][1]);
        PACKF2(p23[r], acc[r][2], acc[r][3]);
    }
    #pragma unroll 4
    for (int k4 = 0; k4 < 64; k4 += 4) {
        float4 av[4];
        #pragma unroll
        for (int r = 0; r < 4; ++r)
            av[r] = *reinterpret_cast<const float4*>(A + (ti + r) * 64 + k4);
        #pragma unroll
        for (int kk = 0; kk < 4; ++kk) {
            float4 b = *reinterpret_cast<const float4*>(B + (k4 + kk) * 64 + tj);
            unsigned long long b01, b23;
            PACKF2(b01, b.x, b.y);
            PACKF2(b23, b.z, b.w);
            #pragma unroll
            for (int r = 0; r < 4; ++r) {
                float a = f4c(av[r], kk);
                unsigned long long aa;
                PACKF2(aa, a, a);
                FMAF2(p01[r], aa, b01);
                FMAF2(p23[r], aa, b23);
            }
        }
    }
    #pragma unroll
    for (int r = 0; r < 4; ++r) {
        UNPACKF2(acc[r][0], acc[r][1], p01[r]);
        UNPACKF2(acc[r][2], acc[r][3], p23[r]);
    }
}

// scalar transposed-A tile (tiny gemm1 only)
__device__ __forceinline__ void tile_mm_tn(const float* __restrict__ A,
                                           const float* __restrict__ B,
                                           float acc[4][4], int ti, int tj)
{
    #pragma unroll 4
    for (int k = 0; k < 64; ++k) {
        float a[4];
        #pragma unroll
        for (int r = 0; r < 4; ++r) a[r] = A[k * 64 + ti + r];
        float4 b = *reinterpret_cast<const float4*>(B + k * 64 + tj);
        #pragma unroll
        for (int r = 0; r < 4; ++r) {
            acc[r][0] += a[r] * b.x; acc[r][1] += a[r] * b.y;
            acc[r][2] += a[r] * b.z; acc[r][3] += a[r] * b.w;
        }
    }
}

// ---------------------------------------------------------------------------
// In-shared 64x64 GEMM: C = alpha*(A@B) + beta*D + diag*I. 256 threads.
// ---------------------------------------------------------------------------
__device__ __forceinline__ void mm64(const float* __restrict__ A,
                                     const float* __restrict__ B,
                                     float alpha, float beta,
                                     const float* __restrict__ D,
                                     float diag, float* __restrict__ C, int tid)
{
    const int ti = (tid >> 4) << 2, tj = (tid & 15) << 2;
    float acc[4][4] = {};
    tile_mm_nn(A, B, acc, ti, tj);
    __syncthreads();
    #pragma unroll
    for (int r = 0; r < 4; ++r) {
        float4 v;
        v.x = alpha * acc[r][0]; v.y = alpha * acc[r][1];
        v.z = alpha * acc[r][2]; v.w = alpha * acc[r][3];
        if (beta != 0.0f) {
            float4 d = *reinterpret_cast<const float4*>(D + (ti + r) * 64 + tj);
            v.x += beta * d.x; v.y += beta * d.y; v.z += beta * d.z; v.w += beta * d.w;
        }
        if (diag != 0.0f) {
            int row = ti + r;
            if (row >= tj && row < tj + 4) (&v.x)[row - tj] += diag;
        }
        *reinterpret_cast<float4*>(C + (ti + r) * 64 + tj) = v;
    }
    __syncthreads();
}

// ---------------------------------------------------------------------------
// Batched matrix sqrt via coupled Newton-Schulz. One CTA/matrix, 8 iters.
// ---------------------------------------------------------------------------
__global__ __launch_bounds__(256) void nssqrt_kernel(
    const float* __restrict__ in, float* __restrict__ out)
{
    extern __shared__ float sh[];          // 4 * 4096 floats
    float *Y = sh, *Z = sh + 4096, *W = sh + 8192, *T = sh + 12288;
    __shared__ float red[256];
    __shared__ float s_s;

    const int tid = threadIdx.x;
    const size_t boff = (size_t)blockIdx.x * MATSZ;

    float fa = 0.0f;
    for (int idx = tid; idx < MATSZ; idx += 256) {
        float v = in[boff + idx];
        Y[idx] = v;
        fa += v * v;
        Z[idx] = ((idx >> 6) == (idx & 63)) ? 1.0f : 0.0f;
    }
    red[tid] = fa;
    __syncthreads();
    #pragma unroll
    for (int s = 128; s > 0; s >>= 1) {
        if (tid < s) red[tid] += red[tid + s];
        __syncthreads();
    }
    if (tid == 0) s_s = fmaxf(sqrtf(red[0]) / 1.8f, 1e-20f);
    __syncthreads();
    float inv_s = 1.0f / s_s;
    for (int idx = tid; idx < MATSZ; idx += 256) Y[idx] *= inv_s;
    __syncthreads();

    for (int it = 0; it < 8; ++it) {
        mm64(Z, Y, 1.0f, 0.0f, nullptr, 0.0f, W, tid);      // W = Z@Y
        mm64(Y, W, -0.5f, 1.5f, Y, 0.0f, T, tid);           // T = 1.5Y - 0.5 Y@W
        if (it < 7) {
            mm64(W, Z, -0.5f, 1.5f, Z, 0.0f, Y, tid);       // Znew -> old Y buffer
            float* nY = T; float* nZ = Y; float* nT = Z;
            Y = nY; Z = nZ; T = nT;
        } else {
            Y = T;
        }
    }
    float rs = sqrtf(s_s);
    for (int idx = tid; idx < MATSZ; idx += 256)
        out[boff + idx] = Y[idx] * rs;
}

// ---------------------------------------------------------------------------
// Tiny (1-2 matrix) coupled Newton-Schulz: A^{1/2} and A^{-1/2}. 256 thr.
// ---------------------------------------------------------------------------
__global__ __launch_bounds__(256) void nssmall_kernel(
    const float* __restrict__ inA, float* sqA, float* isqA,
    const float* __restrict__ inB, float* sqB, float* isqB)
{
    extern __shared__ float sh[];          // 4 * 4096 floats
    float *Y = sh, *Z = sh + 4096, *W = sh + 8192, *T = sh + 12288;
    __shared__ float red[256];
    __shared__ float s_s;

    const int tid = threadIdx.x;
    const float* in = blockIdx.x ? inB : inA;
    float* osq  = blockIdx.x ? sqB  : sqA;
    float* oisq = blockIdx.x ? isqB : isqA;

    float fa = 0.0f;
    for (int idx = tid; idx < MATSZ; idx += 256) {
        float v = in[idx];
        Y[idx] = v;
        fa += v * v;
        Z[idx] = ((idx >> 6) == (idx & 63)) ? 1.0f : 0.0f;
    }
    red[tid] = fa;
    __syncthreads();
    #pragma unroll
    for (int s = 128; s > 0; s >>= 1) {
        if (tid < s) red[tid] += red[tid + s];
        __syncthreads();
    }
    if (tid == 0) s_s = fmaxf(sqrtf(red[0]) / 1.8f, 1e-20f);
    __syncthreads();
    float inv_s = 1.0f / s_s;
    for (int idx = tid; idx < MATSZ; idx += 256) Y[idx] *= inv_s;
    __syncthreads();

    for (int it = 0; it < 12; ++it) {
        mm64(Z, Y, 1.0f, 0.0f, nullptr, 0.0f, W, tid);      // W = Z@Y
        mm64(Y, W, -0.5f, 1.5f, Y, 0.0f, T, tid);           // newY -> T
        mm64(W, Z, -0.5f, 1.5f, Z, 0.0f, Y, tid);           // newZ -> old Y
        float* oY = Y; float* oZ = Z;
        Y = T; Z = oY; T = oZ;
    }
    float rs  = sqrtf(s_s);
    float irs = rsqrtf(s_s);
    if (osq)
        for (int idx = tid; idx < MATSZ; idx += 256) osq[idx] = Y[idx] * rs;
    if (oisq)
        for (int idx = tid; idx < MATSZ; idx += 256) oisq[idx] = Z[idx] * irs;
}

// ---------------------------------------------------------------------------
// expm core on shared buffer B (degree-5 Taylor + squaring). P, Q scratch.
// ---------------------------------------------------------------------------
__device__ __forceinline__ void expm_core(float* B, float* P, float* Q,
                                          float* __restrict__ out, size_t boff,
                                          int tid, float fro2)
{
    __shared__ float sc_s;
    __shared__ int   j_s;
    if (tid == 0) {
        float F = sqrtf(fro2);
        int j = 0;
        while (F > 0.25f && j < 40) { F *= 0.5f; ++j; }
        j_s = j;
        sc_s = exp2f((float)(-j));
    }
    __syncthreads();
    const int j = j_s;
    float sc = sc_s;
    for (int idx = tid; idx < MATSZ; idx += 256) B[idx] *= sc;
    __syncthreads();

    const float c5 = 1.0f / 120.0f, c4 = 1.0f / 24.0f;
    for (int idx = tid; idx < MATSZ; idx += 256) {
        float v = c5 * B[idx];
        if ((idx >> 6) == (idx & 63)) v += c4;
        P[idx] = v;
    }
    __syncthreads();
    const float cs[4] = { 1.0f / 6.0f, 0.5f, 1.0f, 1.0f };
    float *cur = P, *oth = Q;
    #pragma unroll
    for (int k = 0; k < 4; ++k) {
        mm64(cur, B, 1.0f, 0.0f, nullptr, cs[k], oth, tid);
        float* t = cur; cur = oth; oth = t;
    }
    for (int t = 0; t < j; ++t) {
        mm64(cur, cur, 1.0f, 0.0f, nullptr, 0.0f, oth, tid);
        float* tt = cur; cur = oth; oth = tt;
    }
    for (int idx = tid; idx < MATSZ; idx += 256)
        out[boff + idx] = cur[idx];
}

// plain expm (tiny serialized use): out = exp(in_b)
__global__ __launch_bounds__(256) void expm_kernel(
    const float* __restrict__ in, float* __restrict__ out)
{
    extern __shared__ float sh[];          // 3 * 4096 floats
    float *B = sh, *P = sh + 4096, *Q = sh + 8192;
    __shared__ float red[256];
    const int tid = threadIdx.x;
    const size_t boff = (size_t)blockIdx.x * MATSZ;

    float fa = 0.0f;
    for (int idx = tid; idx < MATSZ; idx += 256) {
        float v = in[boff + idx];
        B[idx] = v;
        fa += v * v;
    }
    red[tid] = fa;
    __syncthreads();
    #pragma unroll
    for (int s = 128; s > 0; s >>= 1) {
        if (tid < s) red[tid] += red[tid + s];
        __syncthreads();
    }
    __shared__ float fro2_s;
    if (tid == 0) fro2_s = red[0];
    __syncthreads();
    expm_core(B, P, Q, out, boff, tid, fro2_s);
}

// fused: out_b = exp( g_scal[0] * Pm @ T0_b @ Ptm )   (64KB dynamic smem)
__global__ __launch_bounds__(256) void expm_fused_kernel(
    const float* __restrict__ Pm, const float* __restrict__ T0,
    const float* __restrict__ Ptm, float* __restrict__ out)
{
    extern __shared__ float sh[];          // 4 * 4096 floats
    float *b0 = sh, *b1 = sh + 4096, *b2 = sh + 8192, *b3 = sh + 12288;
    __shared__ float red[256];
    const int tid = threadIdx.x;
    const size_t boff = (size_t)blockIdx.x * MATSZ;
    const float fac = g_scal[0];

    for (int i = tid; i < MATSZ; i += 256) {
        b0[i] = Pm[i];
        b1[i] = T0[boff + i];
        b2[i] = Ptm[i];
    }
    __syncthreads();
    mm64(b0, b1, 1.0f, 0.0f, nullptr, 0.0f, b3, tid);       // T1 = P @ T0
    mm64(b3, b2, fac,  0.0f, nullptr, 0.0f, b1, tid);       // arg -> b1

    float fa = 0.0f;
    for (int i = tid; i < MATSZ; i += 256) { float v = b1[i]; fa += v * v; }
    red[tid] = fa;
    __syncthreads();
    #pragma unroll
    for (int s = 128; s > 0; s >>= 1) {
        if (tid < s) red[tid] += red[tid + s];
        __syncthreads();
    }
    __shared__ float fro2_s;
    if (tid == 0) fro2_s = red[0];
    __syncthreads();
    expm_core(b1, b0, b2, out, boff, tid, fro2_s);
}

// ---------------------------------------------------------------------------
// One-sided (Hestenes) Jacobi LOG, symmetric 64x64 — half-warp float4.
// out = V log(L) V^T; optional fro_out[blockIdx] = sum_j log(lam_j)^2.
// ---------------------------------------------------------------------------
__global__ __launch_bounds__(512) void jac1s512(
    const float* __restrict__ in, float* __restrict__ out1,
    float* __restrict__ fro_out, int nsweeps)
{
    __shared__ float  As[64 * 68];
    __shared__ float  norms[64];
    __shared__ float  gv[64], ll2[64];
    __shared__ uchar2 ptab[63 * 32];

    const int tid  = threadIdx.x;
    const int lane = tid & 31;
    const int wid  = tid >> 5;
    const int sl   = lane & 15;
    const int k    = (wid << 1) | (lane >> 4);
    const size_t boff = (size_t)blockIdx.x * MATSZ;

    for (int i = tid; i < 63 * 32; i += 512) {
        int r = i >> 5, kk = i & 31;
        int p, q;
        if (kk == 0) { p = 63; q = r; }
        else {
            int a1 = r + kk;      p = (a1 < 63) ? a1 : a1 - 63;
            int a2 = r + 63 - kk; q = (a2 < 63) ? a2 : a2 - 63;
        }
        ptab[i] = make_uchar2((unsigned char)p, (unsigned char)q);
    }

    for (int idx = tid; idx < MATSZ; idx += 512) {
        int c = idx >> 6, r = idx & 63;
        As[c * 68 + r] = in[boff + idx];
    }
    __syncthreads();

    for (int j = k; j < 64; j += 32) {
        float4 a = *reinterpret_cast<const float4*>(As + j * 68 + sl * 4);
        float s = a.x * a.x + a.y * a.y + a.z * a.z + a.w * a.w;
        #pragma unroll
        for (int o = 8; o; o >>= 1) s += __shfl_xor_sync(0xFFFFFFFFu, s, o);
        if (sl == 0) norms[j] = s;
    }
    __syncthreads();

    for (int sw = 0; sw < nsweeps; ++sw) {
        for (int r = 0; r < 63; ++r) {
            uchar2 pq = ptab[(r << 5) | k];
            const int p = pq.x, q = pq.y;
            float4* cp = reinterpret_cast<float4*>(As + p * 68);
            float4* cq = reinterpret_cast<float4*>(As + q * 68);
            float4 ap = cp[sl];
            float4 aq = cq[sl];
            float g = ap.x * aq.x + ap.y * aq.y + ap.z * aq.z + ap.w * aq.w;
            #pragma unroll
            for (int o = 8; o; o >>= 1) g += __shfl_xor_sync(0xFFFFFFFFu, g, o);
            if (g != 0.0f) {
                float al = norms[p], be = norms[q];
                float tau = (be - al) / (2.0f * g);
                float t = 1.0f / (fabsf(tau) + sqrtf(1.0f + tau * tau));
                if (tau < 0.0f) t = -t;
                float c = rsqrtf(1.0f + t * t);
                float s = t * c;
                float4 np, nq;
                np.x = c * ap.x - s * aq.x;  nq.x = s * ap.x + c * aq.x;
                np.y = c * ap.y - s * aq.y;  nq.y = s * ap.y + c * aq.y;
                np.z = c * ap.z - s * aq.z;  nq.z = s * ap.z + c * aq.z;
                np.w = c * ap.w - s * aq.w;  nq.w = s * ap.w + c * aq.w;
                cp[sl] = np;
                cq[sl] = nq;
                if (sl == 0) {
                    float cc = c * c, ss = s * s, cs2 = 2.0f * c * s;
                    norms[p] = cc * al - cs2 * g + ss * be;
                    norms[q] = ss * al + cs2 * g + cc * be;
                }
            }
            __syncthreads();
        }
    }

    for (int j = k; j < 64; j += 32) {
        float4 a = *reinterpret_cast<const float4*>(As + j * 68 + sl * 4);
        float s = a.x * a.x + a.y * a.y + a.z * a.z + a.w * a.w;
        #pragma unroll
        for (int o = 8; o; o >>= 1) s += __shfl_xor_sync(0xFFFFFFFFu, s, o);
        if (sl == 0) {
            s = fmaxf(s, 1e-30f);
            float lam = sqrtf(s);
            float lg = logf(lam);
            gv[j]  = lg / s;
            ll2[j] = lg * lg;
        }
    }
    __syncthreads();

    const int ti = (tid >> 4) * 2;
    const int tj = (tid & 15) << 2;
    float acc[2][4] = {};
    #pragma unroll 4
    for (int kk = 0; kk < 64; ++kk) {
        const float* ck = As + kk * 68;
        float gk = gv[kk];
        float2 ar = *reinterpret_cast<const float2*>(ck + ti);
        float4 b  = *reinterpret_cast<const float4*>(ck + tj);
        float a0 = gk * ar.x, a1 = gk * ar.y;
        acc[0][0] += a0 * b.x; acc[0][1] += a0 * b.y; acc[0][2] += a0 * b.z; acc[0][3] += a0 * b.w;
        acc[1][0] += a1 * b.x; acc[1][1] += a1 * b.y; acc[1][2] += a1 * b.z; acc[1][3] += a1 * b.w;
    }
    #pragma unroll
    for (int r = 0; r < 2; ++r) {
        float4 v = make_float4(acc[r][0], acc[r][1], acc[r][2], acc[r][3]);
        *reinterpret_cast<float4*>(out1 + boff + (size_t)(ti + r) * 64 + tj) = v;
    }
    if (fro_out && tid == 0) {
        float s = 0.0f;
        #pragma unroll
        for (int j = 0; j < 64; ++j) s += ll2[j];
        fro_out[blockIdx.x] = s;
    }
}

// out_b = scale * L @ X_b @ R  (L, R broadcast)
__global__ __launch_bounds__(256) void cong_kernel(
    const float* __restrict__ Lm, const float* __restrict__ Xb,
    const float* __restrict__ Rm, float* __restrict__ out)
{
    __shared__ float Ls[MATSZ], Rs[MATSZ], Xs[MATSZ];
    const int tid = threadIdx.x;
    const size_t boff = (size_t)blockIdx.x * MATSZ;
    for (int i = tid; i < MATSZ; i += 256) {
        Ls[i] = Lm[i]; Rs[i] = Rm[i]; Xs[i] = Xb[boff + i];
    }
    __syncthreads();

    const int ti = (tid >> 4) << 2, tj = (tid & 15) << 2;
    float acc[4][4] = {};
    tile_mm_nn(Ls, Xs, acc, ti, tj);          // T = L @ X
    __syncthreads();
    #pragma unroll
    for (int r = 0; r < 4; ++r)
        #pragma unroll
        for (int c = 0; c < 4; ++c) Xs[(ti + r) * 64 + tj + c] = acc[r][c];
    __syncthreads();

    float acc2[4][4] = {};
    tile_mm_nn(Xs, Rs, acc2, ti, tj);         // out = T @ R
    #pragma unroll
    for (int r = 0; r < 4; ++r) {
        float4 v = make_float4(acc2[r][0], acc2[r][1], acc2[r][2], acc2[r][3]);
        *reinterpret_cast<float4*>(out + boff + (size_t)(ti + r) * 64 + tj) = v;
    }
}

// fused: out_b = (L @ X_b @ R)^2
__global__ __launch_bounds__(256) void cong_sq_kernel(
    const float* __restrict__ Lm, const float* __restrict__ Xb,
    const float* __restrict__ Rm, float* __restrict__ out)
{
    __shared__ float Ls[MATSZ], Rs[MATSZ], Xs[MATSZ];
    const int tid = threadIdx.x;
    const size_t boff = (size_t)blockIdx.x * MATSZ;
    for (int i = tid; i < MATSZ; i += 256) {
        Ls[i] = Lm[i]; Rs[i] = Rm[i]; Xs[i] = Xb[boff + i];
    }
    __syncthreads();

    const int ti = (tid >> 4) << 2, tj = (tid & 15) << 2;
    float acc[4][4] = {};
    tile_mm_nn(Ls, Xs, acc, ti, tj);          // T = L @ X
    __syncthreads();
    #pragma unroll
    for (int r = 0; r < 4; ++r)
        #pragma unroll
        for (int c = 0; c < 4; ++c) Xs[(ti + r) * 64 + tj + c] = acc[r][c];
    __syncthreads();

    float acc2[4][4] = {};
    tile_mm_nn(Xs, Rs, acc2, ti, tj);         // S = T @ R
    __syncthreads();
    #pragma unroll
    for (int r = 0; r < 4; ++r)
        #pragma unroll
        for (int c = 0; c < 4; ++c) Ls[(ti + r) * 64 + tj + c] = acc2[r][c];
    __syncthreads();

    float acc3[4][4] = {};
    tile_mm_nn(Ls, Ls, acc3, ti, tj);         // out = S @ S
    #pragma unroll
    for (int r = 0; r < 4; ++r) {
        float4 v = make_float4(acc3[r][0], acc3[r][1], acc3[r][2], acc3[r][3]);
        *reinterpret_cast<float4*>(out + boff + (size_t)(ti + r) * 64 + tj) = v;
    }
}

// single 64x64 gemm: C = op(A) @ B
__global__ __launch_bounds__(256) void gemm1_kernel(
    const float* __restrict__ A, const float* __restrict__ B,
    float* __restrict__ C, int transA)
{
    __shared__ float As_[MATSZ], Bs_[MATSZ];
    const int tid = threadIdx.x;
    for (int i = tid; i < MATSZ; i += 256) { As_[i] = A[i]; Bs_[i] = B[i]; }
    __syncthreads();
    const int ti = (tid >> 4) << 2, tj = (tid & 15) << 2;
    float acc[4][4] = {};
    if (transA) tile_mm_tn(As_, Bs_, acc, ti, tj);
    else        tile_mm_nn(As_, Bs_, acc, ti, tj);
    #pragma unroll
    for (int r = 0; r < 4; ++r) {
        float4 v = make_float4(acc[r][0], acc[r][1], acc[r][2], acc[r][3]);
        *reinterpret_cast<float4*>(C + (size_t)(ti + r) * 64 + tj) = v;
    }
}

// two-phase batch mean
__global__ __launch_bounds__(256) void mean1_kernel(const float* __restrict__ in)
{
    const int bc = blockIdx.x >> 4;
    const int e  = ((blockIdx.x & 15) << 8) + threadIdx.x;
    const float* base = in + (size_t)bc * 128 * MATSZ + e;
    double a0 = 0, a1 = 0, a2 = 0, a3 = 0;
    for (int b = 0; b < 128; b += 4) {
        a0 += (double)base[(size_t)(b + 0) * MATSZ];
        a1 += (double)base[(size_t)(b + 1) * MATSZ];
        a2 += (double)base[(size_t)(b + 2) * MATSZ];
        a3 += (double)base[(size_t)(b + 3) * MATSZ];
    }
    g_meanpart[bc * MATSZ + e] = (a0 + a1) + (a2 + a3);
}

__global__ __launch_bounds__(256) void mean2_kernel(float* __restrict__ out)
{
    const int e = (blockIdx.x << 8) + threadIdx.x;
    double a = 0;
    #pragma unroll
    for (int c = 0; c < 32; ++c) a += g_meanpart[c * MATSZ + e];
    out[e] = (float)(a * (1.0 / (double)NB));
}

// variance from per-matrix ||log||_F^2 (deterministic, 1 CTA)
__global__ __launch_bounds__(256) void var_reduce_kernel(const float* __restrict__ shift)
{
    __shared__ double sh[256];
    const int tid = threadIdx.x;
    double a = 0;
    #pragma unroll
    for (int i = 0; i < 16; ++i) a += (double)g_fro[tid * 16 + i];
    sh[tid] = a;
    __syncthreads();
    for (int s = 128; s > 0; s >>= 1) {
        if (tid < s) sh[tid] += sh[tid + s];
        __syncthreads();
    }
    if (tid == 0) {
        double var = sh[0] / (double)NB;
        g_scal[0] = shift[0] / (float)sqrt(var + 1e-5);
    }
}

extern "C" void kernel_launch(void* const* d_in, const int* in_sizes, int n_in,
                              void* d_out, int out_size)
{
    const float* X     = (const float*)d_in[0];
    const float* W     = (const float*)d_in[1];
    const float* M     = (const float*)d_in[2];
    const float* shift = (const float*)d_in[3];
    float* out = (float*)d_out;

    float *bufA, *bufB, *bufC, *bufD, *sm, *fro;
    cudaGetSymbolAddress((void**)&bufA, g_bufA);
    cudaGetSymbolAddress((void**)&bufB, g_bufB);
    cudaGetSymbolAddress((void**)&bufC, g_bufC);
    cudaGetSymbolAddress((void**)&bufD, g_bufD);
    cudaGetSymbolAddress((void**)&sm,   g_small);
    cudaGetSymbolAddress((void**)&fro,  g_fro);

    cudaFuncSetAttribute(nssqrt_kernel,     cudaFuncAttributeMaxDynamicSharedMemorySize, 65536);
    cudaFuncSetAttribute(nssmall_kernel,    cudaFuncAttributeMaxDynamicSharedMemorySize, 65536);
    cudaFuncSetAttribute(expm_kernel,       cudaFuncAttributeMaxDynamicSharedMemorySize, 49152);
    cudaFuncSetAttribute(expm_fused_kernel, cudaFuncAttributeMaxDynamicSharedMemorySize, 65536);

    static cudaStream_t s2 = [] {
        cudaStream_t s; cudaStreamCreateWithFlags(&s, cudaStreamNonBlocking); return s;
    }();
    static cudaEvent_t evFork = [] {
        cudaEvent_t e; cudaEventCreateWithFlags(&e, cudaEventDisableTiming); return e;
    }();
    static cudaEvent_t evMnh = [] {
        cudaEvent_t e; cudaEventCreateWithFlags(&e, cudaEventDisableTiming); return e;
    }();
    static cudaEvent_t evPrep = [] {
        cudaEvent_t e; cudaEventCreateWithFlags(&e, cudaEventDisableTiming); return e;
    }();

    #define SLOT(i) (sm + (i) * MATSZ)
    // slots: 0 Mh, 1 Mnh, 2 Wh, 3 prep-tmp, 4 Wc, 5 Wch, 6 Wcnh, 7 P,
    //        8 Q, 10 G0, 11 G0h, 12 G0nh, 13 Tm, 14 expTm, 15 G, 16 mnh,
    //        17 Pt, 18 Qt, 19 mid-tmp

    // ---- fork: parameter prep on s2, concurrent with nssqrt on stream0 ----
    cudaEventRecord(evFork, 0);
    cudaStreamWaitEvent(s2, evFork, 0);
    nssmall_kernel<<<2, 256, 65536, s2>>>(M, SLOT(0), SLOT(1),   // Mh, Mnh
                                          W, SLOT(2), nullptr);  // Wh
    cudaEventRecord(evMnh, s2);
    gemm1_kernel<<<1, 256, 0, s2>>>(SLOT(1), SLOT(2), SLOT(3), 0);   // Mnh Wh
    gemm1_kernel<<<1, 256, 0, s2>>>(SLOT(3), SLOT(1), SLOT(4), 0);   // Wc
    nssmall_kernel<<<1, 256, 65536, s2>>>(SLOT(4), SLOT(5), SLOT(6),
                                          SLOT(4), nullptr, nullptr); // Wch, Wcnh
    gemm1_kernel<<<1, 256, 0, s2>>>(SLOT(6), SLOT(2), SLOT(7), 0);   // P  = Wcnh Wh
    gemm1_kernel<<<1, 256, 0, s2>>>(SLOT(2), SLOT(6), SLOT(17), 0);  // Pt = Wh Wcnh
    gemm1_kernel<<<1, 256, 0, s2>>>(SLOT(0), SLOT(5), SLOT(8), 0);   // Q  = Mh Wch
    gemm1_kernel<<<1, 256, 0, s2>>>(SLOT(5), SLOT(0), SLOT(18), 0);  // Qt = Wch Mh
    cudaEventRecord(evPrep, s2);

    // ---- stream0: Xp = X^{1/2}; join Mnh; Xc = Mnh Xp Mnh ----
    nssqrt_kernel<<<NB, 256, 65536>>>(X, bufA);
    cudaStreamWaitEvent(0, evMnh, 0);
    cong_kernel<<<NB, 256>>>(SLOT(1), bufA, SLOT(1), bufB);          // Xc

    // bary_geom: 1 Karcher step from arithmetic mean
    mean1_kernel<<<512, 256>>>(bufB);
    mean2_kernel<<<16, 256>>>(SLOT(10));                             // G0
    nssmall_kernel<<<1, 256, 65536>>>(SLOT(10), SLOT(11), SLOT(12),
                                      SLOT(10), nullptr, nullptr);   // G0h, G0nh
    cong_kernel<<<NB, 256>>>(SLOT(12), bufB, SLOT(12), bufC);
    jac1s512<<<NB, 512>>>(bufC, bufA, nullptr, 6);
    mean1_kernel<<<512, 256>>>(bufA);
    mean2_kernel<<<16, 256>>>(SLOT(13));                             // Tm
    expm_kernel<<<1, 256, 49152>>>(SLOT(13), SLOT(14));              // expTm
    gemm1_kernel<<<1, 256>>>(SLOT(11), SLOT(14), SLOT(19), 0);
    gemm1_kernel<<<1, 256>>>(SLOT(19), SLOT(11), SLOT(15), 0);       // G
    nssmall_kernel<<<1, 256, 65536>>>(SLOT(15), nullptr, SLOT(16),
                                      SLOT(15), nullptr, nullptr);   // mnh

    // tangent at I + eigen-based variance
    cong_kernel<<<NB, 256>>>(SLOT(16), bufB, SLOT(16), bufC);
    jac1s512<<<NB, 512>>>(bufC, bufD, fro, 6);                       // T0, ||log||_F^2
    var_reduce_kernel<<<1, 256>>>(shift);

    // join full prep; E = exp(factor * P T0 Pt)  (fused)
    cudaStreamWaitEvent(0, evPrep, 0);
    expm_fused_kernel<<<NB, 256, 65536>>>(SLOT(7), bufD, SLOT(17), bufA);

    // out = (Q E Qt)^2  (fused)
    cong_sq_kernel<<<NB, 256>>>(SLOT(8), bufA, SLOT(18), out);
    #undef SLOT
}

// round 15
// speedup vs baseline: 2.3898x; 1.0627x over previous
#include <cuda_runtime.h>
#include <math.h>

#define NN 64
#define MATSZ 4096
#define NB 4096

// device-global scratch (no runtime allocation allowed)
__device__ float  g_bufA[(size_t)NB * MATSZ];
__device__ float  g_bufB[(size_t)NB * MATSZ];
__device__ float  g_bufC[(size_t)NB * MATSZ];
__device__ float  g_bufD[(size_t)NB * MATSZ];
__device__ float  g_small[20 * MATSZ];
__device__ double g_meanpart[32 * MATSZ];
__device__ float  g_fro[NB];
__device__ float  g_scal[4];

// Blackwell packed fp32x2 (FFMA2) — PTX-only, ptxas never auto-fuses.
#define PACKF2(d, lo, hi) asm("mov.b64 %0, {%1, %2};" : "=l"(d) : "f"(lo), "f"(hi))
#define UNPACKF2(lo, hi, d) asm("mov.b64 {%0, %1}, %2;" : "=f"(lo), "=f"(hi) : "l"(d))
#define FMAF2(acc, a, b) asm("fma.rn.f32x2 %0, %1, %2, %0;" : "+l"(acc) : "l"(a), "l"(b))

__device__ __forceinline__ float f4c(const float4& v, int k) {
    return k == 0 ? v.x : k == 1 ? v.y : k == 2 ? v.z : v.w;
}

// ---------------------------------------------------------------------------
// 256-thread 4x4-tile inner product with packed f32x2 accumulation.
// ---------------------------------------------------------------------------
__device__ __forceinline__ void tile_mm_nn(const float* __restrict__ A,
                                           const float* __restrict__ B,
                                           float acc[4][4], int ti, int tj)
{
    unsigned long long p01[4], p23[4];
    #pragma unroll
    for (int r = 0; r < 4; ++r) {
        PACKF2(p01[r], acc[r][0], acc[r][1]);
        PACKF2(p23[r], acc[r][2], acc[r][3]);
    }
    #pragma unroll 4
    for (int k4 = 0; k4 < 64; k4 += 4) {
        float4 av[4];
        #pragma unroll
        for (int r = 0; r < 4; ++r)
            av[r] = *reinterpret_cast<const float4*>(A + (ti + r) * 64 + k4);
        #pragma unroll
        for (int kk = 0; kk < 4; ++kk) {
            float4 b = *reinterpret_cast<const float4*>(B + (k4 + kk) * 64 + tj);
            unsigned long long b01, b23;
            PACKF2(b01, b.x, b.y);
            PACKF2(b23, b.z, b.w);
            #pragma unroll
            for (int r = 0; r < 4; ++r) {
                float a = f4c(av[r], kk);
                unsigned long long aa;
                PACKF2(aa, a, a);
                FMAF2(p01[r], aa, b01);
                FMAF2(p23[r], aa, b23);
            }
        }
    }
    #pragma unroll
    for (int r = 0; r < 4; ++r) {
        UNPACKF2(acc[r][0], acc[r][1], p01[r]);
        UNPACKF2(acc[r][2], acc[r][3], p23[r]);
    }
}

// scalar transposed-A tile (tiny gemm1 only)
__device__ __forceinline__ void tile_mm_tn(const float* __restrict__ A,
                                           const float* __restrict__ B,
                                           float acc[4][4], int ti, int tj)
{
    #pragma unroll 4
    for (int k = 0; k < 64; ++k) {
        float a[4];
        #pragma unroll
        for (int r = 0; r < 4; ++r) a[r] = A[k * 64 + ti + r];
        float4 b = *reinterpret_cast<const float4*>(B + k * 64 + tj);
        #pragma unroll
        for (int r = 0; r < 4; ++r) {
            acc[r][0] += a[r] * b.x; acc[r][1] += a[r] * b.y;
            acc[r][2] += a[r] * b.z; acc[r][3] += a[r] * b.w;
        }
    }
}

// ---------------------------------------------------------------------------
// In-shared 64x64 GEMM: C = alpha*(A@B) + beta*D + diag*I. 256 threads.
// ---------------------------------------------------------------------------
__device__ __forceinline__ void mm64(const float* __restrict__ A,
                                     const float* __restrict__ B,
                                     float alpha, float beta,
                                     const float* __restrict__ D,
                                     float diag, float* __restrict__ C, int tid)
{
    const int ti = (tid >> 4) << 2, tj = (tid & 15) << 2;
    float acc[4][4] = {};
    tile_mm_nn(A, B, acc, ti, tj);
    __syncthreads();
    #pragma unroll
    for (int r = 0; r < 4; ++r) {
        float4 v;
        v.x = alpha * acc[r][0]; v.y = alpha * acc[r][1];
        v.z = alpha * acc[r][2]; v.w = alpha * acc[r][3];
        if (beta != 0.0f) {
            float4 d = *reinterpret_cast<const float4*>(D + (ti + r) * 64 + tj);
            v.x += beta * d.x; v.y += beta * d.y; v.z += beta * d.z; v.w += beta * d.w;
        }
        if (diag != 0.0f) {
            int row = ti + r;
            if (row >= tj && row < tj + 4) (&v.x)[row - tj] += diag;
        }
        *reinterpret_cast<float4*>(C + (ti + r) * 64 + tj) = v;
    }
    __syncthreads();
}

// ---------------------------------------------------------------------------
// Batched matrix sqrt via coupled Newton-Schulz. One CTA/matrix, 8 iters.
// ---------------------------------------------------------------------------
__global__ __launch_bounds__(256) void nssqrt_kernel(
    const float* __restrict__ in, float* __restrict__ out)
{
    extern __shared__ float sh[];          // 4 * 4096 floats
    float *Y = sh, *Z = sh + 4096, *W = sh + 8192, *T = sh + 12288;
    __shared__ float red[256];
    __shared__ float s_s;

    const int tid = threadIdx.x;
    const size_t boff = (size_t)blockIdx.x * MATSZ;

    float fa = 0.0f;
    for (int idx = tid; idx < MATSZ; idx += 256) {
        float v = in[boff + idx];
        Y[idx] = v;
        fa += v * v;
        Z[idx] = ((idx >> 6) == (idx & 63)) ? 1.0f : 0.0f;
    }
    red[tid] = fa;
    __syncthreads();
    #pragma unroll
    for (int s = 128; s > 0; s >>= 1) {
        if (tid < s) red[tid] += red[tid + s];
        __syncthreads();
    }
    if (tid == 0) s_s = fmaxf(sqrtf(red[0]) / 1.8f, 1e-20f);
    __syncthreads();
    float inv_s = 1.0f / s_s;
    for (int idx = tid; idx < MATSZ; idx += 256) Y[idx] *= inv_s;
    __syncthreads();

    for (int it = 0; it < 8; ++it) {
        mm64(Z, Y, 1.0f, 0.0f, nullptr, 0.0f, W, tid);      // W = Z@Y
        mm64(Y, W, -0.5f, 1.5f, Y, 0.0f, T, tid);           // T = 1.5Y - 0.5 Y@W
        if (it < 7) {
            mm64(W, Z, -0.5f, 1.5f, Z, 0.0f, Y, tid);       // Znew -> old Y buffer
            float* nY = T; float* nZ = Y; float* nT = Z;
            Y = nY; Z = nZ; T = nT;
        } else {
            Y = T;
        }
    }
    float rs = sqrtf(s_s);
    for (int idx = tid; idx < MATSZ; idx += 256)
        out[boff + idx] = Y[idx] * rs;
}

// ---------------------------------------------------------------------------
// Tiny (1-2 matrix) coupled Newton-Schulz: A^{1/2} and A^{-1/2}. 256 thr.
// 10 iterations (inputs near identity; converged by ~7).
// ---------------------------------------------------------------------------
__global__ __launch_bounds__(256) void nssmall_kernel(
    const float* __restrict__ inA, float* sqA, float* isqA,
    const float* __restrict__ inB, float* sqB, float* isqB)
{
    extern __shared__ float sh[];          // 4 * 4096 floats
    float *Y = sh, *Z = sh + 4096, *W = sh + 8192, *T = sh + 12288;
    __shared__ float red[256];
    __shared__ float s_s;

    const int tid = threadIdx.x;
    const float* in = blockIdx.x ? inB : inA;
    float* osq  = blockIdx.x ? sqB  : sqA;
    float* oisq = blockIdx.x ? isqB : isqA;

    float fa = 0.0f;
    for (int idx = tid; idx < MATSZ; idx += 256) {
        float v = in[idx];
        Y[idx] = v;
        fa += v * v;
        Z[idx] = ((idx >> 6) == (idx & 63)) ? 1.0f : 0.0f;
    }
    red[tid] = fa;
    __syncthreads();
    #pragma unroll
    for (int s = 128; s > 0; s >>= 1) {
        if (tid < s) red[tid] += red[tid + s];
        __syncthreads();
    }
    if (tid == 0) s_s = fmaxf(sqrtf(red[0]) / 1.8f, 1e-20f);
    __syncthreads();
    float inv_s = 1.0f / s_s;
    for (int idx = tid; idx < MATSZ; idx += 256) Y[idx] *= inv_s;
    __syncthreads();

    for (int it = 0; it < 10; ++it) {
        mm64(Z, Y, 1.0f, 0.0f, nullptr, 0.0f, W, tid);      // W = Z@Y
        mm64(Y, W, -0.5f, 1.5f, Y, 0.0f, T, tid);           // newY -> T
        mm64(W, Z, -0.5f, 1.5f, Z, 0.0f, Y, tid);           // newZ -> old Y
        float* oY = Y; float* oZ = Z;
        Y = T; Z = oY; T = oZ;
    }
    float rs  = sqrtf(s_s);
    float irs = rsqrtf(s_s);
    if (osq)
        for (int idx = tid; idx < MATSZ; idx += 256) osq[idx] = Y[idx] * rs;
    if (oisq)
        for (int idx = tid; idx < MATSZ; idx += 256) oisq[idx] = Z[idx] * irs;
}

// ---------------------------------------------------------------------------
// expm core on shared buffer B (degree-5 Taylor + squaring). P, Q scratch.
// ---------------------------------------------------------------------------
__device__ __forceinline__ void expm_core(float* B, float* P, float* Q,
                                          float* __restrict__ out, size_t boff,
                                          int tid, float fro2)
{
    __shared__ float sc_s;
    __shared__ int   j_s;
    if (tid == 0) {
        float F = sqrtf(fro2);
        int j = 0;
        while (F > 0.25f && j < 40) { F *= 0.5f; ++j; }
        j_s = j;
        sc_s = exp2f((float)(-j));
    }
    __syncthreads();
    const int j = j_s;
    float sc = sc_s;
    for (int idx = tid; idx < MATSZ; idx += 256) B[idx] *= sc;
    __syncthreads();

    const float c5 = 1.0f / 120.0f, c4 = 1.0f / 24.0f;
    for (int idx = tid; idx < MATSZ; idx += 256) {
        float v = c5 * B[idx];
        if ((idx >> 6) == (idx & 63)) v += c4;
        P[idx] = v;
    }
    __syncthreads();
    const float cs[4] = { 1.0f / 6.0f, 0.5f, 1.0f, 1.0f };
    float *cur = P, *oth = Q;
    #pragma unroll
    for (int k = 0; k < 4; ++k) {
        mm64(cur, B, 1.0f, 0.0f, nullptr, cs[k], oth, tid);
        float* t = cur; cur = oth; oth = t;
    }
    for (int t = 0; t < j; ++t) {
        mm64(cur, cur, 1.0f, 0.0f, nullptr, 0.0f, oth, tid);
        float* tt = cur; cur = oth; oth = tt;
    }
    for (int idx = tid; idx < MATSZ; idx += 256)
        out[boff + idx] = cur[idx];
}

// plain expm (tiny serialized use): out = exp(in_b)
__global__ __launch_bounds__(256) void expm_kernel(
    const float* __restrict__ in, float* __restrict__ out)
{
    extern __shared__ float sh[];          // 3 * 4096 floats
    float *B = sh, *P = sh + 4096, *Q = sh + 8192;
    __shared__ float red[256];
    const int tid = threadIdx.x;
    const size_t boff = (size_t)blockIdx.x * MATSZ;

    float fa = 0.0f;
    for (int idx = tid; idx < MATSZ; idx += 256) {
        float v = in[boff + idx];
        B[idx] = v;
        fa += v * v;
    }
    red[tid] = fa;
    __syncthreads();
    #pragma unroll
    for (int s = 128; s > 0; s >>= 1) {
        if (tid < s) red[tid] += red[tid + s];
        __syncthreads();
    }
    __shared__ float fro2_s;
    if (tid == 0) fro2_s = red[0];
    __syncthreads();
    expm_core(B, P, Q, out, boff, tid, fro2_s);
}

// fused: out_b = exp( g_scal[0] * Pm @ T0_b @ Ptm )   (64KB dynamic smem)
__global__ __launch_bounds__(256) void expm_fused_kernel(
    const float* __restrict__ Pm, const float* __restrict__ T0,
    const float* __restrict__ Ptm, float* __restrict__ out)
{
    extern __shared__ float sh[];          // 4 * 4096 floats
    float *b0 = sh, *b1 = sh + 4096, *b2 = sh + 8192, *b3 = sh + 12288;
    __shared__ float red[256];
    const int tid = threadIdx.x;
    const size_t boff = (size_t)blockIdx.x * MATSZ;
    const float fac = g_scal[0];

    for (int i = tid; i < MATSZ; i += 256) {
        b0[i] = Pm[i];
        b1[i] = T0[boff + i];
        b2[i] = Ptm[i];
    }
    __syncthreads();
    mm64(b0, b1, 1.0f, 0.0f, nullptr, 0.0f, b3, tid);       // T1 = P @ T0
    mm64(b3, b2, fac,  0.0f, nullptr, 0.0f, b1, tid);       // arg -> b1

    float fa = 0.0f;
    for (int i = tid; i < MATSZ; i += 256) { float v = b1[i]; fa += v * v; }
    red[tid] = fa;
    __syncthreads();
    #pragma unroll
    for (int s = 128; s > 0; s >>= 1) {
        if (tid < s) red[tid] += red[tid + s];
        __syncthreads();
    }
    __shared__ float fro2_s;
    if (tid == 0) fro2_s = red[0];
    __syncthreads();
    expm_core(b1, b0, b2, out, boff, tid, fro2_s);
}

// ---------------------------------------------------------------------------
// One-sided (Hestenes) Jacobi LOG, symmetric 64x64 — half-warp float4.
// out = V log(L) V^T; optional fro_out[blockIdx] = sum_j log(lam_j)^2.
// ---------------------------------------------------------------------------
__global__ __launch_bounds__(512) void jac1s512(
    const float* __restrict__ in, float* __restrict__ out1,
    float* __restrict__ fro_out, int nsweeps)
{
    __shared__ float  As[64 * 68];
    __shared__ float  norms[64];
    __shared__ float  gv[64], ll2[64];
    __shared__ uchar2 ptab[63 * 32];

    const int tid  = threadIdx.x;
    const int lane = tid & 31;
    const int wid  = tid >> 5;
    const int sl   = lane & 15;
    const int k    = (wid << 1) | (lane >> 4);
    const size_t boff = (size_t)blockIdx.x * MATSZ;

    for (int i = tid; i < 63 * 32; i += 512) {
        int r = i >> 5, kk = i & 31;
        int p, q;
        if (kk == 0) { p = 63; q = r; }
        else {
            int a1 = r + kk;      p = (a1 < 63) ? a1 : a1 - 63;
            int a2 = r + 63 - kk; q = (a2 < 63) ? a2 : a2 - 63;
        }
        ptab[i] = make_uchar2((unsigned char)p, (unsigned char)q);
    }

    for (int idx = tid; idx < MATSZ; idx += 512) {
        int c = idx >> 6, r = idx & 63;
        As[c * 68 + r] = in[boff + idx];
    }
    __syncthreads();

    for (int j = k; j < 64; j += 32) {
        float4 a = *reinterpret_cast<const float4*>(As + j * 68 + sl * 4);
        float s = a.x * a.x + a.y * a.y + a.z * a.z + a.w * a.w;
        #pragma unroll
        for (int o = 8; o; o >>= 1) s += __shfl_xor_sync(0xFFFFFFFFu, s, o);
        if (sl == 0) norms[j] = s;
    }
    __syncthreads();

    for (int sw = 0; sw < nsweeps; ++sw) {
        for (int r = 0; r < 63; ++r) {
            uchar2 pq = ptab[(r << 5) | k];
            const int p = pq.x, q = pq.y;
            float4* cp = reinterpret_cast<float4*>(As + p * 68);
            float4* cq = reinterpret_cast<float4*>(As + q * 68);
            float4 ap = cp[sl];
            float4 aq = cq[sl];
            float g = ap.x * aq.x + ap.y * aq.y + ap.z * aq.z + ap.w * aq.w;
            #pragma unroll
            for (int o = 8; o; o >>= 1) g += __shfl_xor_sync(0xFFFFFFFFu, g, o);
            if (g != 0.0f) {
                float al = norms[p], be = norms[q];
                float tau = (be - al) / (2.0f * g);
                float t = 1.0f / (fabsf(tau) + sqrtf(1.0f + tau * tau));
                if (tau < 0.0f) t = -t;
                float c = rsqrtf(1.0f + t * t);
                float s = t * c;
                float4 np, nq;
                np.x = c * ap.x - s * aq.x;  nq.x = s * ap.x + c * aq.x;
                np.y = c * ap.y - s * aq.y;  nq.y = s * ap.y + c * aq.y;
                np.z = c * ap.z - s * aq.z;  nq.z = s * ap.z + c * aq.z;
                np.w = c * ap.w - s * aq.w;  nq.w = s * ap.w + c * aq.w;
                cp[sl] = np;
                cq[sl] = nq;
                if (sl == 0) {
                    float cc = c * c, ss = s * s, cs2 = 2.0f * c * s;
                    norms[p] = cc * al - cs2 * g + ss * be;
                    norms[q] = ss * al + cs2 * g + cc * be;
                }
            }
            __syncthreads();
        }
    }

    for (int j = k; j < 64; j += 32) {
        float4 a = *reinterpret_cast<const float4*>(As + j * 68 + sl * 4);
        float s = a.x * a.x + a.y * a.y + a.z * a.z + a.w * a.w;
        #pragma unroll
        for (int o = 8; o; o >>= 1) s += __shfl_xor_sync(0xFFFFFFFFu, s, o);
        if (sl == 0) {
            s = fmaxf(s, 1e-30f);
            float lam = sqrtf(s);
            float lg = logf(lam);
            gv[j]  = lg / s;
            ll2[j] = lg * lg;
        }
    }
    __syncthreads();

    const int ti = (tid >> 4) * 2;
    const int tj = (tid & 15) << 2;
    float acc[2][4] = {};
    #pragma unroll 4
    for (int kk = 0; kk < 64; ++kk) {
        const float* ck = As + kk * 68;
        float gk = gv[kk];
        float2 ar = *reinterpret_cast<const float2*>(ck + ti);
        float4 b  = *reinterpret_cast<const float4*>(ck + tj);
        float a0 = gk * ar.x, a1 = gk * ar.y;
        acc[0][0] += a0 * b.x; acc[0][1] += a0 * b.y; acc[0][2] += a0 * b.z; acc[0][3] += a0 * b.w;
        acc[1][0] += a1 * b.x; acc[1][1] += a1 * b.y; acc[1][2] += a1 * b.z; acc[1][3] += a1 * b.w;
    }
    #pragma unroll
    for (int r = 0; r < 2; ++r) {
        float4 v = make_float4(acc[r][0], acc[r][1], acc[r][2], acc[r][3]);
        *reinterpret_cast<float4*>(out1 + boff + (size_t)(ti + r) * 64 + tj) = v;
    }
    if (fro_out && tid == 0) {
        float s = 0.0f;
        #pragma unroll
        for (int j = 0; j < 64; ++j) s += ll2[j];
        fro_out[blockIdx.x] = s;
    }
}

// out_b = L @ X_b @ R  (L, R broadcast)
__global__ __launch_bounds__(256) void cong_kernel(
    const float* __restrict__ Lm, const float* __restrict__ Xb,
    const float* __restrict__ Rm, float* __restrict__ out)
{
    __shared__ float Ls[MATSZ], Rs[MATSZ], Xs[MATSZ];
    const int tid = threadIdx.x;
    const size_t boff = (size_t)blockIdx.x * MATSZ;
    for (int i = tid; i < MATSZ; i += 256) {
        Ls[i] = Lm[i]; Rs[i] = Rm[i]; Xs[i] = Xb[boff + i];
    }
    __syncthreads();

    const int ti = (tid >> 4) << 2, tj = (tid & 15) << 2;
    float acc[4][4] = {};
    tile_mm_nn(Ls, Xs, acc, ti, tj);          // T = L @ X
    __syncthreads();
    #pragma unroll
    for (int r = 0; r < 4; ++r)
        #pragma unroll
        for (int c = 0; c < 4; ++c) Xs[(ti + r) * 64 + tj + c] = acc[r][c];
    __syncthreads();

    float acc2[4][4] = {};
    tile_mm_nn(Xs, Rs, acc2, ti, tj);         // out = T @ R
    #pragma unroll
    for (int r = 0; r < 4; ++r) {
        float4 v = make_float4(acc2[r][0], acc2[r][1], acc2[r][2], acc2[r][3]);
        *reinterpret_cast<float4*>(out + boff + (size_t)(ti + r) * 64 + tj) = v;
    }
}

// fused: out_b = (L @ X_b @ R)^2
__global__ __launch_bounds__(256) void cong_sq_kernel(
    const float* __restrict__ Lm, const float* __restrict__ Xb,
    const float* __restrict__ Rm, float* __restrict__ out)
{
    __shared__ float Ls[MATSZ], Rs[MATSZ], Xs[MATSZ];
    const int tid = threadIdx.x;
    const size_t boff = (size_t)blockIdx.x * MATSZ;
    for (int i = tid; i < MATSZ; i += 256) {
        Ls[i] = Lm[i]; Rs[i] = Rm[i]; Xs[i] = Xb[boff + i];
    }
    __syncthreads();

    const int ti = (tid >> 4) << 2, tj = (tid & 15) << 2;
    float acc[4][4] = {};
    tile_mm_nn(Ls, Xs, acc, ti, tj);          // T = L @ X
    __syncthreads();
    #pragma unroll
    for (int r = 0; r < 4; ++r)
        #pragma unroll
        for (int c = 0; c < 4; ++c) Xs[(ti + r) * 64 + tj + c] = acc[r][c];
    __syncthreads();

    float acc2[4][4] = {};
    tile_mm_nn(Xs, Rs, acc2, ti, tj);         // S = T @ R
    __syncthreads();
    #pragma unroll
    for (int r = 0; r < 4; ++r)
        #pragma unroll
        for (int c = 0; c < 4; ++c) Ls[(ti + r) * 64 + tj + c] = acc2[r][c];
    __syncthreads();

    float acc3[4][4] = {};
    tile_mm_nn(Ls, Ls, acc3, ti, tj);         // out = S @ S
    #pragma unroll
    for (int r = 0; r < 4; ++r) {
        float4 v = make_float4(acc3[r][0], acc3[r][1], acc3[r][2], acc3[r][3]);
        *reinterpret_cast<float4*>(out + boff + (size_t)(ti + r) * 64 + tj) = v;
    }
}

// single 64x64 gemm: C = op(A) @ B
__global__ __launch_bounds__(256) void gemm1_kernel(
    const float* __restrict__ A, const float* __restrict__ B,
    float* __restrict__ C, int transA)
{
    __shared__ float As_[MATSZ], Bs_[MATSZ];
    const int tid = threadIdx.x;
    for (int i = tid; i < MATSZ; i += 256) { As_[i] = A[i]; Bs_[i] = B[i]; }
    __syncthreads();
    const int ti = (tid >> 4) << 2, tj = (tid & 15) << 2;
    float acc[4][4] = {};
    if (transA) tile_mm_tn(As_, Bs_, acc, ti, tj);
    else        tile_mm_nn(As_, Bs_, acc, ti, tj);
    #pragma unroll
    for (int r = 0; r < 4; ++r) {
        float4 v = make_float4(acc[r][0], acc[r][1], acc[r][2], acc[r][3]);
        *reinterpret_cast<float4*>(C + (size_t)(ti + r) * 64 + tj) = v;
    }
}

// two-phase batch mean
__global__ __launch_bounds__(256) void mean1_kernel(const float* __restrict__ in)
{
    const int bc = blockIdx.x >> 4;
    const int e  = ((blockIdx.x & 15) << 8) + threadIdx.x;
    const float* base = in + (size_t)bc * 128 * MATSZ + e;
    double a0 = 0, a1 = 0, a2 = 0, a3 = 0;
    for (int b = 0; b < 128; b += 4) {
        a0 += (double)base[(size_t)(b + 0) * MATSZ];
        a1 += (double)base[(size_t)(b + 1) * MATSZ];
        a2 += (double)base[(size_t)(b + 2) * MATSZ];
        a3 += (double)base[(size_t)(b + 3) * MATSZ];
    }
    g_meanpart[bc * MATSZ + e] = (a0 + a1) + (a2 + a3);
}

__global__ __launch_bounds__(256) void mean2_kernel(float* __restrict__ out)
{
    const int e = (blockIdx.x << 8) + threadIdx.x;
    double a = 0;
    #pragma unroll
    for (int c = 0; c < 32; ++c) a += g_meanpart[c * MATSZ + e];
    out[e] = (float)(a * (1.0 / (double)NB));
}

// variance from per-matrix ||log||_F^2 (deterministic, 1 CTA)
__global__ __launch_bounds__(256) void var_reduce_kernel(const float* __restrict__ shift)
{
    __shared__ double sh[256];
    const int tid = threadIdx.x;
    double a = 0;
    #pragma unroll
    for (int i = 0; i < 16; ++i) a += (double)g_fro[tid * 16 + i];
    sh[tid] = a;
    __syncthreads();
    for (int s = 128; s > 0; s >>= 1) {
        if (tid < s) sh[tid] += sh[tid + s];
        __syncthreads();
    }
    if (tid == 0) {
        double var = sh[0] / (double)NB;
        g_scal[0] = shift[0] / (float)sqrt(var + 1e-5);
    }
}

extern "C" void kernel_launch(void* const* d_in, const int* in_sizes, int n_in,
                              void* d_out, int out_size)
{
    const float* X     = (const float*)d_in[0];
    const float* W     = (const float*)d_in[1];
    const float* M     = (const float*)d_in[2];
    const float* shift = (const float*)d_in[3];
    float* out = (float*)d_out;

    float *bufA, *bufB, *bufC, *bufD, *sm, *fro;
    cudaGetSymbolAddress((void**)&bufA, g_bufA);
    cudaGetSymbolAddress((void**)&bufB, g_bufB);
    cudaGetSymbolAddress((void**)&bufC, g_bufC);
    cudaGetSymbolAddress((void**)&bufD, g_bufD);
    cudaGetSymbolAddress((void**)&sm,   g_small);
    cudaGetSymbolAddress((void**)&fro,  g_fro);

    cudaFuncSetAttribute(nssqrt_kernel,     cudaFuncAttributeMaxDynamicSharedMemorySize, 65536);
    cudaFuncSetAttribute(nssmall_kernel,    cudaFuncAttributeMaxDynamicSharedMemorySize, 65536);
    cudaFuncSetAttribute(expm_kernel,       cudaFuncAttributeMaxDynamicSharedMemorySize, 49152);
    cudaFuncSetAttribute(expm_fused_kernel, cudaFuncAttributeMaxDynamicSharedMemorySize, 65536);

    static cudaStream_t s2 = [] {
        cudaStream_t s; cudaStreamCreateWithFlags(&s, cudaStreamNonBlocking); return s;
    }();
    static cudaEvent_t evFork = [] {
        cudaEvent_t e; cudaEventCreateWithFlags(&e, cudaEventDisableTiming); return e;
    }();
    static cudaEvent_t evMnh = [] {
        cudaEvent_t e; cudaEventCreateWithFlags(&e, cudaEventDisableTiming); return e;
    }();
    static cudaEvent_t evPrep = [] {
        cudaEvent_t e; cudaEventCreateWithFlags(&e, cudaEventDisableTiming); return e;
    }();

    #define SLOT(i) (sm + (i) * MATSZ)
    // slots: 0 Mh, 1 Mnh, 2 Wh, 3 prep-tmp, 4 Wc, 5 Wch, 6 Wcnh, 7 P,
    //        8 Q, 10 G0, 11 G0h, 12 G0nh, 13 Tm, 14 expTm, 15 G, 16 mnh,
    //        17 Pt, 18 Qt, 19 mid-tmp

    // ---- fork: parameter prep on s2, concurrent with nssqrt on stream0 ----
    cudaEventRecord(evFork, 0);
    cudaStreamWaitEvent(s2, evFork, 0);
    nssmall_kernel<<<2, 256, 65536, s2>>>(M, SLOT(0), SLOT(1),   // Mh, Mnh
                                          W, SLOT(2), nullptr);  // Wh
    cudaEventRecord(evMnh, s2);
    gemm1_kernel<<<1, 256, 0, s2>>>(SLOT(1), SLOT(2), SLOT(3), 0);   // Mnh Wh
    gemm1_kernel<<<1, 256, 0, s2>>>(SLOT(3), SLOT(1), SLOT(4), 0);   // Wc
    nssmall_kernel<<<1, 256, 65536, s2>>>(SLOT(4), SLOT(5), SLOT(6),
                                          SLOT(4), nullptr, nullptr); // Wch, Wcnh
    gemm1_kernel<<<1, 256, 0, s2>>>(SLOT(6), SLOT(2), SLOT(7), 0);   // P  = Wcnh Wh
    gemm1_kernel<<<1, 256, 0, s2>>>(SLOT(2), SLOT(6), SLOT(17), 0);  // Pt = Wh Wcnh
    gemm1_kernel<<<1, 256, 0, s2>>>(SLOT(0), SLOT(5), SLOT(8), 0);   // Q  = Mh Wch
    gemm1_kernel<<<1, 256, 0, s2>>>(SLOT(5), SLOT(0), SLOT(18), 0);  // Qt = Wch Mh
    cudaEventRecord(evPrep, s2);

    // ---- stream0: Xp = X^{1/2}; join Mnh; Xc = Mnh Xp Mnh ----
    nssqrt_kernel<<<NB, 256, 65536>>>(X, bufA);
    cudaStreamWaitEvent(0, evMnh, 0);
    cong_kernel<<<NB, 256>>>(SLOT(1), bufA, SLOT(1), bufB);          // Xc

    // bary_geom: 1 Karcher step from arithmetic mean
    mean1_kernel<<<512, 256>>>(bufB);
    mean2_kernel<<<16, 256>>>(SLOT(10));                             // G0
    nssmall_kernel<<<1, 256, 65536>>>(SLOT(10), SLOT(11), SLOT(12),
                                      SLOT(10), nullptr, nullptr);   // G0h, G0nh
    cong_kernel<<<NB, 256>>>(SLOT(12), bufB, SLOT(12), bufC);
    jac1s512<<<NB, 512>>>(bufC, bufA, nullptr, 5);                   // stage-1 log (mean-only)
    mean1_kernel<<<512, 256>>>(bufA);
    mean2_kernel<<<16, 256>>>(SLOT(13));                             // Tm
    expm_kernel<<<1, 256, 49152>>>(SLOT(13), SLOT(14));              // expTm
    gemm1_kernel<<<1, 256>>>(SLOT(11), SLOT(14), SLOT(19), 0);
    gemm1_kernel<<<1, 256>>>(SLOT(19), SLOT(11), SLOT(15), 0);       // G
    nssmall_kernel<<<1, 256, 65536>>>(SLOT(15), nullptr, SLOT(16),
                                      SLOT(15), nullptr, nullptr);   // mnh

    // tangent at I + eigen-based variance (stage-2 log: full 6 sweeps)
    cong_kernel<<<NB, 256>>>(SLOT(16), bufB, SLOT(16), bufC);
    jac1s512<<<NB, 512>>>(bufC, bufD, fro, 6);                       // T0, ||log||_F^2
    var_reduce_kernel<<<1, 256>>>(shift);

    // join full prep; E = exp(factor * P T0 Pt)  (fused)
    cudaStreamWaitEvent(0, evPrep, 0);
    expm_fused_kernel<<<NB, 256, 65536>>>(SLOT(7), bufD, SLOT(17), bufA);

    // out = (Q E Qt)^2  (fused)
    cong_sq_kernel<<<NB, 256>>>(SLOT(8), bufA, SLOT(18), out);
    #undef SLOT
}

// round 16
// speedup vs baseline: 2.5100x; 1.0503x over previous
#include <cuda_runtime.h>
#include <math.h>

#define NN 64
#define MATSZ 4096
#define NB 4096

// device-global scratch (no runtime allocation allowed)
__device__ float  g_bufA[(size_t)NB * MATSZ];
__device__ float  g_bufB[(size_t)NB * MATSZ];
__device__ float  g_bufD[(size_t)NB * MATSZ];
__device__ float  g_small[20 * MATSZ];
__device__ double g_meanpart[32 * MATSZ];
__device__ float  g_fro[NB];
__device__ float  g_scal[4];

// Blackwell packed fp32x2 (FFMA2) — PTX-only, ptxas never auto-fuses.
#define PACKF2(d, lo, hi) asm("mov.b64 %0, {%1, %2};" : "=l"(d) : "f"(lo), "f"(hi))
#define UNPACKF2(lo, hi, d) asm("mov.b64 {%0, %1}, %2;" : "=f"(lo), "=f"(hi) : "l"(d))
#define FMAF2(acc, a, b) asm("fma.rn.f32x2 %0, %1, %2, %0;" : "+l"(acc) : "l"(a), "l"(b))

__device__ __forceinline__ float f4c(const float4& v, int k) {
    return k == 0 ? v.x : k == 1 ? v.y : k == 2 ? v.z : v.w;
}

// ---------------------------------------------------------------------------
// 256-thread 4x4-tile inner product with packed f32x2 accumulation.
// ---------------------------------------------------------------------------
__device__ __forceinline__ void tile_mm_nn(const float* __restrict__ A,
                                           const float* __restrict__ B,
                                           float acc[4][4], int ti, int tj)
{
    unsigned long long p01[4], p23[4];
    #pragma unroll
    for (int r = 0; r < 4; ++r) {
        PACKF2(p01[r], acc[r][0], acc[r][1]);
        PACKF2(p23[r], acc[r][2], acc[r][3]);
    }
    #pragma unroll 4
    for (int k4 = 0; k4 < 64; k4 += 4) {
        float4 av[4];
        #pragma unroll
        for (int r = 0; r < 4; ++r)
            av[r] = *reinterpret_cast<const float4*>(A + (ti + r) * 64 + k4);
        #pragma unroll
        for (int kk = 0; kk < 4; ++kk) {
            float4 b = *reinterpret_cast<const float4*>(B + (k4 + kk) * 64 + tj);
            unsigned long long b01, b23;
            PACKF2(b01, b.x, b.y);
            PACKF2(b23, b.z, b.w);
            #pragma unroll
            for (int r = 0; r < 4; ++r) {
                float a = f4c(av[r], kk);
                unsigned long long aa;
                PACKF2(aa, a, a);
                FMAF2(p01[r], aa, b01);
                FMAF2(p23[r], aa, b23);
            }
        }
    }
    #pragma unroll
    for (int r = 0; r < 4; ++r) {
        UNPACKF2(acc[r][0], acc[r][1], p01[r]);
        UNPACKF2(acc[r][2], acc[r][3], p23[r]);
    }
}

// scalar transposed-A tile (tiny gemm1 only)
__device__ __forceinline__ void tile_mm_tn(const float* __restrict__ A,
                                           const float* __restrict__ B,
                                           float acc[4][4], int ti, int tj)
{
    #pragma unroll 4
    for (int k = 0; k < 64; ++k) {
        float a[4];
        #pragma unroll
        for (int r = 0; r < 4; ++r) a[r] = A[k * 64 + ti + r];
        float4 b = *reinterpret_cast<const float4*>(B + k * 64 + tj);
        #pragma unroll
        for (int r = 0; r < 4; ++r) {
            acc[r][0] += a[r] * b.x; acc[r][1] += a[r] * b.y;
            acc[r][2] += a[r] * b.z; acc[r][3] += a[r] * b.w;
        }
    }
}

// ---------------------------------------------------------------------------
// In-shared 64x64 GEMM: C = alpha*(A@B) + beta*D + diag*I. 256 threads.
// ---------------------------------------------------------------------------
__device__ __forceinline__ void mm64(const float* __restrict__ A,
                                     const float* __restrict__ B,
                                     float alpha, float beta,
                                     const float* __restrict__ D,
                                     float diag, float* __restrict__ C, int tid)
{
    const int ti = (tid >> 4) << 2, tj = (tid & 15) << 2;
    float acc[4][4] = {};
    tile_mm_nn(A, B, acc, ti, tj);
    __syncthreads();
    #pragma unroll
    for (int r = 0; r < 4; ++r) {
        float4 v;
        v.x = alpha * acc[r][0]; v.y = alpha * acc[r][1];
        v.z = alpha * acc[r][2]; v.w = alpha * acc[r][3];
        if (beta != 0.0f) {
            float4 d = *reinterpret_cast<const float4*>(D + (ti + r) * 64 + tj);
            v.x += beta * d.x; v.y += beta * d.y; v.z += beta * d.z; v.w += beta * d.w;
        }
        if (diag != 0.0f) {
            int row = ti + r;
            if (row >= tj && row < tj + 4) (&v.x)[row - tj] += diag;
        }
        *reinterpret_cast<float4*>(C + (ti + r) * 64 + tj) = v;
    }
    __syncthreads();
}

// ---------------------------------------------------------------------------
// 512-thread in-shared GEMM, 2x4 tiles: C[sC] = A[sA] @ B[64].
// All reads complete before the barrier, so C may alias A or B.
// ---------------------------------------------------------------------------
__device__ __forceinline__ void mm512(const float* __restrict__ A, int sA,
                                      const float* __restrict__ B,
                                      float* __restrict__ C, int sC, int tid)
{
    const int ti = (tid >> 4) << 1;   // 0..62, 2 rows
    const int tj = (tid & 15) << 2;   // 0..60, 4 cols
    unsigned long long p01[2], p23[2];
    #pragma unroll
    for (int r = 0; r < 2; ++r) { PACKF2(p01[r], 0.0f, 0.0f); PACKF2(p23[r], 0.0f, 0.0f); }
    #pragma unroll 4
    for (int k4 = 0; k4 < 64; k4 += 4) {
        float4 a0 = *reinterpret_cast<const float4*>(A + (ti + 0) * sA + k4);
        float4 a1 = *reinterpret_cast<const float4*>(A + (ti + 1) * sA + k4);
        #pragma unroll
        for (int kk = 0; kk < 4; ++kk) {
            float4 b = *reinterpret_cast<const float4*>(B + (k4 + kk) * 64 + tj);
            unsigned long long b01, b23;
            PACKF2(b01, b.x, b.y);
            PACKF2(b23, b.z, b.w);
            float f0 = f4c(a0, kk), f1 = f4c(a1, kk);
            unsigned long long aa0, aa1;
            PACKF2(aa0, f0, f0);
            PACKF2(aa1, f1, f1);
            FMAF2(p01[0], aa0, b01); FMAF2(p23[0], aa0, b23);
            FMAF2(p01[1], aa1, b01); FMAF2(p23[1], aa1, b23);
        }
    }
    float acc[2][4];
    #pragma unroll
    for (int r = 0; r < 2; ++r) {
        UNPACKF2(acc[r][0], acc[r][1], p01[r]);
        UNPACKF2(acc[r][2], acc[r][3], p23[r]);
    }
    __syncthreads();   // ALL reads of A, B complete
    #pragma unroll
    for (int r = 0; r < 2; ++r) {
        float4 v = make_float4(acc[r][0], acc[r][1], acc[r][2], acc[r][3]);
        *reinterpret_cast<float4*>(C + (ti + r) * sC + tj) = v;
    }
    __syncthreads();
}

// ---------------------------------------------------------------------------
// Batched matrix sqrt via coupled Newton-Schulz. One CTA/matrix, 8 iters.
// ---------------------------------------------------------------------------
__global__ __launch_bounds__(256) void nssqrt_kernel(
    const float* __restrict__ in, float* __restrict__ out)
{
    extern __shared__ float sh[];          // 4 * 4096 floats
    float *Y = sh, *Z = sh + 4096, *W = sh + 8192, *T = sh + 12288;
    __shared__ float red[256];
    __shared__ float s_s;

    const int tid = threadIdx.x;
    const size_t boff = (size_t)blockIdx.x * MATSZ;

    float fa = 0.0f;
    for (int idx = tid; idx < MATSZ; idx += 256) {
        float v = in[boff + idx];
        Y[idx] = v;
        fa += v * v;
        Z[idx] = ((idx >> 6) == (idx & 63)) ? 1.0f : 0.0f;
    }
    red[tid] = fa;
    __syncthreads();
    #pragma unroll
    for (int s = 128; s > 0; s >>= 1) {
        if (tid < s) red[tid] += red[tid + s];
        __syncthreads();
    }
    if (tid == 0) s_s = fmaxf(sqrtf(red[0]) / 1.8f, 1e-20f);
    __syncthreads();
    float inv_s = 1.0f / s_s;
    for (int idx = tid; idx < MATSZ; idx += 256) Y[idx] *= inv_s;
    __syncthreads();

    for (int it = 0; it < 8; ++it) {
        mm64(Z, Y, 1.0f, 0.0f, nullptr, 0.0f, W, tid);      // W = Z@Y
        mm64(Y, W, -0.5f, 1.5f, Y, 0.0f, T, tid);           // T = 1.5Y - 0.5 Y@W
        if (it < 7) {
            mm64(W, Z, -0.5f, 1.5f, Z, 0.0f, Y, tid);       // Znew -> old Y buffer
            float* nY = T; float* nZ = Y; float* nT = Z;
            Y = nY; Z = nZ; T = nT;
        } else {
            Y = T;
        }
    }
    float rs = sqrtf(s_s);
    for (int idx = tid; idx < MATSZ; idx += 256)
        out[boff + idx] = Y[idx] * rs;
}

// ---------------------------------------------------------------------------
// Tiny (1-2 matrix) coupled Newton-Schulz: A^{1/2} and A^{-1/2}. 256 thr.
// ---------------------------------------------------------------------------
__global__ __launch_bounds__(256) void nssmall_kernel(
    const float* __restrict__ inA, float* sqA, float* isqA,
    const float* __restrict__ inB, float* sqB, float* isqB)
{
    extern __shared__ float sh[];          // 4 * 4096 floats
    float *Y = sh, *Z = sh + 4096, *W = sh + 8192, *T = sh + 12288;
    __shared__ float red[256];
    __shared__ float s_s;

    const int tid = threadIdx.x;
    const float* in = blockIdx.x ? inB : inA;
    float* osq  = blockIdx.x ? sqB  : sqA;
    float* oisq = blockIdx.x ? isqB : isqA;

    float fa = 0.0f;
    for (int idx = tid; idx < MATSZ; idx += 256) {
        float v = in[idx];
        Y[idx] = v;
        fa += v * v;
        Z[idx] = ((idx >> 6) == (idx & 63)) ? 1.0f : 0.0f;
    }
    red[tid] = fa;
    __syncthreads();
    #pragma unroll
    for (int s = 128; s > 0; s >>= 1) {
        if (tid < s) red[tid] += red[tid + s];
        __syncthreads();
    }
    if (tid == 0) s_s = fmaxf(sqrtf(red[0]) / 1.8f, 1e-20f);
    __syncthreads();
    float inv_s = 1.0f / s_s;
    for (int idx = tid; idx < MATSZ; idx += 256) Y[idx] *= inv_s;
    __syncthreads();

    for (int it = 0; it < 10; ++it) {
        mm64(Z, Y, 1.0f, 0.0f, nullptr, 0.0f, W, tid);      // W = Z@Y
        mm64(Y, W, -0.5f, 1.5f, Y, 0.0f, T, tid);           // newY -> T
        mm64(W, Z, -0.5f, 1.5f, Z, 0.0f, Y, tid);           // newZ -> old Y
        float* oY = Y; float* oZ = Z;
        Y = T; Z = oY; T = oZ;
    }
    float rs  = sqrtf(s_s);
    float irs = rsqrtf(s_s);
    if (osq)
        for (int idx = tid; idx < MATSZ; idx += 256) osq[idx] = Y[idx] * rs;
    if (oisq)
        for (int idx = tid; idx < MATSZ; idx += 256) oisq[idx] = Z[idx] * irs;
}

// ---------------------------------------------------------------------------
// expm core on shared buffer B (degree-5 Taylor + squaring). P, Q scratch.
// ---------------------------------------------------------------------------
__device__ __forceinline__ void expm_core(float* B, float* P, float* Q,
                                          float* __restrict__ out, size_t boff,
                                          int tid, float fro2)
{
    __shared__ float sc_s;
    __shared__ int   j_s;
    if (tid == 0) {
        float F = sqrtf(fro2);
        int j = 0;
        while (F > 0.25f && j < 40) { F *= 0.5f; ++j; }
        j_s = j;
        sc_s = exp2f((float)(-j));
    }
    __syncthreads();
    const int j = j_s;
    float sc = sc_s;
    for (int idx = tid; idx < MATSZ; idx += 256) B[idx] *= sc;
    __syncthreads();

    const float c5 = 1.0f / 120.0f, c4 = 1.0f / 24.0f;
    for (int idx = tid; idx < MATSZ; idx += 256) {
        float v = c5 * B[idx];
        if ((idx >> 6) == (idx & 63)) v += c4;
        P[idx] = v;
    }
    __syncthreads();
    const float cs[4] = { 1.0f / 6.0f, 0.5f, 1.0f, 1.0f };
    float *cur = P, *oth = Q;
    #pragma unroll
    for (int k = 0; k < 4; ++k) {
        mm64(cur, B, 1.0f, 0.0f, nullptr, cs[k], oth, tid);
        float* t = cur; cur = oth; oth = t;
    }
    for (int t = 0; t < j; ++t) {
        mm64(cur, cur, 1.0f, 0.0f, nullptr, 0.0f, oth, tid);
        float* tt = cur; cur = oth; oth = tt;
    }
    for (int idx = tid; idx < MATSZ; idx += 256)
        out[boff + idx] = cur[idx];
}

// plain expm (tiny serialized use): out = exp(in_b)
__global__ __launch_bounds__(256) void expm_kernel(
    const float* __restrict__ in, float* __restrict__ out)
{
    extern __shared__ float sh[];          // 3 * 4096 floats
    float *B = sh, *P = sh + 4096, *Q = sh + 8192;
    __shared__ float red[256];
    const int tid = threadIdx.x;
    const size_t boff = (size_t)blockIdx.x * MATSZ;

    float fa = 0.0f;
    for (int idx = tid; idx < MATSZ; idx += 256) {
        float v = in[boff + idx];
        B[idx] = v;
        fa += v * v;
    }
    red[tid] = fa;
    __syncthreads();
    #pragma unroll
    for (int s = 128; s > 0; s >>= 1) {
        if (tid < s) red[tid] += red[tid + s];
        __syncthreads();
    }
    __shared__ float fro2_s;
    if (tid == 0) fro2_s = red[0];
    __syncthreads();
    expm_core(B, P, Q, out, boff, tid, fro2_s);
}

// fused: out_b = exp( g_scal[0] * Pm @ T0_b @ Ptm )   (64KB dynamic smem)
__global__ __launch_bounds__(256) void expm_fused_kernel(
    const float* __restrict__ Pm, const float* __restrict__ T0,
    const float* __restrict__ Ptm, float* __restrict__ out)
{
    extern __shared__ float sh[];          // 4 * 4096 floats
    float *b0 = sh, *b1 = sh + 4096, *b2 = sh + 8192, *b3 = sh + 12288;
    __shared__ float red[256];
    const int tid = threadIdx.x;
    const size_t boff = (size_t)blockIdx.x * MATSZ;
    const float fac = g_scal[0];

    for (int i = tid; i < MATSZ; i += 256) {
        b0[i] = Pm[i];
        b1[i] = T0[boff + i];
        b2[i] = Ptm[i];
    }
    __syncthreads();
    mm64(b0, b1, 1.0f, 0.0f, nullptr, 0.0f, b3, tid);       // T1 = P @ T0
    mm64(b3, b2, fac,  0.0f, nullptr, 0.0f, b1, tid);       // arg -> b1

    float fa = 0.0f;
    for (int i = tid; i < MATSZ; i += 256) { float v = b1[i]; fa += v * v; }
    red[tid] = fa;
    __syncthreads();
    #pragma unroll
    for (int s = 128; s > 0; s >>= 1) {
        if (tid < s) red[tid] += red[tid + s];
        __syncthreads();
    }
    __shared__ float fro2_s;
    if (tid == 0) fro2_s = red[0];
    __syncthreads();
    expm_core(b1, b0, b2, out, boff, tid, fro2_s);
}

// ---------------------------------------------------------------------------
// FUSED whiten + one-sided Jacobi LOG, symmetric 64x64.
// Computes S = L @ X_b @ L in-shared (512-thread GEMMs, C aliases safe),
// then out = V log(Lam) V^T of S; optional fro_out = sum log(lam)^2.
// ---------------------------------------------------------------------------
__global__ __launch_bounds__(512) void jaclog_cong_kernel(
    const float* __restrict__ Lm, const float* __restrict__ Xb,
    float* __restrict__ out1, float* __restrict__ fro_out, int nsweeps)
{
    __shared__ float  Ls[MATSZ];
    __shared__ float  As[64 * 68];
    __shared__ float  norms[64];
    __shared__ float  gv[64], ll2[64];
    __shared__ uchar2 ptab[63 * 32];

    const int tid  = threadIdx.x;
    const int lane = tid & 31;
    const int wid  = tid >> 5;
    const int sl   = lane & 15;
    const int k    = (wid << 1) | (lane >> 4);
    const size_t boff = (size_t)blockIdx.x * MATSZ;

    for (int i = tid; i < 63 * 32; i += 512) {
        int r = i >> 5, kk = i & 31;
        int p, q;
        if (kk == 0) { p = 63; q = r; }
        else {
            int a1 = r + kk;      p = (a1 < 63) ? a1 : a1 - 63;
            int a2 = r + 63 - kk; q = (a2 < 63) ? a2 : a2 - 63;
        }
        ptab[i] = make_uchar2((unsigned char)p, (unsigned char)q);
    }

    // load L (broadcast) and X (row-major, into As front region stride 64)
    for (int i = tid; i < MATSZ; i += 512) {
        Ls[i] = Lm[i];
        As[i] = Xb[boff + i];
    }
    __syncthreads();

    // S = L @ X @ L: T -> As(64) [aliases B], then S -> As(68 layout)
    mm512(Ls, 64, As, As, 64, tid);      // As(64) = L @ X
    mm512(As, 64, Ls, As, 68, tid);      // As(68) = (L@X) @ L  (symmetric)

    for (int j = k; j < 64; j += 32) {
        float4 a = *reinterpret_cast<const float4*>(As + j * 68 + sl * 4);
        float s = a.x * a.x + a.y * a.y + a.z * a.z + a.w * a.w;
        #pragma unroll
        for (int o = 8; o; o >>= 1) s += __shfl_xor_sync(0xFFFFFFFFu, s, o);
        if (sl == 0) norms[j] = s;
    }
    __syncthreads();

    for (int sw = 0; sw < nsweeps; ++sw) {
        for (int r = 0; r < 63; ++r) {
            uchar2 pq = ptab[(r << 5) | k];
            const int p = pq.x, q = pq.y;
            float4* cp = reinterpret_cast<float4*>(As + p * 68);
            float4* cq = reinterpret_cast<float4*>(As + q * 68);
            float4 ap = cp[sl];
            float4 aq = cq[sl];
            float g = ap.x * aq.x + ap.y * aq.y + ap.z * aq.z + ap.w * aq.w;
            #pragma unroll
            for (int o = 8; o; o >>= 1) g += __shfl_xor_sync(0xFFFFFFFFu, g, o);
            if (g != 0.0f) {
                float al = norms[p], be = norms[q];
                float tau = (be - al) / (2.0f * g);
                float t = 1.0f / (fabsf(tau) + sqrtf(1.0f + tau * tau));
                if (tau < 0.0f) t = -t;
                float c = rsqrtf(1.0f + t * t);
                float s = t * c;
                float4 np, nq;
                np.x = c * ap.x - s * aq.x;  nq.x = s * ap.x + c * aq.x;
                np.y = c * ap.y - s * aq.y;  nq.y = s * ap.y + c * aq.y;
                np.z = c * ap.z - s * aq.z;  nq.z = s * ap.z + c * aq.z;
                np.w = c * ap.w - s * aq.w;  nq.w = s * ap.w + c * aq.w;
                cp[sl] = np;
                cq[sl] = nq;
                if (sl == 0) {
                    float cc = c * c, ss = s * s, cs2 = 2.0f * c * s;
                    norms[p] = cc * al - cs2 * g + ss * be;
                    norms[q] = ss * al + cs2 * g + cc * be;
                }
            }
            __syncthreads();
        }
    }

    for (int j = k; j < 64; j += 32) {
        float4 a = *reinterpret_cast<const float4*>(As + j * 68 + sl * 4);
        float s = a.x * a.x + a.y * a.y + a.z * a.z + a.w * a.w;
        #pragma unroll
        for (int o = 8; o; o >>= 1) s += __shfl_xor_sync(0xFFFFFFFFu, s, o);
        if (sl == 0) {
            s = fmaxf(s, 1e-30f);
            float lam = sqrtf(s);
            float lg = logf(lam);
            gv[j]  = lg / s;
            ll2[j] = lg * lg;
        }
    }
    __syncthreads();

    const int ti = (tid >> 4) * 2;
    const int tj = (tid & 15) << 2;
    float acc[2][4] = {};
    #pragma unroll 4
    for (int kk = 0; kk < 64; ++kk) {
        const float* ck = As + kk * 68;
        float gk = gv[kk];
        float2 ar = *reinterpret_cast<const float2*>(ck + ti);
        float4 b  = *reinterpret_cast<const float4*>(ck + tj);
        float a0 = gk * ar.x, a1 = gk * ar.y;
        acc[0][0] += a0 * b.x; acc[0][1] += a0 * b.y; acc[0][2] += a0 * b.z; acc[0][3] += a0 * b.w;
        acc[1][0] += a1 * b.x; acc[1][1] += a1 * b.y; acc[1][2] += a1 * b.z; acc[1][3] += a1 * b.w;
    }
    #pragma unroll
    for (int r = 0; r < 2; ++r) {
        float4 v = make_float4(acc[r][0], acc[r][1], acc[r][2], acc[r][3]);
        *reinterpret_cast<float4*>(out1 + boff + (size_t)(ti + r) * 64 + tj) = v;
    }
    if (fro_out && tid == 0) {
        float s = 0.0f;
        #pragma unroll
        for (int j = 0; j < 64; ++j) s += ll2[j];
        fro_out[blockIdx.x] = s;
    }
}

// out_b = L @ X_b @ R  (L, R broadcast)  — used once for Xc
__global__ __launch_bounds__(256) void cong_kernel(
    const float* __restrict__ Lm, const float* __restrict__ Xb,
    const float* __restrict__ Rm, float* __restrict__ out)
{
    __shared__ float Ls[MATSZ], Rs[MATSZ], Xs[MATSZ];
    const int tid = threadIdx.x;
    const size_t boff = (size_t)blockIdx.x * MATSZ;
    for (int i = tid; i < MATSZ; i += 256) {
        Ls[i] = Lm[i]; Rs[i] = Rm[i]; Xs[i] = Xb[boff + i];
    }
    __syncthreads();

    const int ti = (tid >> 4) << 2, tj = (tid & 15) << 2;
    float acc[4][4] = {};
    tile_mm_nn(Ls, Xs, acc, ti, tj);          // T = L @ X
    __syncthreads();
    #pragma unroll
    for (int r = 0; r < 4; ++r)
        #pragma unroll
        for (int c = 0; c < 4; ++c) Xs[(ti + r) * 64 + tj + c] = acc[r][c];
    __syncthreads();

    float acc2[4][4] = {};
    tile_mm_nn(Xs, Rs, acc2, ti, tj);         // out = T @ R
    #pragma unroll
    for (int r = 0; r < 4; ++r) {
        float4 v = make_float4(acc2[r][0], acc2[r][1], acc2[r][2], acc2[r][3]);
        *reinterpret_cast<float4*>(out + boff + (size_t)(ti + r) * 64 + tj) = v;
    }
}

// fused: out_b = (L @ X_b @ R)^2
__global__ __launch_bounds__(256) void cong_sq_kernel(
    const float* __restrict__ Lm, const float* __restrict__ Xb,
    const float* __restrict__ Rm, float* __restrict__ out)
{
    __shared__ float Ls[MATSZ], Rs[MATSZ], Xs[MATSZ];
    const int tid = threadIdx.x;
    const size_t boff = (size_t)blockIdx.x * MATSZ;
    for (int i = tid; i < MATSZ; i += 256) {
        Ls[i] = Lm[i]; Rs[i] = Rm[i]; Xs[i] = Xb[boff + i];
    }
    __syncthreads();

    const int ti = (tid >> 4) << 2, tj = (tid & 15) << 2;
    float acc[4][4] = {};
    tile_mm_nn(Ls, Xs, acc, ti, tj);          // T = L @ X
    __syncthreads();
    #pragma unroll
    for (int r = 0; r < 4; ++r)
        #pragma unroll
        for (int c = 0; c < 4; ++c) Xs[(ti + r) * 64 + tj + c] = acc[r][c];
    __syncthreads();

    float acc2[4][4] = {};
    tile_mm_nn(Xs, Rs, acc2, ti, tj);         // S = T @ R
    __syncthreads();
    #pragma unroll
    for (int r = 0; r < 4; ++r)
        #pragma unroll
        for (int c = 0; c < 4; ++c) Ls[(ti + r) * 64 + tj + c] = acc2[r][c];
    __syncthreads();

    float acc3[4][4] = {};
    tile_mm_nn(Ls, Ls, acc3, ti, tj);         // out = S @ S
    #pragma unroll
    for (int r = 0; r < 4; ++r) {
        float4 v = make_float4(acc3[r][0], acc3[r][1], acc3[r][2], acc3[r][3]);
        *reinterpret_cast<float4*>(out + boff + (size_t)(ti + r) * 64 + tj) = v;
    }
}

// single 64x64 gemm: C = op(A) @ B
__global__ __launch_bounds__(256) void gemm1_kernel(
    const float* __restrict__ A, const float* __restrict__ B,
    float* __restrict__ C, int transA)
{
    __shared__ float As_[MATSZ], Bs_[MATSZ];
    const int tid = threadIdx.x;
    for (int i = tid; i < MATSZ; i += 256) { As_[i] = A[i]; Bs_[i] = B[i]; }
    __syncthreads();
    const int ti = (tid >> 4) << 2, tj = (tid & 15) << 2;
    float acc[4][4] = {};
    if (transA) tile_mm_tn(As_, Bs_, acc, ti, tj);
    else        tile_mm_nn(As_, Bs_, acc, ti, tj);
    #pragma unroll
    for (int r = 0; r < 4; ++r) {
        float4 v = make_float4(acc[r][0], acc[r][1], acc[r][2], acc[r][3]);
        *reinterpret_cast<float4*>(C + (size_t)(ti + r) * 64 + tj) = v;
    }
}

// two-phase batch mean
__global__ __launch_bounds__(256) void mean1_kernel(const float* __restrict__ in)
{
    const int bc = blockIdx.x >> 4;
    const int e  = ((blockIdx.x & 15) << 8) + threadIdx.x;
    const float* base = in + (size_t)bc * 128 * MATSZ + e;
    double a0 = 0, a1 = 0, a2 = 0, a3 = 0;
    for (int b = 0; b < 128; b += 4) {
        a0 += (double)base[(size_t)(b + 0) * MATSZ];
        a1 += (double)base[(size_t)(b + 1) * MATSZ];
        a2 += (double)base[(size_t)(b + 2) * MATSZ];
        a3 += (double)base[(size_t)(b + 3) * MATSZ];
    }
    g_meanpart[bc * MATSZ + e] = (a0 + a1) + (a2 + a3);
}

__global__ __launch_bounds__(256) void mean2_kernel(float* __restrict__ out)
{
    const int e = (blockIdx.x << 8) + threadIdx.x;
    double a = 0;
    #pragma unroll
    for (int c = 0; c < 32; ++c) a += g_meanpart[c * MATSZ + e];
    out[e] = (float)(a * (1.0 / (double)NB));
}

// variance from per-matrix ||log||_F^2 (deterministic, 1 CTA)
__global__ __launch_bounds__(256) void var_reduce_kernel(const float* __restrict__ shift)
{
    __shared__ double sh[256];
    const int tid = threadIdx.x;
    double a = 0;
    #pragma unroll
    for (int i = 0; i < 16; ++i) a += (double)g_fro[tid * 16 + i];
    sh[tid] = a;
    __syncthreads();
    for (int s = 128; s > 0; s >>= 1) {
        if (tid < s) sh[tid] += sh[tid + s];
        __syncthreads();
    }
    if (tid == 0) {
        double var = sh[0] / (double)NB;
        g_scal[0] = shift[0] / (float)sqrt(var + 1e-5);
    }
}

extern "C" void kernel_launch(void* const* d_in, const int* in_sizes, int n_in,
                              void* d_out, int out_size)
{
    const float* X     = (const float*)d_in[0];
    const float* W     = (const float*)d_in[1];
    const float* M     = (const float*)d_in[2];
    const float* shift = (const float*)d_in[3];
    float* out = (float*)d_out;

    float *bufA, *bufB, *bufD, *sm, *fro;
    cudaGetSymbolAddress((void**)&bufA, g_bufA);
    cudaGetSymbolAddress((void**)&bufB, g_bufB);
    cudaGetSymbolAddress((void**)&bufD, g_bufD);
    cudaGetSymbolAddress((void**)&sm,   g_small);
    cudaGetSymbolAddress((void**)&fro,  g_fro);

    cudaFuncSetAttribute(nssqrt_kernel,     cudaFuncAttributeMaxDynamicSharedMemorySize, 65536);
    cudaFuncSetAttribute(nssmall_kernel,    cudaFuncAttributeMaxDynamicSharedMemorySize, 65536);
    cudaFuncSetAttribute(expm_kernel,       cudaFuncAttributeMaxDynamicSharedMemorySize, 49152);
    cudaFuncSetAttribute(expm_fused_kernel, cudaFuncAttributeMaxDynamicSharedMemorySize, 65536);

    static cudaStream_t s2 = [] {
        cudaStream_t s; cudaStreamCreateWithFlags(&s, cudaStreamNonBlocking); return s;
    }();
    static cudaEvent_t evFork = [] {
        cudaEvent_t e; cudaEventCreateWithFlags(&e, cudaEventDisableTiming); return e;
    }();
    static cudaEvent_t evMnh = [] {
        cudaEvent_t e; cudaEventCreateWithFlags(&e, cudaEventDisableTiming); return e;
    }();
    static cudaEvent_t evPrep = [] {
        cudaEvent_t e; cudaEventCreateWithFlags(&e, cudaEventDisableTiming); return e;
    }();

    #define SLOT(i) (sm + (i) * MATSZ)
    // slots: 0 Mh, 1 Mnh, 2 Wh, 3 prep-tmp, 4 Wc, 5 Wch, 6 Wcnh, 7 P,
    //        8 Q, 10 G0, 11 G0h, 12 G0nh, 13 Tm, 14 expTm, 15 G, 16 mnh,
    //        17 Pt, 18 Qt, 19 mid-tmp

    // ---- fork: parameter prep on s2, concurrent with nssqrt on stream0 ----
    cudaEventRecord(evFork, 0);
    cudaStreamWaitEvent(s2, evFork, 0);
    nssmall_kernel<<<2, 256, 65536, s2>>>(M, SLOT(0), SLOT(1),   // Mh, Mnh
                                          W, SLOT(2), nullptr);  // Wh
    cudaEventRecord(evMnh, s2);
    gemm1_kernel<<<1, 256, 0, s2>>>(SLOT(1), SLOT(2), SLOT(3), 0);   // Mnh Wh
    gemm1_kernel<<<1, 256, 0, s2>>>(SLOT(3), SLOT(1), SLOT(4), 0);   // Wc
    nssmall_kernel<<<1, 256, 65536, s2>>>(SLOT(4), SLOT(5), SLOT(6),
                                          SLOT(4), nullptr, nullptr); // Wch, Wcnh
    gemm1_kernel<<<1, 256, 0, s2>>>(SLOT(6), SLOT(2), SLOT(7), 0);   // P  = Wcnh Wh
    gemm1_kernel<<<1, 256, 0, s2>>>(SLOT(2), SLOT(6), SLOT(17), 0);  // Pt = Wh Wcnh
    gemm1_kernel<<<1, 256, 0, s2>>>(SLOT(0), SLOT(5), SLOT(8), 0);   // Q  = Mh Wch
    gemm1_kernel<<<1, 256, 0, s2>>>(SLOT(5), SLOT(0), SLOT(18), 0);  // Qt = Wch Mh
    cudaEventRecord(evPrep, s2);

    // ---- stream0: Xp = X^{1/2}; join Mnh; Xc = Mnh Xp Mnh ----
    nssqrt_kernel<<<NB, 256, 65536>>>(X, bufA);
    cudaStreamWaitEvent(0, evMnh, 0);
    cong_kernel<<<NB, 256>>>(SLOT(1), bufA, SLOT(1), bufB);          // Xc

    // bary_geom: 1 Karcher step from arithmetic mean
    mean1_kernel<<<512, 256>>>(bufB);
    mean2_kernel<<<16, 256>>>(SLOT(10));                             // G0
    nssmall_kernel<<<1, 256, 65536>>>(SLOT(10), SLOT(11), SLOT(12),
                                      SLOT(10), nullptr, nullptr);   // G0h, G0nh
    jaclog_cong_kernel<<<NB, 512>>>(SLOT(12), bufB, bufA, nullptr, 4); // log(G0nh Xc G0nh)
    mean1_kernel<<<512, 256>>>(bufA);
    mean2_kernel<<<16, 256>>>(SLOT(13));                             // Tm
    expm_kernel<<<1, 256, 49152>>>(SLOT(13), SLOT(14));              // expTm
    gemm1_kernel<<<1, 256>>>(SLOT(11), SLOT(14), SLOT(19), 0);
    gemm1_kernel<<<1, 256>>>(SLOT(19), SLOT(11), SLOT(15), 0);       // G
    nssmall_kernel<<<1, 256, 65536>>>(SLOT(15), nullptr, SLOT(16),
                                      SLOT(15), nullptr, nullptr);   // mnh

    // tangent at I + eigen-based variance (stage-2: full 6 sweeps)
    jaclog_cong_kernel<<<NB, 512>>>(SLOT(16), bufB, bufD, fro, 6);   // T0, ||log||_F^2
    var_reduce_kernel<<<1, 256>>>(shift);

    // join full prep; E = exp(factor * P T0 Pt)  (fused)
    cudaStreamWaitEvent(0, evPrep, 0);
    expm_fused_kernel<<<NB, 256, 65536>>>(SLOT(7), bufD, SLOT(17), bufA);

    // out = (Q E Qt)^2  (fused)
    cong_sq_kernel<<<NB, 256>>>(SLOT(8), bufA, SLOT(18), out);
    #undef SLOT
}

// round 17
// speedup vs baseline: 2.5414x; 1.0125x over previous
#include <cuda_runtime.h>
#include <math.h>

#define NN 64
#define MATSZ 4096
#define NB 4096

// device-global scratch (no runtime allocation allowed)
__device__ float  g_bufA[(size_t)NB * MATSZ];
__device__ float  g_bufB[(size_t)NB * MATSZ];
__device__ float  g_bufD[(size_t)NB * MATSZ];
__device__ float  g_small[20 * MATSZ];
__device__ double g_meanpart[32 * MATSZ];
__device__ float  g_fro[NB];
__device__ float  g_scal[4];

// Blackwell packed fp32x2 (FFMA2) — PTX-only, ptxas never auto-fuses.
#define PACKF2(d, lo, hi) asm("mov.b64 %0, {%1, %2};" : "=l"(d) : "f"(lo), "f"(hi))
#define UNPACKF2(lo, hi, d) asm("mov.b64 {%0, %1}, %2;" : "=f"(lo), "=f"(hi) : "l"(d))
#define FMAF2(acc, a, b) asm("fma.rn.f32x2 %0, %1, %2, %0;" : "+l"(acc) : "l"(a), "l"(b))

__device__ __forceinline__ float f4c(const float4& v, int k) {
    return k == 0 ? v.x : k == 1 ? v.y : k == 2 ? v.z : v.w;
}

// ---------------------------------------------------------------------------
// 256-thread 4x4-tile inner product with packed f32x2 accumulation.
// ---------------------------------------------------------------------------
__device__ __forceinline__ void tile_mm_nn(const float* __restrict__ A,
                                           const float* __restrict__ B,
                                           float acc[4][4], int ti, int tj)
{
    unsigned long long p01[4], p23[4];
    #pragma unroll
    for (int r = 0; r < 4; ++r) {
        PACKF2(p01[r], acc[r][0], acc[r][1]);
        PACKF2(p23[r], acc[r][2], acc[r][3]);
    }
    #pragma unroll 4
    for (int k4 = 0; k4 < 64; k4 += 4) {
        float4 av[4];
        #pragma unroll
        for (int r = 0; r < 4; ++r)
            av[r] = *reinterpret_cast<const float4*>(A + (ti + r) * 64 + k4);
        #pragma unroll
        for (int kk = 0; kk < 4; ++kk) {
            float4 b = *reinterpret_cast<const float4*>(B + (k4 + kk) * 64 + tj);
            unsigned long long b01, b23;
            PACKF2(b01, b.x, b.y);
            PACKF2(b23, b.z, b.w);
            #pragma unroll
            for (int r = 0; r < 4; ++r) {
                float a = f4c(av[r], kk);
                unsigned long long aa;
                PACKF2(aa, a, a);
                FMAF2(p01[r], aa, b01);
                FMAF2(p23[r], aa, b23);
            }
        }
    }
    #pragma unroll
    for (int r = 0; r < 4; ++r) {
        UNPACKF2(acc[r][0], acc[r][1], p01[r]);
        UNPACKF2(acc[r][2], acc[r][3], p23[r]);
    }
}

// ---------------------------------------------------------------------------
// In-shared 64x64 GEMM: C = alpha*(A@B) + beta*D + diag*I. 256 threads.
// ---------------------------------------------------------------------------
__device__ __forceinline__ void mm64(const float* __restrict__ A,
                                     const float* __restrict__ B,
                                     float alpha, float beta,
                                     const float* __restrict__ D,
                                     float diag, float* __restrict__ C, int tid)
{
    const int ti = (tid >> 4) << 2, tj = (tid & 15) << 2;
    float acc[4][4] = {};
    tile_mm_nn(A, B, acc, ti, tj);
    __syncthreads();
    #pragma unroll
    for (int r = 0; r < 4; ++r) {
        float4 v;
        v.x = alpha * acc[r][0]; v.y = alpha * acc[r][1];
        v.z = alpha * acc[r][2]; v.w = alpha * acc[r][3];
        if (beta != 0.0f) {
            float4 d = *reinterpret_cast<const float4*>(D + (ti + r) * 64 + tj);
            v.x += beta * d.x; v.y += beta * d.y; v.z += beta * d.z; v.w += beta * d.w;
        }
        if (diag != 0.0f) {
            int row = ti + r;
            if (row >= tj && row < tj + 4) (&v.x)[row - tj] += diag;
        }
        *reinterpret_cast<float4*>(C + (ti + r) * 64 + tj) = v;
    }
    __syncthreads();
}

// ---------------------------------------------------------------------------
// 512-thread in-shared GEMM, 2x4 tiles: C[sC] = A[sA] @ B[64].
// All reads complete before the barrier, so C may alias A or B.
// ---------------------------------------------------------------------------
__device__ __forceinline__ void mm512(const float* __restrict__ A, int sA,
                                      const float* __restrict__ B,
                                      float* __restrict__ C, int sC, int tid)
{
    const int ti = (tid >> 4) << 1;
    const int tj = (tid & 15) << 2;
    unsigned long long p01[2], p23[2];
    #pragma unroll
    for (int r = 0; r < 2; ++r) { PACKF2(p01[r], 0.0f, 0.0f); PACKF2(p23[r], 0.0f, 0.0f); }
    #pragma unroll 4
    for (int k4 = 0; k4 < 64; k4 += 4) {
        float4 a0 = *reinterpret_cast<const float4*>(A + (ti + 0) * sA + k4);
        float4 a1 = *reinterpret_cast<const float4*>(A + (ti + 1) * sA + k4);
        #pragma unroll
        for (int kk = 0; kk < 4; ++kk) {
            float4 b = *reinterpret_cast<const float4*>(B + (k4 + kk) * 64 + tj);
            unsigned long long b01, b23;
            PACKF2(b01, b.x, b.y);
            PACKF2(b23, b.z, b.w);
            float f0 = f4c(a0, kk), f1 = f4c(a1, kk);
            unsigned long long aa0, aa1;
            PACKF2(aa0, f0, f0);
            PACKF2(aa1, f1, f1);
            FMAF2(p01[0], aa0, b01); FMAF2(p23[0], aa0, b23);
            FMAF2(p01[1], aa1, b01); FMAF2(p23[1], aa1, b23);
        }
    }
    float acc[2][4];
    #pragma unroll
    for (int r = 0; r < 2; ++r) {
        UNPACKF2(acc[r][0], acc[r][1], p01[r]);
        UNPACKF2(acc[r][2], acc[r][3], p23[r]);
    }
    __syncthreads();
    #pragma unroll
    for (int r = 0; r < 2; ++r) {
        float4 v = make_float4(acc[r][0], acc[r][1], acc[r][2], acc[r][3]);
        *reinterpret_cast<float4*>(C + (ti + r) * sC + tj) = v;
    }
    __syncthreads();
}

// ---------------------------------------------------------------------------
// Batched matrix sqrt via coupled Newton-Schulz. One CTA/matrix, 8 iters.
// Iteration 1 exploits Z0 = I: one GEMM + elementwise Z update.
// ---------------------------------------------------------------------------
__global__ __launch_bounds__(256) void nssqrt_kernel(
    const float* __restrict__ in, float* __restrict__ out)
{
    extern __shared__ float sh[];          // 4 * 4096 floats
    float *Y = sh, *Z = sh + 4096, *W = sh + 8192, *T = sh + 12288;
    __shared__ float red[256];
    __shared__ float s_s;

    const int tid = threadIdx.x;
    const size_t boff = (size_t)blockIdx.x * MATSZ;

    float fa = 0.0f;
    for (int idx = tid; idx < MATSZ; idx += 256) {
        float v = in[boff + idx];
        Y[idx] = v;
        fa += v * v;
    }
    red[tid] = fa;
    __syncthreads();
    #pragma unroll
    for (int s = 128; s > 0; s >>= 1) {
        if (tid < s) red[tid] += red[tid + s];
        __syncthreads();
    }
    if (tid == 0) s_s = fmaxf(sqrtf(red[0]) / 1.8f, 1e-20f);
    __syncthreads();
    float inv_s = 1.0f / s_s;
    for (int idx = tid; idx < MATSZ; idx += 256) Y[idx] *= inv_s;
    __syncthreads();

    // iteration 0 (Z = I): newY = 1.5Y - 0.5 Y@Y ; newZ = 1.5I - 0.5Y
    mm64(Y, Y, -0.5f, 1.5f, Y, 0.0f, T, tid);
    for (int idx = tid; idx < MATSZ; idx += 256)
        Z[idx] = -0.5f * Y[idx] + (((idx >> 6) == (idx & 63)) ? 1.5f : 0.0f);
    __syncthreads();
    { float* o = Y; Y = T; T = o; }

    for (int it = 1; it < 8; ++it) {
        mm64(Z, Y, 1.0f, 0.0f, nullptr, 0.0f, W, tid);      // W = Z@Y
        mm64(Y, W, -0.5f, 1.5f, Y, 0.0f, T, tid);           // T = 1.5Y - 0.5 Y@W
        if (it < 7) {
            mm64(W, Z, -0.5f, 1.5f, Z, 0.0f, Y, tid);       // Znew -> old Y buffer
            float* nY = T; float* nZ = Y; float* nT = Z;
            Y = nY; Z = nZ; T = nT;
        } else {
            Y = T;
        }
    }
    float rs = sqrtf(s_s);
    for (int idx = tid; idx < MATSZ; idx += 256)
        out[boff + idx] = Y[idx] * rs;
}

// ---------------------------------------------------------------------------
// Tiny (1-2 matrix) coupled Newton-Schulz: A^{1/2} and A^{-1/2}. 256 thr.
// 10 iterations total; iteration 1 uses the Z0 = I shortcut.
// ---------------------------------------------------------------------------
__global__ __launch_bounds__(256) void nssmall_kernel(
    const float* __restrict__ inA, float* sqA, float* isqA,
    const float* __restrict__ inB, float* sqB, float* isqB)
{
    extern __shared__ float sh[];          // 4 * 4096 floats
    float *Y = sh, *Z = sh + 4096, *W = sh + 8192, *T = sh + 12288;
    __shared__ float red[256];
    __shared__ float s_s;

    const int tid = threadIdx.x;
    const float* in = blockIdx.x ? inB : inA;
    float* osq  = blockIdx.x ? sqB  : sqA;
    float* oisq = blockIdx.x ? isqB : isqA;

    float fa = 0.0f;
    for (int idx = tid; idx < MATSZ; idx += 256) {
        float v = in[idx];
        Y[idx] = v;
        fa += v * v;
    }
    red[tid] = fa;
    __syncthreads();
    #pragma unroll
    for (int s = 128; s > 0; s >>= 1) {
        if (tid < s) red[tid] += red[tid + s];
        __syncthreads();
    }
    if (tid == 0) s_s = fmaxf(sqrtf(red[0]) / 1.8f, 1e-20f);
    __syncthreads();
    float inv_s = 1.0f / s_s;
    for (int idx = tid; idx < MATSZ; idx += 256) Y[idx] *= inv_s;
    __syncthreads();

    // iteration 0 (Z = I): newY = 1.5Y - 0.5 Y@Y ; newZ = 1.5I - 0.5Y
    mm64(Y, Y, -0.5f, 1.5f, Y, 0.0f, T, tid);
    for (int idx = tid; idx < MATSZ; idx += 256)
        Z[idx] = -0.5f * Y[idx] + (((idx >> 6) == (idx & 63)) ? 1.5f : 0.0f);
    __syncthreads();
    { float* o = Y; Y = T; T = o; }

    for (int it = 1; it < 10; ++it) {
        mm64(Z, Y, 1.0f, 0.0f, nullptr, 0.0f, W, tid);      // W = Z@Y
        mm64(Y, W, -0.5f, 1.5f, Y, 0.0f, T, tid);           // newY -> T
        mm64(W, Z, -0.5f, 1.5f, Z, 0.0f, Y, tid);           // newZ -> old Y
        float* oY = Y; float* oZ = Z;
        Y = T; Z = oY; T = oZ;
    }
    float rs  = sqrtf(s_s);
    float irs = rsqrtf(s_s);
    if (osq)
        for (int idx = tid; idx < MATSZ; idx += 256) osq[idx] = Y[idx] * rs;
    if (oisq)
        for (int idx = tid; idx < MATSZ; idx += 256) oisq[idx] = Z[idx] * irs;
}

// ---------------------------------------------------------------------------
// expm core on shared buffer B (degree-5 Taylor + squaring). P, Q scratch.
// ---------------------------------------------------------------------------
__device__ __forceinline__ void expm_core(float* B, float* P, float* Q,
                                          float* __restrict__ out, size_t boff,
                                          int tid, float fro2)
{
    __shared__ float sc_s;
    __shared__ int   j_s;
    if (tid == 0) {
        float F = sqrtf(fro2);
        int j = 0;
        while (F > 0.25f && j < 40) { F *= 0.5f; ++j; }
        j_s = j;
        sc_s = exp2f((float)(-j));
    }
    __syncthreads();
    const int j = j_s;
    float sc = sc_s;
    for (int idx = tid; idx < MATSZ; idx += 256) B[idx] *= sc;
    __syncthreads();

    const float c5 = 1.0f / 120.0f, c4 = 1.0f / 24.0f;
    for (int idx = tid; idx < MATSZ; idx += 256) {
        float v = c5 * B[idx];
        if ((idx >> 6) == (idx & 63)) v += c4;
        P[idx] = v;
    }
    __syncthreads();
    const float cs[4] = { 1.0f / 6.0f, 0.5f, 1.0f, 1.0f };
    float *cur = P, *oth = Q;
    #pragma unroll
    for (int k = 0; k < 4; ++k) {
        mm64(cur, B, 1.0f, 0.0f, nullptr, cs[k], oth, tid);
        float* t = cur; cur = oth; oth = t;
    }
    for (int t = 0; t < j; ++t) {
        mm64(cur, cur, 1.0f, 0.0f, nullptr, 0.0f, oth, tid);
        float* tt = cur; cur = oth; oth = tt;
    }
    for (int idx = tid; idx < MATSZ; idx += 256)
        out[boff + idx] = cur[idx];
}

// plain expm (tiny serialized use): out = exp(in_b)
__global__ __launch_bounds__(256) void expm_kernel(
    const float* __restrict__ in, float* __restrict__ out)
{
    extern __shared__ float sh[];          // 3 * 4096 floats
    float *B = sh, *P = sh + 4096, *Q = sh + 8192;
    __shared__ float red[256];
    const int tid = threadIdx.x;
    const size_t boff = (size_t)blockIdx.x * MATSZ;

    float fa = 0.0f;
    for (int idx = tid; idx < MATSZ; idx += 256) {
        float v = in[boff + idx];
        B[idx] = v;
        fa += v * v;
    }
    red[tid] = fa;
    __syncthreads();
    #pragma unroll
    for (int s = 128; s > 0; s >>= 1) {
        if (tid < s) red[tid] += red[tid + s];
        __syncthreads();
    }
    __shared__ float fro2_s;
    if (tid == 0) fro2_s = red[0];
    __syncthreads();
    expm_core(B, P, Q, out, boff, tid, fro2_s);
}

// fused: out_b = exp( g_scal[0] * Pm @ T0_b @ Ptm )   (64KB dynamic smem)
__global__ __launch_bounds__(256) void expm_fused_kernel(
    const float* __restrict__ Pm, const float* __restrict__ T0,
    const float* __restrict__ Ptm, float* __restrict__ out)
{
    extern __shared__ float sh[];          // 4 * 4096 floats
    float *b0 = sh, *b1 = sh + 4096, *b2 = sh + 8192, *b3 = sh + 12288;
    __shared__ float red[256];
    const int tid = threadIdx.x;
    const size_t boff = (size_t)blockIdx.x * MATSZ;
    const float fac = g_scal[0];

    for (int i = tid; i < MATSZ; i += 256) {
        b0[i] = Pm[i];
        b1[i] = T0[boff + i];
        b2[i] = Ptm[i];
    }
    __syncthreads();
    mm64(b0, b1, 1.0f, 0.0f, nullptr, 0.0f, b3, tid);       // T1 = P @ T0
    mm64(b3, b2, fac,  0.0f, nullptr, 0.0f, b1, tid);       // arg -> b1

    float fa = 0.0f;
    for (int i = tid; i < MATSZ; i += 256) { float v = b1[i]; fa += v * v; }
    red[tid] = fa;
    __syncthreads();
    #pragma unroll
    for (int s = 128; s > 0; s >>= 1) {
        if (tid < s) red[tid] += red[tid + s];
        __syncthreads();
    }
    __shared__ float fro2_s;
    if (tid == 0) fro2_s = red[0];
    __syncthreads();
    expm_core(b1, b0, b2, out, boff, tid, fro2_s);
}

// ---------------------------------------------------------------------------
// FUSED whiten + one-sided Jacobi LOG, symmetric 64x64.
// S = L @ X_b @ L in-shared, then out = V log(Lam) V^T of S.
// Near-orthogonal pairs (cos < 1e-7) skip the rotation (below fp32 noise).
// ---------------------------------------------------------------------------
__global__ __launch_bounds__(512) void jaclog_cong_kernel(
    const float* __restrict__ Lm, const float* __restrict__ Xb,
    float* __restrict__ out1, float* __restrict__ fro_out, int nsweeps)
{
    __shared__ float  Ls[MATSZ];
    __shared__ float  As[64 * 68];
    __shared__ float  norms[64];
    __shared__ float  gv[64], ll2[64];
    __shared__ uchar2 ptab[63 * 32];

    const int tid  = threadIdx.x;
    const int lane = tid & 31;
    const int wid  = tid >> 5;
    const int sl   = lane & 15;
    const int k    = (wid << 1) | (lane >> 4);
    const size_t boff = (size_t)blockIdx.x * MATSZ;

    for (int i = tid; i < 63 * 32; i += 512) {
        int r = i >> 5, kk = i & 31;
        int p, q;
        if (kk == 0) { p = 63; q = r; }
        else {
            int a1 = r + kk;      p = (a1 < 63) ? a1 : a1 - 63;
            int a2 = r + 63 - kk; q = (a2 < 63) ? a2 : a2 - 63;
        }
        ptab[i] = make_uchar2((unsigned char)p, (unsigned char)q);
    }

    for (int i = tid; i < MATSZ; i += 512) {
        Ls[i] = Lm[i];
        As[i] = Xb[boff + i];
    }
    __syncthreads();

    mm512(Ls, 64, As, As, 64, tid);      // As(64) = L @ X
    mm512(As, 64, Ls, As, 68, tid);      // As(68) = (L@X) @ L  (symmetric)

    for (int j = k; j < 64; j += 32) {
        float4 a = *reinterpret_cast<const float4*>(As + j * 68 + sl * 4);
        float s = a.x * a.x + a.y * a.y + a.z * a.z + a.w * a.w;
        #pragma unroll
        for (int o = 8; o; o >>= 1) s += __shfl_xor_sync(0xFFFFFFFFu, s, o);
        if (sl == 0) norms[j] = s;
    }
    __syncthreads();

    for (int sw = 0; sw < nsweeps; ++sw) {
        for (int r = 0; r < 63; ++r) {
            uchar2 pq = ptab[(r << 5) | k];
            const int p = pq.x, q = pq.y;
            float4* cp = reinterpret_cast<float4*>(As + p * 68);
            float4* cq = reinterpret_cast<float4*>(As + q * 68);
            float4 ap = cp[sl];
            float4 aq = cq[sl];
            float g = ap.x * aq.x + ap.y * aq.y + ap.z * aq.z + ap.w * aq.w;
            #pragma unroll
            for (int o = 8; o; o >>= 1) g += __shfl_xor_sync(0xFFFFFFFFu, g, o);
            float al = norms[p], be = norms[q];
            if (g * g > 1e-14f * al * be) {      // skip sub-noise rotations
                float tau = (be - al) / (2.0f * g);
                float t = 1.0f / (fabsf(tau) + sqrtf(1.0f + tau * tau));
                if (tau < 0.0f) t = -t;
                float c = rsqrtf(1.0f + t * t);
                float s = t * c;
                float4 np, nq;
                np.x = c * ap.x - s * aq.x;  nq.x = s * ap.x + c * aq.x;
                np.y = c * ap.y - s * aq.y;  nq.y = s * ap.y + c * aq.y;
                np.z = c * ap.z - s * aq.z;  nq.z = s * ap.z + c * aq.z;
                np.w = c * ap.w - s * aq.w;  nq.w = s * ap.w + c * aq.w;
                cp[sl] = np;
                cq[sl] = nq;
                if (sl == 0) {
                    float cc = c * c, ss = s * s, cs2 = 2.0f * c * s;
                    norms[p] = cc * al - cs2 * g + ss * be;
                    norms[q] = ss * al + cs2 * g + cc * be;
                }
            }
            __syncthreads();
        }
    }

    for (int j = k; j < 64; j += 32) {
        float4 a = *reinterpret_cast<const float4*>(As + j * 68 + sl * 4);
        float s = a.x * a.x + a.y * a.y + a.z * a.z + a.w * a.w;
        #pragma unroll
        for (int o = 8; o; o >>= 1) s += __shfl_xor_sync(0xFFFFFFFFu, s, o);
        if (sl == 0) {
            s = fmaxf(s, 1e-30f);
            float lam = sqrtf(s);
            float lg = logf(lam);
            gv[j]  = lg / s;
            ll2[j] = lg * lg;
        }
    }
    __syncthreads();

    const int ti = (tid >> 4) * 2;
    const int tj = (tid & 15) << 2;
    float acc[2][4] = {};
    #pragma unroll 4
    for (int kk = 0; kk < 64; ++kk) {
        const float* ck = As + kk * 68;
        float gk = gv[kk];
        float2 ar = *reinterpret_cast<const float2*>(ck + ti);
        float4 b  = *reinterpret_cast<const float4*>(ck + tj);
        float a0 = gk * ar.x, a1 = gk * ar.y;
        acc[0][0] += a0 * b.x; acc[0][1] += a0 * b.y; acc[0][2] += a0 * b.z; acc[0][3] += a0 * b.w;
        acc[1][0] += a1 * b.x; acc[1][1] += a1 * b.y; acc[1][2] += a1 * b.z; acc[1][3] += a1 * b.w;
    }
    #pragma unroll
    for (int r = 0; r < 2; ++r) {
        float4 v = make_float4(acc[r][0], acc[r][1], acc[r][2], acc[r][3]);
        *reinterpret_cast<float4*>(out1 + boff + (size_t)(ti + r) * 64 + tj) = v;
    }
    if (fro_out && tid == 0) {
        float s = 0.0f;
        #pragma unroll
        for (int j = 0; j < 64; ++j) s += ll2[j];
        fro_out[blockIdx.x] = s;
    }
}

// out_b = L @ X_b @ R  (L, R broadcast)  — used once for Xc
__global__ __launch_bounds__(256) void cong_kernel(
    const float* __restrict__ Lm, const float* __restrict__ Xb,
    const float* __restrict__ Rm, float* __restrict__ out)
{
    __shared__ float Ls[MATSZ], Rs[MATSZ], Xs[MATSZ];
    const int tid = threadIdx.x;
    const size_t boff = (size_t)blockIdx.x * MATSZ;
    for (int i = tid; i < MATSZ; i += 256) {
        Ls[i] = Lm[i]; Rs[i] = Rm[i]; Xs[i] = Xb[boff + i];
    }
    __syncthreads();

    const int ti = (tid >> 4) << 2, tj = (tid & 15) << 2;
    float acc[4][4] = {};
    tile_mm_nn(Ls, Xs, acc, ti, tj);
    __syncthreads();
    #pragma unroll
    for (int r = 0; r < 4; ++r)
        #pragma unroll
        for (int c = 0; c < 4; ++c) Xs[(ti + r) * 64 + tj + c] = acc[r][c];
    __syncthreads();

    float acc2[4][4] = {};
    tile_mm_nn(Xs, Rs, acc2, ti, tj);
    #pragma unroll
    for (int r = 0; r < 4; ++r) {
        float4 v = make_float4(acc2[r][0], acc2[r][1], acc2[r][2], acc2[r][3]);
        *reinterpret_cast<float4*>(out + boff + (size_t)(ti + r) * 64 + tj) = v;
    }
}

// single-matrix congruence: out = L @ X @ L  (one CTA)
__global__ __launch_bounds__(256) void cong1_kernel(
    const float* __restrict__ Lm, const float* __restrict__ Xm,
    float* __restrict__ out)
{
    __shared__ float Ls[MATSZ], Xs[MATSZ];
    const int tid = threadIdx.x;
    for (int i = tid; i < MATSZ; i += 256) { Ls[i] = Lm[i]; Xs[i] = Xm[i]; }
    __syncthreads();

    const int ti = (tid >> 4) << 2, tj = (tid & 15) << 2;
    float acc[4][4] = {};
    tile_mm_nn(Ls, Xs, acc, ti, tj);          // T = L @ X
    __syncthreads();
    #pragma unroll
    for (int r = 0; r < 4; ++r)
        #pragma unroll
        for (int c = 0; c < 4; ++c) Xs[(ti + r) * 64 + tj + c] = acc[r][c];
    __syncthreads();

    float acc2[4][4] = {};
    tile_mm_nn(Xs, Ls, acc2, ti, tj);         // out = T @ L
    #pragma unroll
    for (int r = 0; r < 4; ++r) {
        float4 v = make_float4(acc2[r][0], acc2[r][1], acc2[r][2], acc2[r][3]);
        *reinterpret_cast<float4*>(out + (size_t)(ti + r) * 64 + tj) = v;
    }
}

// fused: out_b = (L @ X_b @ R)^2
__global__ __launch_bounds__(256) void cong_sq_kernel(
    const float* __restrict__ Lm, const float* __restrict__ Xb,
    const float* __restrict__ Rm, float* __restrict__ out)
{
    __shared__ float Ls[MATSZ], Rs[MATSZ], Xs[MATSZ];
    const int tid = threadIdx.x;
    const size_t boff = (size_t)blockIdx.x * MATSZ;
    for (int i = tid; i < MATSZ; i += 256) {
        Ls[i] = Lm[i]; Rs[i] = Rm[i]; Xs[i] = Xb[boff + i];
    }
    __syncthreads();

    const int ti = (tid >> 4) << 2, tj = (tid & 15) << 2;
    float acc[4][4] = {};
    tile_mm_nn(Ls, Xs, acc, ti, tj);          // T = L @ X
    __syncthreads();
    #pragma unroll
    for (int r = 0; r < 4; ++r)
        #pragma unroll
        for (int c = 0; c < 4; ++c) Xs[(ti + r) * 64 + tj + c] = acc[r][c];
    __syncthreads();

    float acc2[4][4] = {};
    tile_mm_nn(Xs, Rs, acc2, ti, tj);         // S = T @ R
    __syncthreads();
    #pragma unroll
    for (int r = 0; r < 4; ++r)
        #pragma unroll
        for (int c = 0; c < 4; ++c) Ls[(ti + r) * 64 + tj + c] = acc2[r][c];
    __syncthreads();

    float acc3[4][4] = {};
    tile_mm_nn(Ls, Ls, acc3, ti, tj);         // out = S @ S
    #pragma unroll
    for (int r = 0; r < 4; ++r) {
        float4 v = make_float4(acc3[r][0], acc3[r][1], acc3[r][2], acc3[r][3]);
        *reinterpret_cast<float4*>(out + boff + (size_t)(ti + r) * 64 + tj) = v;
    }
}

// single 64x64 gemm: C = A @ B
__global__ __launch_bounds__(256) void gemm1_kernel(
    const float* __restrict__ A, const float* __restrict__ B,
    float* __restrict__ C)
{
    __shared__ float As_[MATSZ], Bs_[MATSZ];
    const int tid = threadIdx.x;
    for (int i = tid; i < MATSZ; i += 256) { As_[i] = A[i]; Bs_[i] = B[i]; }
    __syncthreads();
    const int ti = (tid >> 4) << 2, tj = (tid & 15) << 2;
    float acc[4][4] = {};
    tile_mm_nn(As_, Bs_, acc, ti, tj);
    #pragma unroll
    for (int r = 0; r < 4; ++r) {
        float4 v = make_float4(acc[r][0], acc[r][1], acc[r][2], acc[r][3]);
        *reinterpret_cast<float4*>(C + (size_t)(ti + r) * 64 + tj) = v;
    }
}

// two-phase batch mean
__global__ __launch_bounds__(256) void mean1_kernel(const float* __restrict__ in)
{
    const int bc = blockIdx.x >> 4;
    const int e  = ((blockIdx.x & 15) << 8) + threadIdx.x;
    const float* base = in + (size_t)bc * 128 * MATSZ + e;
    double a0 = 0, a1 = 0, a2 = 0, a3 = 0;
    for (int b = 0; b < 128; b += 4) {
        a0 += (double)base[(size_t)(b + 0) * MATSZ];
        a1 += (double)base[(size_t)(b + 1) * MATSZ];
        a2 += (double)base[(size_t)(b + 2) * MATSZ];
        a3 += (double)base[(size_t)(b + 3) * MATSZ];
    }
    g_meanpart[bc * MATSZ + e] = (a0 + a1) + (a2 + a3);
}

__global__ __launch_bounds__(256) void mean2_kernel(float* __restrict__ out)
{
    const int e = (blockIdx.x << 8) + threadIdx.x;
    double a = 0;
    #pragma unroll
    for (int c = 0; c < 32; ++c) a += g_meanpart[c * MATSZ + e];
    out[e] = (float)(a * (1.0 / (double)NB));
}

// variance from per-matrix ||log||_F^2 (deterministic, 1 CTA)
__global__ __launch_bounds__(256) void var_reduce_kernel(const float* __restrict__ shift)
{
    __shared__ double sh[256];
    const int tid = threadIdx.x;
    double a = 0;
    #pragma unroll
    for (int i = 0; i < 16; ++i) a += (double)g_fro[tid * 16 + i];
    sh[tid] = a;
    __syncthreads();
    for (int s = 128; s > 0; s >>= 1) {
        if (tid < s) sh[tid] += sh[tid + s];
        __syncthreads();
    }
    if (tid == 0) {
        double var = sh[0] / (double)NB;
        g_scal[0] = shift[0] / (float)sqrt(var + 1e-5);
    }
}

extern "C" void kernel_launch(void* const* d_in, const int* in_sizes, int n_in,
                              void* d_out, int out_size)
{
    const float* X     = (const float*)d_in[0];
    const float* W     = (const float*)d_in[1];
    const float* M     = (const float*)d_in[2];
    const float* shift = (const float*)d_in[3];
    float* out = (float*)d_out;

    float *bufA, *bufB, *bufD, *sm, *fro;
    cudaGetSymbolAddress((void**)&bufA, g_bufA);
    cudaGetSymbolAddress((void**)&bufB, g_bufB);
    cudaGetSymbolAddress((void**)&bufD, g_bufD);
    cudaGetSymbolAddress((void**)&sm,   g_small);
    cudaGetSymbolAddress((void**)&fro,  g_fro);

    cudaFuncSetAttribute(nssqrt_kernel,     cudaFuncAttributeMaxDynamicSharedMemorySize, 65536);
    cudaFuncSetAttribute(nssmall_kernel,    cudaFuncAttributeMaxDynamicSharedMemorySize, 65536);
    cudaFuncSetAttribute(expm_kernel,       cudaFuncAttributeMaxDynamicSharedMemorySize, 49152);
    cudaFuncSetAttribute(expm_fused_kernel, cudaFuncAttributeMaxDynamicSharedMemorySize, 65536);

    static cudaStream_t s2 = [] {
        cudaStream_t s; cudaStreamCreateWithFlags(&s, cudaStreamNonBlocking); return s;
    }();
    static cudaEvent_t evFork = [] {
        cudaEvent_t e; cudaEventCreateWithFlags(&e, cudaEventDisableTiming); return e;
    }();
    static cudaEvent_t evMnh = [] {
        cudaEvent_t e; cudaEventCreateWithFlags(&e, cudaEventDisableTiming); return e;
    }();
    static cudaEvent_t evPrep = [] {
        cudaEvent_t e; cudaEventCreateWithFlags(&e, cudaEventDisableTiming); return e;
    }();

    #define SLOT(i) (sm + (i) * MATSZ)
    // slots: 0 Mh, 1 Mnh, 2 Wh, 3 prep-tmp, 4 Wc, 5 Wch, 6 Wcnh, 7 P,
    //        8 Q, 10 G0, 11 G0h, 12 G0nh, 13 Tm, 14 expTm, 15 G, 16 mnh,
    //        17 Pt, 18 Qt

    // ---- fork: parameter prep on s2, concurrent with nssqrt on stream0 ----
    cudaEventRecord(evFork, 0);
    cudaStreamWaitEvent(s2, evFork, 0);
    nssmall_kernel<<<2, 256, 65536, s2>>>(M, SLOT(0), SLOT(1),   // Mh, Mnh
                                          W, SLOT(2), nullptr);  // Wh
    cudaEventRecord(evMnh, s2);
    gemm1_kernel<<<1, 256, 0, s2>>>(SLOT(1), SLOT(2), SLOT(3));      // Mnh Wh
    gemm1_kernel<<<1, 256, 0, s2>>>(SLOT(3), SLOT(1), SLOT(4));      // Wc
    nssmall_kernel<<<1, 256, 65536, s2>>>(SLOT(4), SLOT(5), SLOT(6),
                                          SLOT(4), nullptr, nullptr); // Wch, Wcnh
    gemm1_kernel<<<1, 256, 0, s2>>>(SLOT(6), SLOT(2), SLOT(7));      // P  = Wcnh Wh
    gemm1_kernel<<<1, 256, 0, s2>>>(SLOT(2), SLOT(6), SLOT(17));     // Pt = Wh Wcnh
    gemm1_kernel<<<1, 256, 0, s2>>>(SLOT(0), SLOT(5), SLOT(8));      // Q  = Mh Wch
    gemm1_kernel<<<1, 256, 0, s2>>>(SLOT(5), SLOT(0), SLOT(18));     // Qt = Wch Mh
    cudaEventRecord(evPrep, s2);

    // ---- stream0: Xp = X^{1/2}; join Mnh; Xc = Mnh Xp Mnh ----
    nssqrt_kernel<<<NB, 256, 65536>>>(X, bufA);
    cudaStreamWaitEvent(0, evMnh, 0);
    cong_kernel<<<NB, 256>>>(SLOT(1), bufA, SLOT(1), bufB);          // Xc

    // bary_geom: 1 Karcher step from arithmetic mean
    mean1_kernel<<<512, 256>>>(bufB);
    mean2_kernel<<<16, 256>>>(SLOT(10));                             // G0
    nssmall_kernel<<<1, 256, 65536>>>(SLOT(10), SLOT(11), SLOT(12),
                                      SLOT(10), nullptr, nullptr);   // G0h, G0nh
    jaclog_cong_kernel<<<NB, 512>>>(SLOT(12), bufB, bufA, nullptr, 4); // log(G0nh Xc G0nh)
    mean1_kernel<<<512, 256>>>(bufA);
    mean2_kernel<<<16, 256>>>(SLOT(13));                             // Tm
    expm_kernel<<<1, 256, 49152>>>(SLOT(13), SLOT(14));              // expTm
    cong1_kernel<<<1, 256>>>(SLOT(11), SLOT(14), SLOT(15));          // G = G0h expTm G0h
    nssmall_kernel<<<1, 256, 65536>>>(SLOT(15), nullptr, SLOT(16),
                                      SLOT(15), nullptr, nullptr);   // mnh

    // tangent at I + eigen-based variance (stage-2: full 6 sweeps)
    jaclog_cong_kernel<<<NB, 512>>>(SLOT(16), bufB, bufD, fro, 6);   // T0, ||log||_F^2
    var_reduce_kernel<<<1, 256>>>(shift);

    // join full prep; E = exp(factor * P T0 Pt)  (fused)
    cudaStreamWaitEvent(0, evPrep, 0);
    expm_fused_kernel<<<NB, 256, 65536>>>(SLOT(7), bufD, SLOT(17), bufA);

    // out = (Q E Qt)^2  (fused)
    cong_sq_kernel<<<NB, 256>>>(SLOT(8), bufA, SLOT(18), out);
    #undef SLOT
}